// round 1
// baseline (speedup 1.0000x reference)
#include <cuda_runtime.h>
#include <math.h>

// ---------------------------------------------------------------------------
// Problem constants
// ---------------------------------------------------------------------------
#define NT   1024          // sequence length
#define DIMF 512           // model dim
#define NB   4             // batch
#define NHD  8             // heads
#define HD   64            // head dim

static constexpr size_t SZ = (size_t)NB * NT * DIMF;   // 2,097,152 floats

// one big scratch buffer (device global: no allocations allowed)
__device__ float g_buf[SZ * 10 + 16384];

static constexpr size_t O_FEAQ  = 0;
static constexpr size_t O_FEAKV = 1 * SZ;
static constexpr size_t O_Q     = 2 * SZ;
static constexpr size_t O_K     = 3 * SZ;
static constexpr size_t O_V     = 4 * SZ;
static constexpr size_t O_ATT   = 5 * SZ;
static constexpr size_t O_X     = 6 * SZ;
static constexpr size_t O_OUT1  = 7 * SZ;
static constexpr size_t O_H     = 8 * SZ;
static constexpr size_t O_H2    = 9 * SZ;
static constexpr size_t O_T1    = 10 * SZ;          // 4096 floats
static constexpr size_t O_T     = 10 * SZ + 4096;   // 4096 floats
static constexpr size_t O_STATS = 10 * SZ + 8192;   // 8 floats

// ---------------------------------------------------------------------------
// LayerNorm over last dim (512), one block per row, 128 threads x float4
// ---------------------------------------------------------------------------
__global__ void __launch_bounds__(128) ln_k(const float* __restrict__ x,
                                            const float* __restrict__ g,
                                            const float* __restrict__ b,
                                            float* __restrict__ y)
{
    const int row = blockIdx.x;
    const int t   = threadIdx.x;
    float4 v = ((const float4*)(x + (size_t)row * DIMF))[t];
    float s  = v.x + v.y + v.z + v.w;
    float s2 = v.x*v.x + v.y*v.y + v.z*v.z + v.w*v.w;
#pragma unroll
    for (int off = 16; off; off >>= 1) {
        s  += __shfl_xor_sync(0xffffffffu, s,  off);
        s2 += __shfl_xor_sync(0xffffffffu, s2, off);
    }
    __shared__ float sh[8];
    const int w = t >> 5, lane = t & 31;
    if (lane == 0) { sh[w] = s; sh[4 + w] = s2; }
    __syncthreads();
    s  = sh[0] + sh[1] + sh[2] + sh[3];
    s2 = sh[4] + sh[5] + sh[6] + sh[7];
    const float mu   = s * (1.0f / DIMF);
    const float var  = s2 * (1.0f / DIMF) - mu * mu;
    const float rstd = rsqrtf(var + 1e-5f);
    float4 gv = ((const float4*)g)[t];
    float4 bv = ((const float4*)b)[t];
    float4 r;
    r.x = (v.x - mu) * rstd * gv.x + bv.x;
    r.y = (v.y - mu) * rstd * gv.y + bv.y;
    r.z = (v.z - mu) * rstd * gv.z + bv.z;
    r.w = (v.w - mu) * rstd * gv.w + bv.w;
    ((float4*)(y + (size_t)row * DIMF))[t] = r;
}

// ---------------------------------------------------------------------------
// SGEMM: C[M,N] = A[M,K] @ B[K,N] (+bias, +gelu). 64x64 tiles, BK=16, 256 thr.
// EPI: 0 = none, 1 = +bias, 2 = +bias then exact GELU
// ---------------------------------------------------------------------------
__device__ __forceinline__ float gelu_exact(float x)
{
    return 0.5f * x * (1.0f + erff(x * 0.70710678118654752f));
}

template <int EPI>
__global__ void __launch_bounds__(256) sgemm_k(const float* __restrict__ A,
                                               const float* __restrict__ Bm,
                                               const float* __restrict__ bias,
                                               float* __restrict__ C,
                                               int M, int N, int K)
{
    __shared__ float As[16 * 68];  // [k][m], padded
    __shared__ float Bs[16 * 68];  // [k][n], padded

    const int tid = threadIdx.x;
    const int tx = tid & 15, ty = tid >> 4;
    const int m0 = blockIdx.y * 64, n0 = blockIdx.x * 64;

    const int ra = tid >> 2, ca = (tid & 3) << 2;   // A tile: 64 rows x 16 k
    const int rb = tid >> 4, cb = (tid & 15) << 2;  // B tile: 16 k x 64 cols

    float acc[4][4] = {};

    for (int k0 = 0; k0 < K; k0 += 16) {
        __syncthreads();
        float4 a4 = *(const float4*)(A  + (size_t)(m0 + ra) * K + k0 + ca);
        float4 b4 = *(const float4*)(Bm + (size_t)(k0 + rb) * N + n0 + cb);
        As[(ca + 0) * 68 + ra] = a4.x;
        As[(ca + 1) * 68 + ra] = a4.y;
        As[(ca + 2) * 68 + ra] = a4.z;
        As[(ca + 3) * 68 + ra] = a4.w;
        *(float4*)&Bs[rb * 68 + cb] = b4;
        __syncthreads();
#pragma unroll
        for (int k = 0; k < 16; k++) {
            float4 av = *(const float4*)&As[k * 68 + 4 * ty];
            float4 bv = *(const float4*)&Bs[k * 68 + 4 * tx];
            float a[4] = {av.x, av.y, av.z, av.w};
            float bb[4] = {bv.x, bv.y, bv.z, bv.w};
#pragma unroll
            for (int i = 0; i < 4; i++)
#pragma unroll
                for (int j = 0; j < 4; j++)
                    acc[i][j] = fmaf(a[i], bb[j], acc[i][j]);
        }
    }

#pragma unroll
    for (int i = 0; i < 4; i++) {
        float4 r;
        float* rr = (float*)&r;
#pragma unroll
        for (int j = 0; j < 4; j++) {
            float v = acc[i][j];
            if (EPI >= 1) v += bias[n0 + 4 * tx + j];
            if (EPI == 2) v = gelu_exact(v);
            rr[j] = v;
        }
        *(float4*)(C + (size_t)(m0 + 4 * ty + i) * N + n0 + 4 * tx) = r;
    }
}

// ---------------------------------------------------------------------------
// Fused attention: out = softmax_rows(|Q K^T|) @ V_flip / 8
// One CTA = one (b,h) x 64-row Q block. Online softmax over 16 key tiles.
// ---------------------------------------------------------------------------
__global__ void __launch_bounds__(256) attn_k(const float* __restrict__ Q,
                                              const float* __restrict__ K,
                                              const float* __restrict__ V,
                                              float* __restrict__ O)
{
    extern __shared__ float sm[];
    float* Qs  = sm;                 // [row][k]  64x68
    float* KsT = sm + 64 * 68;       // [k][col]  64x68
    float* Vs  = sm + 2 * 64 * 68;   // [col][d]  64x68
    float* Ps  = sm + 3 * 64 * 68;   // [row][col] 64x68

    const int qb = blockIdx.x;               // 0..15
    const int bh = blockIdx.y;               // 0..31
    const int b = bh >> 3, h = bh & 7;
    const int tid = threadIdx.x;
    const int tx = tid & 15, ty = tid >> 4;

    const float* Qb_ = Q + ((size_t)b * NT) * DIMF + h * HD;
    const float* Kb_ = K + ((size_t)b * NT) * DIMF + h * HD;
    const float* Vb_ = V + ((size_t)b * NT) * DIMF + h * HD;

#pragma unroll 4
    for (int i = tid; i < 64 * 64; i += 256) {
        int r = i >> 6, c = i & 63;
        Qs[r * 68 + c] = Qb_[(size_t)(qb * 64 + r) * DIMF + c];
    }

    float m[4], l[4], o[4][4];
#pragma unroll
    for (int i = 0; i < 4; i++) {
        m[i] = -1e30f; l[i] = 0.0f;
#pragma unroll
        for (int j = 0; j < 4; j++) o[i][j] = 0.0f;
    }

    for (int kt = 0; kt < 16; kt++) {
        __syncthreads();
#pragma unroll 4
        for (int i = tid; i < 64 * 64; i += 256) {
            int r = i >> 6, c = i & 63;
            int kr = kt * 64 + r;
            KsT[c * 68 + r] = Kb_[(size_t)kr * DIMF + c];
            // flipped V: row (-kr) mod 1024
            Vs[r * 68 + c] = Vb_[(size_t)((NT - kr) & (NT - 1)) * DIMF + c];
        }
        __syncthreads();

        // S tile: s[i][j] = sum_k Qs[4ty+i][k] * KsT[k][4tx+j]
        float s[4][4] = {};
#pragma unroll
        for (int k4 = 0; k4 < 16; k4++) {
            float4 q4[4];
#pragma unroll
            for (int i = 0; i < 4; i++)
                q4[i] = *(const float4*)&Qs[(4 * ty + i) * 68 + 4 * k4];
#pragma unroll
            for (int kk = 0; kk < 4; kk++) {
                float4 kv = *(const float4*)&KsT[(4 * k4 + kk) * 68 + 4 * tx];
                float kvv[4] = {kv.x, kv.y, kv.z, kv.w};
#pragma unroll
                for (int i = 0; i < 4; i++) {
                    float qv = (kk == 0) ? q4[i].x : (kk == 1) ? q4[i].y
                             : (kk == 2) ? q4[i].z : q4[i].w;
#pragma unroll
                    for (int j = 0; j < 4; j++)
                        s[i][j] = fmaf(qv, kvv[j], s[i][j]);
                }
            }
        }

        // online softmax on |s| (rows split across 16 lanes sharing ty)
#pragma unroll
        for (int i = 0; i < 4; i++) {
            float mt = fmaxf(fmaxf(fabsf(s[i][0]), fabsf(s[i][1])),
                             fmaxf(fabsf(s[i][2]), fabsf(s[i][3])));
#pragma unroll
            for (int off = 8; off; off >>= 1)
                mt = fmaxf(mt, __shfl_xor_sync(0xffffffffu, mt, off, 16));
            float mn = fmaxf(m[i], mt);
            float corr = __expf(m[i] - mn);
            float4 p4;
            p4.x = __expf(fabsf(s[i][0]) - mn);
            p4.y = __expf(fabsf(s[i][1]) - mn);
            p4.z = __expf(fabsf(s[i][2]) - mn);
            p4.w = __expf(fabsf(s[i][3]) - mn);
            *(float4*)&Ps[(4 * ty + i) * 68 + 4 * tx] = p4;
            float ls = p4.x + p4.y + p4.z + p4.w;
#pragma unroll
            for (int off = 8; off; off >>= 1)
                ls += __shfl_xor_sync(0xffffffffu, ls, off, 16);
            l[i] = l[i] * corr + ls;
            m[i] = mn;
#pragma unroll
            for (int j = 0; j < 4; j++) o[i][j] *= corr;
        }
        __syncthreads();

        // O += P @ V
#pragma unroll
        for (int c4 = 0; c4 < 16; c4++) {
            float4 p4[4];
#pragma unroll
            for (int i = 0; i < 4; i++)
                p4[i] = *(const float4*)&Ps[(4 * ty + i) * 68 + 4 * c4];
#pragma unroll
            for (int cc = 0; cc < 4; cc++) {
                float4 vv = *(const float4*)&Vs[(4 * c4 + cc) * 68 + 4 * tx];
                float vvv[4] = {vv.x, vv.y, vv.z, vv.w};
#pragma unroll
                for (int i = 0; i < 4; i++) {
                    float pv = (cc == 0) ? p4[i].x : (cc == 1) ? p4[i].y
                             : (cc == 2) ? p4[i].z : p4[i].w;
#pragma unroll
                    for (int j = 0; j < 4; j++)
                        o[i][j] = fmaf(pv, vvv[j], o[i][j]);
                }
            }
        }
    }

    float* Ob = O + ((size_t)(b * NT + qb * 64 + 4 * ty)) * DIMF + h * HD + 4 * tx;
#pragma unroll
    for (int i = 0; i < 4; i++) {
        float inv = 1.0f / (8.0f * l[i]);   // softmax / sqrt(64)
        float4 r;
        r.x = o[i][0] * inv; r.y = o[i][1] * inv;
        r.z = o[i][2] * inv; r.w = o[i][3] * inv;
        *(float4*)(Ob + (size_t)i * DIMF) = r;
    }
}

// ---------------------------------------------------------------------------
// Per-sample mean / std (ddof=1) over (n, dim)
// ---------------------------------------------------------------------------
__global__ void __launch_bounds__(512) stats_k(const float* __restrict__ a,
                                               float* __restrict__ st)
{
    const int b = blockIdx.x;
    const float* p = a + (size_t)b * (NT * DIMF);
    float s = 0.0f, s2 = 0.0f;
    for (int i = threadIdx.x; i < NT * DIMF; i += 512) {
        float v = p[i];
        s += v;
        s2 = fmaf(v, v, s2);
    }
#pragma unroll
    for (int off = 16; off; off >>= 1) {
        s  += __shfl_xor_sync(0xffffffffu, s,  off);
        s2 += __shfl_xor_sync(0xffffffffu, s2, off);
    }
    __shared__ float sh[16], sh2[16];
    const int w = threadIdx.x >> 5;
    if ((threadIdx.x & 31) == 0) { sh[w] = s; sh2[w] = s2; }
    __syncthreads();
    if (threadIdx.x == 0) {
        float ts = 0.0f, ts2 = 0.0f;
        for (int i = 0; i < 16; i++) { ts += sh[i]; ts2 += sh2[i]; }
        double N   = (double)(NT * DIMF);
        double mu  = (double)ts / N;
        double var = ((double)ts2 - N * mu * mu) / (N - 1.0);   // ddof=1
        st[b * 2 + 0] = (float)mu;
        st[b * 2 + 1] = (float)(1.0 / sqrt(var));
    }
}

// ---------------------------------------------------------------------------
// Time MLP (tiny): h1 = silu(te @ w_emd1 + b1), t = h1 @ w_emd2 + b2
// ---------------------------------------------------------------------------
__global__ void __launch_bounds__(256) tmlp1_k(const float* __restrict__ te,
                                               const float* __restrict__ w,
                                               const float* __restrict__ bb,
                                               float* __restrict__ h1)
{
    const int b = blockIdx.y;
    const int j = blockIdx.x * 256 + threadIdx.x;   // < 1024
    float acc = 0.0f;
    for (int k = 0; k < 512; k++)
        acc = fmaf(te[b * 512 + k], w[k * 1024 + j], acc);
    acc += bb[j];
    h1[b * 1024 + j] = acc / (1.0f + __expf(-acc));  // silu
}

__global__ void __launch_bounds__(256) tmlp2_k(const float* __restrict__ h1,
                                               const float* __restrict__ w,
                                               const float* __restrict__ bb,
                                               float* __restrict__ tout)
{
    const int b = blockIdx.y;
    const int j = blockIdx.x * 256 + threadIdx.x;
    float acc = 0.0f;
    for (int k = 0; k < 1024; k++)
        acc = fmaf(h1[b * 1024 + k], w[k * 1024 + j], acc);
    tout[b * 1024 + j] = acc + bb[j];
}

// ---------------------------------------------------------------------------
// FiLM apply: x = (att - mu) * rstd * std_t[b,c] + mean_t[b,c]
// ---------------------------------------------------------------------------
__global__ void __launch_bounds__(256) film_k(const float* __restrict__ a,
                                              const float* __restrict__ t,
                                              const float* __restrict__ st,
                                              float* __restrict__ x)
{
    const int idx = blockIdx.x * 256 + threadIdx.x;   // < 4*1024*512
    const int c = idx & 511;
    const int b = idx >> 19;                          // 1024*512 = 2^19
    const float mu = st[b * 2], rstd = st[b * 2 + 1];
    x[idx] = (a[idx] - mu) * rstd * t[b * 1024 + 512 + c] + t[b * 1024 + c];
}

// ---------------------------------------------------------------------------
// Launch
// ---------------------------------------------------------------------------
extern "C" void kernel_launch(void* const* d_in, const int* in_sizes, int n_in,
                              void* d_out, int out_size)
{
    const float* con   = (const float*)d_in[0];
    const float* diff  = (const float*)d_in[1];
    const float* temb  = (const float*)d_in[2];
    const float* lncg  = (const float*)d_in[3];
    const float* lncb  = (const float*)d_in[4];
    const float* lndg  = (const float*)d_in[5];
    const float* lndb  = (const float*)d_in[6];
    const float* wq    = (const float*)d_in[7];
    const float* wk    = (const float*)d_in[8];
    const float* wv    = (const float*)d_in[9];
    const float* wout  = (const float*)d_in[10];
    const float* bout  = (const float*)d_in[11];
    const float* wemd1 = (const float*)d_in[12];
    const float* bemd1 = (const float*)d_in[13];
    const float* wemd2 = (const float*)d_in[14];
    const float* bemd2 = (const float*)d_in[15];
    const float* mlng  = (const float*)d_in[16];
    const float* mlnb  = (const float*)d_in[17];
    const float* mw1   = (const float*)d_in[18];
    const float* mb1   = (const float*)d_in[19];
    const float* mw2   = (const float*)d_in[20];
    const float* mb2   = (const float*)d_in[21];

    float* buf = nullptr;
    cudaGetSymbolAddress((void**)&buf, g_buf);

    const int attn_smem = 4 * 64 * 68 * 4;   // 69632 B
    cudaFuncSetAttribute(attn_k, cudaFuncAttributeMaxDynamicSharedMemorySize,
                         attn_smem);

    // 1) LayerNorms
    ln_k<<<NB * NT, 128>>>(diff, lndg, lndb, buf + O_FEAQ);
    ln_k<<<NB * NT, 128>>>(con,  lncg, lncb, buf + O_FEAKV);

    // 2) Q/K/V projections
    dim3 gg(DIMF / 64, (NB * NT) / 64);   // (8, 64)
    sgemm_k<0><<<gg, 256>>>(buf + O_FEAQ,  wq, nullptr, buf + O_Q, NB * NT, DIMF, DIMF);
    sgemm_k<0><<<gg, 256>>>(buf + O_FEAKV, wk, nullptr, buf + O_K, NB * NT, DIMF, DIMF);
    sgemm_k<0><<<gg, 256>>>(buf + O_FEAKV, wv, nullptr, buf + O_V, NB * NT, DIMF, DIMF);

    // 3) Fourier attention == softmax(|QK^T|) @ V_flip / 8
    attn_k<<<dim3(NT / 64, NB * NHD), 256, attn_smem>>>(
        buf + O_Q, buf + O_K, buf + O_V, buf + O_ATT);

    // 4) per-sample stats + time MLP + FiLM
    stats_k<<<NB, 512>>>(buf + O_ATT, buf + O_STATS);
    tmlp1_k<<<dim3(4, NB), 256>>>(temb, wemd1, bemd1, buf + O_T1);
    tmlp2_k<<<dim3(4, NB), 256>>>(buf + O_T1, wemd2, bemd2, buf + O_T);
    film_k<<<(int)(SZ / 256), 256>>>(buf + O_ATT, buf + O_T, buf + O_STATS,
                                     buf + O_X);

    // 5) output projection
    sgemm_k<1><<<gg, 256>>>(buf + O_X, wout, bout, buf + O_OUT1, NB * NT, DIMF, DIMF);

    // 6) FeedForward: LN -> Linear+GELU -> Linear
    ln_k<<<NB * NT, 128>>>(buf + O_OUT1, mlng, mlnb, buf + O_H);
    sgemm_k<2><<<gg, 256>>>(buf + O_H,  mw1, mb1, buf + O_H2, NB * NT, DIMF, DIMF);
    sgemm_k<1><<<gg, 256>>>(buf + O_H2, mw2, mb2, (float*)d_out, NB * NT, DIMF, DIMF);
}

// round 3
// speedup vs baseline: 1.3535x; 1.3535x over previous
#include <cuda_runtime.h>
#include <math.h>
#include <stdint.h>

// ---------------------------------------------------------------------------
// Problem constants
// ---------------------------------------------------------------------------
#define NT   1024          // sequence length
#define DIMF 512           // model dim
#define NB   4             // batch
#define NHD  8             // heads
#define HD   64            // head dim

static constexpr size_t SZ = (size_t)NB * NT * DIMF;   // 2,097,152 floats

// one big scratch buffer (device global: no allocations allowed)
__device__ float g_buf[SZ * 10 + 2 * 1024 * 1024];

static constexpr size_t O_FEAQ  = 0;
static constexpr size_t O_FEAKV = 1 * SZ;
static constexpr size_t O_Q     = 2 * SZ;
static constexpr size_t O_K     = 3 * SZ;
static constexpr size_t O_V     = 4 * SZ;
static constexpr size_t O_ATT   = 5 * SZ;
static constexpr size_t O_X     = 6 * SZ;
static constexpr size_t O_OUT1  = 7 * SZ;
static constexpr size_t O_H     = 8 * SZ;
static constexpr size_t O_H2    = 9 * SZ;
static constexpr size_t O_T1    = 10 * SZ;          // 4096 floats
static constexpr size_t O_T     = 10 * SZ + 4096;   // 4096 floats
static constexpr size_t O_STATS = 10 * SZ + 8192;   // 8 floats
static constexpr size_t O_WT    = 10 * SZ + 16384;  // 6 x 512*512 transposed weights
static constexpr size_t WSTEP   = (size_t)DIMF * DIMF;

// ---------------------------------------------------------------------------
// helpers
// ---------------------------------------------------------------------------
__device__ __forceinline__ uint32_t cvt_tf32(float x)
{
    uint32_t u;
    asm("cvt.rna.tf32.f32 %0, %1;" : "=r"(u) : "f"(x));
    return u;
}

__device__ __forceinline__ void mma_tf32(float c[4],
                                         uint32_t a0, uint32_t a1,
                                         uint32_t a2, uint32_t a3,
                                         uint32_t b0, uint32_t b1)
{
    asm volatile(
        "mma.sync.aligned.m16n8k8.row.col.f32.tf32.tf32.f32 "
        "{%0,%1,%2,%3}, {%4,%5,%6,%7}, {%8,%9}, {%0,%1,%2,%3};"
        : "+f"(c[0]), "+f"(c[1]), "+f"(c[2]), "+f"(c[3])
        : "r"(a0), "r"(a1), "r"(a2), "r"(a3), "r"(b0), "r"(b1));
}

__device__ __forceinline__ float gelu_exact(float x)
{
    return 0.5f * x * (1.0f + erff(x * 0.70710678118654752f));
}

// ---------------------------------------------------------------------------
// 512x512 transpose (weights -> [N][K] so the mma B operand is K-major)
// ---------------------------------------------------------------------------
__global__ void __launch_bounds__(256) tr512_k(const float* __restrict__ w,
                                               float* __restrict__ wt)
{
    __shared__ float t[32][33];
    const int tx = threadIdx.x & 31, ty = threadIdx.x >> 5;  // 32x8
    const int x = blockIdx.x * 32 + tx;
    const int y0 = blockIdx.y * 32;
#pragma unroll
    for (int j = 0; j < 32; j += 8)
        t[ty + j][tx] = w[(size_t)(y0 + ty + j) * 512 + x];
    __syncthreads();
    const int x2 = y0 + tx;
#pragma unroll
    for (int j = 0; j < 32; j += 8)
        wt[(size_t)(blockIdx.x * 32 + ty + j) * 512 + x2] = t[tx][ty + j];
}

// ---------------------------------------------------------------------------
// Tensor-core tf32 GEMM: C[4096,512] = A[4096,512] @ Bt^T  (Bt is [N,K])
// mma.sync m16n8k8, CTA tile 128x128, 8 warps (warp tile 64x32),
// K chunks of 32, double-buffered smem (pad 36).
// EPI: 0 = none, 1 = +bias, 2 = +bias then exact GELU
// ---------------------------------------------------------------------------
#define TPAD 36

template <int EPI>
__global__ void __launch_bounds__(256, 1) mgemm_k(const float* __restrict__ A,
                                                  const float* __restrict__ Bt,
                                                  const float* __restrict__ bias,
                                                  float* __restrict__ C)
{
    extern __shared__ float sm[];
    float* Asm[2] = {sm,            sm + 128 * TPAD};
    float* Bsm[2] = {sm + 2 * 128 * TPAD, sm + 3 * 128 * TPAD};

    const int tid = threadIdx.x;
    const int wid = tid >> 5, lane = tid & 31;
    const int g = lane >> 2, tq = lane & 3;
    const int m0w = (wid >> 2) * 64;      // warp row offset in tile
    const int n0w = (wid & 3) * 32;       // warp col offset in tile

    const int m0 = blockIdx.y * 128, n0 = blockIdx.x * 128;
    const float* Ab = A  + (size_t)m0 * 512;
    const float* Bb = Bt + (size_t)n0 * 512;

    // loader indices: 1024 float4 segments per operand, 4 per thread
    const int lrow[4] = {(tid + 0)   >> 3, (tid + 256) >> 3,
                         (tid + 512) >> 3, (tid + 768) >> 3};
    const int lseg = tid & 7;

    float acc[4][4][4] = {};   // [mi][ni][frag]

    // prologue: chunk 0 -> buffer 0
#pragma unroll
    for (int i = 0; i < 4; i++) {
        float4 a4 = *(const float4*)(Ab + (size_t)lrow[i] * 512 + lseg * 4);
        float4 b4 = *(const float4*)(Bb + (size_t)lrow[i] * 512 + lseg * 4);
        uint4* pa = (uint4*)&Asm[0][lrow[i] * TPAD + lseg * 4];
        uint4* pb = (uint4*)&Bsm[0][lrow[i] * TPAD + lseg * 4];
        *pa = make_uint4(cvt_tf32(a4.x), cvt_tf32(a4.y), cvt_tf32(a4.z), cvt_tf32(a4.w));
        *pb = make_uint4(cvt_tf32(b4.x), cvt_tf32(b4.y), cvt_tf32(b4.z), cvt_tf32(b4.w));
    }
    __syncthreads();

    for (int c = 0; c < 16; c++) {
        const int cur = c & 1, nxt = cur ^ 1;

        // issue next chunk's global loads early (latency hidden by compute)
        float4 sa[4], sb[4];
        if (c < 15) {
#pragma unroll
            for (int i = 0; i < 4; i++) {
                sa[i] = *(const float4*)(Ab + (size_t)lrow[i] * 512 + (c + 1) * 32 + lseg * 4);
                sb[i] = *(const float4*)(Bb + (size_t)lrow[i] * 512 + (c + 1) * 32 + lseg * 4);
            }
        }

        const float* As = Asm[cur];
        const float* Bs = Bsm[cur];
#pragma unroll
        for (int ks = 0; ks < 4; ks++) {
            const int kk = ks * 8;
            uint32_t af[4][4], bf[4][2];
#pragma unroll
            for (int mi = 0; mi < 4; mi++) {
                const int r = m0w + mi * 16 + g;
                af[mi][0] = __float_as_uint(As[(r    ) * TPAD + kk + tq]);
                af[mi][1] = __float_as_uint(As[(r + 8) * TPAD + kk + tq]);
                af[mi][2] = __float_as_uint(As[(r    ) * TPAD + kk + tq + 4]);
                af[mi][3] = __float_as_uint(As[(r + 8) * TPAD + kk + tq + 4]);
            }
#pragma unroll
            for (int ni = 0; ni < 4; ni++) {
                const int r = n0w + ni * 8 + g;
                bf[ni][0] = __float_as_uint(Bs[r * TPAD + kk + tq]);
                bf[ni][1] = __float_as_uint(Bs[r * TPAD + kk + tq + 4]);
            }
#pragma unroll
            for (int mi = 0; mi < 4; mi++)
#pragma unroll
                for (int ni = 0; ni < 4; ni++)
                    mma_tf32(acc[mi][ni], af[mi][0], af[mi][1], af[mi][2], af[mi][3],
                             bf[ni][0], bf[ni][1]);
        }

        if (c < 15) {
#pragma unroll
            for (int i = 0; i < 4; i++) {
                uint4* pa = (uint4*)&Asm[nxt][lrow[i] * TPAD + lseg * 4];
                uint4* pb = (uint4*)&Bsm[nxt][lrow[i] * TPAD + lseg * 4];
                *pa = make_uint4(cvt_tf32(sa[i].x), cvt_tf32(sa[i].y),
                                 cvt_tf32(sa[i].z), cvt_tf32(sa[i].w));
                *pb = make_uint4(cvt_tf32(sb[i].x), cvt_tf32(sb[i].y),
                                 cvt_tf32(sb[i].z), cvt_tf32(sb[i].w));
            }
        }
        __syncthreads();
    }

    // epilogue: c0/c1 -> (row, 2tq), c2/c3 -> (row+8, 2tq)
#pragma unroll
    for (int mi = 0; mi < 4; mi++) {
        const int row = m0 + m0w + mi * 16 + g;
#pragma unroll
        for (int ni = 0; ni < 4; ni++) {
            const int col = n0 + n0w + ni * 8 + 2 * tq;
            float v0 = acc[mi][ni][0], v1 = acc[mi][ni][1];
            float v2 = acc[mi][ni][2], v3 = acc[mi][ni][3];
            if (EPI >= 1) {
                const float b0 = bias[col], b1 = bias[col + 1];
                v0 += b0; v1 += b1; v2 += b0; v3 += b1;
            }
            if (EPI == 2) {
                v0 = gelu_exact(v0); v1 = gelu_exact(v1);
                v2 = gelu_exact(v2); v3 = gelu_exact(v3);
            }
            *(float2*)(C + (size_t)row * 512 + col)       = make_float2(v0, v1);
            *(float2*)(C + (size_t)(row + 8) * 512 + col) = make_float2(v2, v3);
        }
    }
}

// ---------------------------------------------------------------------------
// LayerNorm over last dim (512), one block per row, 128 threads x float4
// ---------------------------------------------------------------------------
__global__ void __launch_bounds__(128) ln_k(const float* __restrict__ x,
                                            const float* __restrict__ g,
                                            const float* __restrict__ b,
                                            float* __restrict__ y)
{
    const int row = blockIdx.x;
    const int t   = threadIdx.x;
    float4 v = ((const float4*)(x + (size_t)row * DIMF))[t];
    float s  = v.x + v.y + v.z + v.w;
    float s2 = v.x*v.x + v.y*v.y + v.z*v.z + v.w*v.w;
#pragma unroll
    for (int off = 16; off; off >>= 1) {
        s  += __shfl_xor_sync(0xffffffffu, s,  off);
        s2 += __shfl_xor_sync(0xffffffffu, s2, off);
    }
    __shared__ float sh[8];
    const int w = t >> 5, lane = t & 31;
    if (lane == 0) { sh[w] = s; sh[4 + w] = s2; }
    __syncthreads();
    s  = sh[0] + sh[1] + sh[2] + sh[3];
    s2 = sh[4] + sh[5] + sh[6] + sh[7];
    const float mu   = s * (1.0f / DIMF);
    const float var  = s2 * (1.0f / DIMF) - mu * mu;
    const float rstd = rsqrtf(var + 1e-5f);
    float4 gv = ((const float4*)g)[t];
    float4 bv = ((const float4*)b)[t];
    float4 r;
    r.x = (v.x - mu) * rstd * gv.x + bv.x;
    r.y = (v.y - mu) * rstd * gv.y + bv.y;
    r.z = (v.z - mu) * rstd * gv.z + bv.z;
    r.w = (v.w - mu) * rstd * gv.w + bv.w;
    ((float4*)(y + (size_t)row * DIMF))[t] = r;
}

// ---------------------------------------------------------------------------
// Fused attention: out = softmax_rows(|Q K^T|) @ V_flip / 8
// One CTA = one (b,h) x 64-row Q block. Online softmax over 16 key tiles.
// ---------------------------------------------------------------------------
__global__ void __launch_bounds__(256) attn_k(const float* __restrict__ Q,
                                              const float* __restrict__ K,
                                              const float* __restrict__ V,
                                              float* __restrict__ O)
{
    extern __shared__ float smf[];
    float* Qs  = smf;
    float* KsT = smf + 64 * 68;
    float* Vs  = smf + 2 * 64 * 68;
    float* Ps  = smf + 3 * 64 * 68;

    const int qb = blockIdx.x;
    const int bh = blockIdx.y;
    const int b = bh >> 3, h = bh & 7;
    const int tid = threadIdx.x;
    const int tx = tid & 15, ty = tid >> 4;

    const float* Qb_ = Q + ((size_t)b * NT) * DIMF + h * HD;
    const float* Kb_ = K + ((size_t)b * NT) * DIMF + h * HD;
    const float* Vb_ = V + ((size_t)b * NT) * DIMF + h * HD;

#pragma unroll 4
    for (int i = tid; i < 64 * 64; i += 256) {
        int r = i >> 6, c = i & 63;
        Qs[r * 68 + c] = Qb_[(size_t)(qb * 64 + r) * DIMF + c];
    }

    float m[4], l[4], o[4][4];
#pragma unroll
    for (int i = 0; i < 4; i++) {
        m[i] = -1e30f; l[i] = 0.0f;
#pragma unroll
        for (int j = 0; j < 4; j++) o[i][j] = 0.0f;
    }

    for (int kt = 0; kt < 16; kt++) {
        __syncthreads();
#pragma unroll 4
        for (int i = tid; i < 64 * 64; i += 256) {
            int r = i >> 6, c = i & 63;
            int kr = kt * 64 + r;
            KsT[c * 68 + r] = Kb_[(size_t)kr * DIMF + c];
            Vs[r * 68 + c] = Vb_[(size_t)((NT - kr) & (NT - 1)) * DIMF + c];
        }
        __syncthreads();

        float s[4][4] = {};
#pragma unroll
        for (int k4 = 0; k4 < 16; k4++) {
            float4 q4[4];
#pragma unroll
            for (int i = 0; i < 4; i++)
                q4[i] = *(const float4*)&Qs[(4 * ty + i) * 68 + 4 * k4];
#pragma unroll
            for (int kk = 0; kk < 4; kk++) {
                float4 kv = *(const float4*)&KsT[(4 * k4 + kk) * 68 + 4 * tx];
                float kvv[4] = {kv.x, kv.y, kv.z, kv.w};
#pragma unroll
                for (int i = 0; i < 4; i++) {
                    float qv = (kk == 0) ? q4[i].x : (kk == 1) ? q4[i].y
                             : (kk == 2) ? q4[i].z : q4[i].w;
#pragma unroll
                    for (int j = 0; j < 4; j++)
                        s[i][j] = fmaf(qv, kvv[j], s[i][j]);
                }
            }
        }

#pragma unroll
        for (int i = 0; i < 4; i++) {
            float mt = fmaxf(fmaxf(fabsf(s[i][0]), fabsf(s[i][1])),
                             fmaxf(fabsf(s[i][2]), fabsf(s[i][3])));
#pragma unroll
            for (int off = 8; off; off >>= 1)
                mt = fmaxf(mt, __shfl_xor_sync(0xffffffffu, mt, off, 16));
            float mn = fmaxf(m[i], mt);
            float corr = __expf(m[i] - mn);
            float4 p4;
            p4.x = __expf(fabsf(s[i][0]) - mn);
            p4.y = __expf(fabsf(s[i][1]) - mn);
            p4.z = __expf(fabsf(s[i][2]) - mn);
            p4.w = __expf(fabsf(s[i][3]) - mn);
            *(float4*)&Ps[(4 * ty + i) * 68 + 4 * tx] = p4;
            float ls = p4.x + p4.y + p4.z + p4.w;
#pragma unroll
            for (int off = 8; off; off >>= 1)
                ls += __shfl_xor_sync(0xffffffffu, ls, off, 16);
            l[i] = l[i] * corr + ls;
            m[i] = mn;
#pragma unroll
            for (int j = 0; j < 4; j++) o[i][j] *= corr;
        }
        __syncthreads();

#pragma unroll
        for (int c4 = 0; c4 < 16; c4++) {
            float4 p4[4];
#pragma unroll
            for (int i = 0; i < 4; i++)
                p4[i] = *(const float4*)&Ps[(4 * ty + i) * 68 + 4 * c4];
#pragma unroll
            for (int cc = 0; cc < 4; cc++) {
                float4 vv = *(const float4*)&Vs[(4 * c4 + cc) * 68 + 4 * tx];
                float vvv[4] = {vv.x, vv.y, vv.z, vv.w};
#pragma unroll
                for (int i = 0; i < 4; i++) {
                    float pv = (cc == 0) ? p4[i].x : (cc == 1) ? p4[i].y
                             : (cc == 2) ? p4[i].z : p4[i].w;
#pragma unroll
                    for (int j = 0; j < 4; j++)
                        o[i][j] = fmaf(pv, vvv[j], o[i][j]);
                }
            }
        }
    }

    float* Ob = O + ((size_t)(b * NT + qb * 64 + 4 * ty)) * DIMF + h * HD + 4 * tx;
#pragma unroll
    for (int i = 0; i < 4; i++) {
        float inv = 1.0f / (8.0f * l[i]);
        float4 r;
        r.x = o[i][0] * inv; r.y = o[i][1] * inv;
        r.z = o[i][2] * inv; r.w = o[i][3] * inv;
        *(float4*)(Ob + (size_t)i * DIMF) = r;
    }
}

// ---------------------------------------------------------------------------
// Per-sample mean / std (ddof=1) over (n, dim)
// ---------------------------------------------------------------------------
__global__ void __launch_bounds__(512) stats_k(const float* __restrict__ a,
                                               float* __restrict__ st)
{
    const int b = blockIdx.x;
    const float* p = a + (size_t)b * (NT * DIMF);
    float s = 0.0f, s2 = 0.0f;
    for (int i = threadIdx.x; i < NT * DIMF; i += 512) {
        float v = p[i];
        s += v;
        s2 = fmaf(v, v, s2);
    }
#pragma unroll
    for (int off = 16; off; off >>= 1) {
        s  += __shfl_xor_sync(0xffffffffu, s,  off);
        s2 += __shfl_xor_sync(0xffffffffu, s2, off);
    }
    __shared__ float sh[16], sh2[16];
    const int w = threadIdx.x >> 5;
    if ((threadIdx.x & 31) == 0) { sh[w] = s; sh2[w] = s2; }
    __syncthreads();
    if (threadIdx.x == 0) {
        float ts = 0.0f, ts2 = 0.0f;
        for (int i = 0; i < 16; i++) { ts += sh[i]; ts2 += sh2[i]; }
        double N   = (double)(NT * DIMF);
        double mu  = (double)ts / N;
        double var = ((double)ts2 - N * mu * mu) / (N - 1.0);
        st[b * 2 + 0] = (float)mu;
        st[b * 2 + 1] = (float)(1.0 / sqrt(var));
    }
}

// ---------------------------------------------------------------------------
// Time MLP (tiny)
// ---------------------------------------------------------------------------
__global__ void __launch_bounds__(256) tmlp1_k(const float* __restrict__ te,
                                               const float* __restrict__ w,
                                               const float* __restrict__ bb,
                                               float* __restrict__ h1)
{
    const int b = blockIdx.y;
    const int j = blockIdx.x * 256 + threadIdx.x;
    float acc = 0.0f;
    for (int k = 0; k < 512; k++)
        acc = fmaf(te[b * 512 + k], w[k * 1024 + j], acc);
    acc += bb[j];
    h1[b * 1024 + j] = acc / (1.0f + __expf(-acc));
}

__global__ void __launch_bounds__(256) tmlp2_k(const float* __restrict__ h1,
                                               const float* __restrict__ w,
                                               const float* __restrict__ bb,
                                               float* __restrict__ tout)
{
    const int b = blockIdx.y;
    const int j = blockIdx.x * 256 + threadIdx.x;
    float acc = 0.0f;
    for (int k = 0; k < 1024; k++)
        acc = fmaf(h1[b * 1024 + k], w[k * 1024 + j], acc);
    tout[b * 1024 + j] = acc + bb[j];
}

// ---------------------------------------------------------------------------
// FiLM apply
// ---------------------------------------------------------------------------
__global__ void __launch_bounds__(256) film_k(const float* __restrict__ a,
                                              const float* __restrict__ t,
                                              const float* __restrict__ st,
                                              float* __restrict__ x)
{
    const int idx = blockIdx.x * 256 + threadIdx.x;
    const int c = idx & 511;
    const int b = idx >> 19;
    const float mu = st[b * 2], rstd = st[b * 2 + 1];
    x[idx] = (a[idx] - mu) * rstd * t[b * 1024 + 512 + c] + t[b * 1024 + c];
}

// ---------------------------------------------------------------------------
// Launch
// ---------------------------------------------------------------------------
extern "C" void kernel_launch(void* const* d_in, const int* in_sizes, int n_in,
                              void* d_out, int out_size)
{
    const float* con   = (const float*)d_in[0];
    const float* diff  = (const float*)d_in[1];
    const float* temb  = (const float*)d_in[2];
    const float* lncg  = (const float*)d_in[3];
    const float* lncb  = (const float*)d_in[4];
    const float* lndg  = (const float*)d_in[5];
    const float* lndb  = (const float*)d_in[6];
    const float* wq    = (const float*)d_in[7];
    const float* wk    = (const float*)d_in[8];
    const float* wv    = (const float*)d_in[9];
    const float* wout  = (const float*)d_in[10];
    const float* bout  = (const float*)d_in[11];
    const float* wemd1 = (const float*)d_in[12];
    const float* bemd1 = (const float*)d_in[13];
    const float* wemd2 = (const float*)d_in[14];
    const float* bemd2 = (const float*)d_in[15];
    const float* mlng  = (const float*)d_in[16];
    const float* mlnb  = (const float*)d_in[17];
    const float* mw1   = (const float*)d_in[18];
    const float* mb1   = (const float*)d_in[19];
    const float* mw2   = (const float*)d_in[20];
    const float* mb2   = (const float*)d_in[21];

    float* buf = nullptr;
    cudaGetSymbolAddress((void**)&buf, g_buf);

    const int attn_smem = 4 * 64 * 68 * 4;            // 69632 B
    cudaFuncSetAttribute(attn_k, cudaFuncAttributeMaxDynamicSharedMemorySize,
                         attn_smem);
    const int mg_smem = 4 * 128 * TPAD * 4;           // 73728 B
    cudaFuncSetAttribute(mgemm_k<0>, cudaFuncAttributeMaxDynamicSharedMemorySize, mg_smem);
    cudaFuncSetAttribute(mgemm_k<1>, cudaFuncAttributeMaxDynamicSharedMemorySize, mg_smem);
    cudaFuncSetAttribute(mgemm_k<2>, cudaFuncAttributeMaxDynamicSharedMemorySize, mg_smem);

    // 0) transpose the six 512x512 weights to [N,K]
    dim3 trg(16, 16);
    tr512_k<<<trg, 256>>>(wq,   buf + O_WT + 0 * WSTEP);
    tr512_k<<<trg, 256>>>(wk,   buf + O_WT + 1 * WSTEP);
    tr512_k<<<trg, 256>>>(wv,   buf + O_WT + 2 * WSTEP);
    tr512_k<<<trg, 256>>>(wout, buf + O_WT + 3 * WSTEP);
    tr512_k<<<trg, 256>>>(mw1,  buf + O_WT + 4 * WSTEP);
    tr512_k<<<trg, 256>>>(mw2,  buf + O_WT + 5 * WSTEP);

    // 1) LayerNorms
    ln_k<<<NB * NT, 128>>>(diff, lndg, lndb, buf + O_FEAQ);
    ln_k<<<NB * NT, 128>>>(con,  lncg, lncb, buf + O_FEAKV);

    // 2) Q/K/V projections (tensor-core tf32)
    dim3 mg(4, 32);
    mgemm_k<0><<<mg, 256, mg_smem>>>(buf + O_FEAQ,  buf + O_WT + 0 * WSTEP, nullptr, buf + O_Q);
    mgemm_k<0><<<mg, 256, mg_smem>>>(buf + O_FEAKV, buf + O_WT + 1 * WSTEP, nullptr, buf + O_K);
    mgemm_k<0><<<mg, 256, mg_smem>>>(buf + O_FEAKV, buf + O_WT + 2 * WSTEP, nullptr, buf + O_V);

    // 3) Fourier attention == softmax(|QK^T|) @ V_flip / 8
    attn_k<<<dim3(NT / 64, NB * NHD), 256, attn_smem>>>(
        buf + O_Q, buf + O_K, buf + O_V, buf + O_ATT);

    // 4) per-sample stats + time MLP + FiLM
    stats_k<<<NB, 512>>>(buf + O_ATT, buf + O_STATS);
    tmlp1_k<<<dim3(4, NB), 256>>>(temb, wemd1, bemd1, buf + O_T1);
    tmlp2_k<<<dim3(4, NB), 256>>>(buf + O_T1, wemd2, bemd2, buf + O_T);
    film_k<<<(int)(SZ / 256), 256>>>(buf + O_ATT, buf + O_T, buf + O_STATS,
                                     buf + O_X);

    // 5) output projection
    mgemm_k<1><<<mg, 256, mg_smem>>>(buf + O_X, buf + O_WT + 3 * WSTEP, bout, buf + O_OUT1);

    // 6) FeedForward: LN -> Linear+GELU -> Linear
    ln_k<<<NB * NT, 128>>>(buf + O_OUT1, mlng, mlnb, buf + O_H);
    mgemm_k<2><<<mg, 256, mg_smem>>>(buf + O_H,  buf + O_WT + 4 * WSTEP, mb1, buf + O_H2);
    mgemm_k<1><<<mg, 256, mg_smem>>>(buf + O_H2, buf + O_WT + 5 * WSTEP, mb2, (float*)d_out);
}

// round 4
// speedup vs baseline: 1.3585x; 1.0037x over previous
#include <cuda_runtime.h>
#include <math.h>
#include <stdint.h>

// ---------------------------------------------------------------------------
// Problem constants
// ---------------------------------------------------------------------------
#define NT   1024          // sequence length
#define DIMF 512           // model dim
#define NB   4             // batch
#define NHD  8             // heads
#define HD   64            // head dim

static constexpr size_t SZ = (size_t)NB * NT * DIMF;   // 2,097,152 floats

// one big scratch buffer (device global: no allocations allowed)
__device__ float g_buf[SZ * 10 + 2 * 1024 * 1024];

static constexpr size_t O_FEAQ  = 0;
static constexpr size_t O_FEAKV = 1 * SZ;
static constexpr size_t O_Q     = 2 * SZ;
static constexpr size_t O_K     = 3 * SZ;
static constexpr size_t O_V     = 4 * SZ;
static constexpr size_t O_ATT   = 5 * SZ;
static constexpr size_t O_X     = 6 * SZ;
static constexpr size_t O_OUT1  = 7 * SZ;
static constexpr size_t O_H     = 8 * SZ;
static constexpr size_t O_H2    = 9 * SZ;
static constexpr size_t O_T1    = 10 * SZ;          // 4096 floats
static constexpr size_t O_T     = 10 * SZ + 4096;   // 4096 floats
static constexpr size_t O_STATS = 10 * SZ + 8192;   // 8 floats
static constexpr size_t O_WT    = 10 * SZ + 16384;  // 6 x 512*512 transposed weights
static constexpr size_t WSTEP   = (size_t)DIMF * DIMF;

// ---------------------------------------------------------------------------
// helpers
// ---------------------------------------------------------------------------
__device__ __forceinline__ uint32_t cvt_tf32(float x)
{
    uint32_t u;
    asm("cvt.rna.tf32.f32 %0, %1;" : "=r"(u) : "f"(x));
    return u;
}

__device__ __forceinline__ void mma_tf32(float c[4],
                                         uint32_t a0, uint32_t a1,
                                         uint32_t a2, uint32_t a3,
                                         uint32_t b0, uint32_t b1)
{
    asm volatile(
        "mma.sync.aligned.m16n8k8.row.col.f32.tf32.tf32.f32 "
        "{%0,%1,%2,%3}, {%4,%5,%6,%7}, {%8,%9}, {%0,%1,%2,%3};"
        : "+f"(c[0]), "+f"(c[1]), "+f"(c[2]), "+f"(c[3])
        : "r"(a0), "r"(a1), "r"(a2), "r"(a3), "r"(b0), "r"(b1));
}

__device__ __forceinline__ float gelu_exact(float x)
{
    return 0.5f * x * (1.0f + erff(x * 0.70710678118654752f));
}

// ---------------------------------------------------------------------------
// 512x512 transpose (weights -> [N][K] so the mma B operand is K-major)
// ---------------------------------------------------------------------------
__global__ void __launch_bounds__(256) tr512_k(const float* __restrict__ w,
                                               float* __restrict__ wt)
{
    __shared__ float t[32][33];
    const int tx = threadIdx.x & 31, ty = threadIdx.x >> 5;  // 32x8
    const int x = blockIdx.x * 32 + tx;
    const int y0 = blockIdx.y * 32;
#pragma unroll
    for (int j = 0; j < 32; j += 8)
        t[ty + j][tx] = w[(size_t)(y0 + ty + j) * 512 + x];
    __syncthreads();
    const int x2 = y0 + tx;
#pragma unroll
    for (int j = 0; j < 32; j += 8)
        wt[(size_t)(blockIdx.x * 32 + ty + j) * 512 + x2] = t[tx][ty + j];
}

// ---------------------------------------------------------------------------
// Tensor-core tf32 GEMM: C[4096,512] = A[4096,512] @ Bt^T  (Bt is [N,K])
// mma.sync m16n8k8, CTA tile 128x128, 8 warps (warp tile 64x32),
// K chunks of 32, double-buffered smem (pad 36).
// EPI: 0 = none, 1 = +bias, 2 = +bias then exact GELU
// ---------------------------------------------------------------------------
#define TPAD 36

template <int EPI>
__global__ void __launch_bounds__(256, 1) mgemm_k(const float* __restrict__ A,
                                                  const float* __restrict__ Bt,
                                                  const float* __restrict__ bias,
                                                  float* __restrict__ C)
{
    extern __shared__ float sm[];
    float* Asm[2] = {sm,            sm + 128 * TPAD};
    float* Bsm[2] = {sm + 2 * 128 * TPAD, sm + 3 * 128 * TPAD};

    const int tid = threadIdx.x;
    const int wid = tid >> 5, lane = tid & 31;
    const int g = lane >> 2, tq = lane & 3;
    const int m0w = (wid >> 2) * 64;      // warp row offset in tile
    const int n0w = (wid & 3) * 32;       // warp col offset in tile

    const int m0 = blockIdx.y * 128, n0 = blockIdx.x * 128;
    const float* Ab = A  + (size_t)m0 * 512;
    const float* Bb = Bt + (size_t)n0 * 512;

    // loader indices: 1024 float4 segments per operand, 4 per thread
    const int lrow[4] = {(tid + 0)   >> 3, (tid + 256) >> 3,
                         (tid + 512) >> 3, (tid + 768) >> 3};
    const int lseg = tid & 7;

    float acc[4][4][4] = {};   // [mi][ni][frag]

    // prologue: chunk 0 -> buffer 0
#pragma unroll
    for (int i = 0; i < 4; i++) {
        float4 a4 = *(const float4*)(Ab + (size_t)lrow[i] * 512 + lseg * 4);
        float4 b4 = *(const float4*)(Bb + (size_t)lrow[i] * 512 + lseg * 4);
        uint4* pa = (uint4*)&Asm[0][lrow[i] * TPAD + lseg * 4];
        uint4* pb = (uint4*)&Bsm[0][lrow[i] * TPAD + lseg * 4];
        *pa = make_uint4(cvt_tf32(a4.x), cvt_tf32(a4.y), cvt_tf32(a4.z), cvt_tf32(a4.w));
        *pb = make_uint4(cvt_tf32(b4.x), cvt_tf32(b4.y), cvt_tf32(b4.z), cvt_tf32(b4.w));
    }
    __syncthreads();

    for (int c = 0; c < 16; c++) {
        const int cur = c & 1, nxt = cur ^ 1;

        // issue next chunk's global loads early (latency hidden by compute)
        float4 sa[4], sb[4];
        if (c < 15) {
#pragma unroll
            for (int i = 0; i < 4; i++) {
                sa[i] = *(const float4*)(Ab + (size_t)lrow[i] * 512 + (c + 1) * 32 + lseg * 4);
                sb[i] = *(const float4*)(Bb + (size_t)lrow[i] * 512 + (c + 1) * 32 + lseg * 4);
            }
        }

        const float* As = Asm[cur];
        const float* Bs = Bsm[cur];
#pragma unroll
        for (int ks = 0; ks < 4; ks++) {
            const int kk = ks * 8;
            uint32_t af[4][4], bf[4][2];
#pragma unroll
            for (int mi = 0; mi < 4; mi++) {
                const int r = m0w + mi * 16 + g;
                af[mi][0] = __float_as_uint(As[(r    ) * TPAD + kk + tq]);
                af[mi][1] = __float_as_uint(As[(r + 8) * TPAD + kk + tq]);
                af[mi][2] = __float_as_uint(As[(r    ) * TPAD + kk + tq + 4]);
                af[mi][3] = __float_as_uint(As[(r + 8) * TPAD + kk + tq + 4]);
            }
#pragma unroll
            for (int ni = 0; ni < 4; ni++) {
                const int r = n0w + ni * 8 + g;
                bf[ni][0] = __float_as_uint(Bs[r * TPAD + kk + tq]);
                bf[ni][1] = __float_as_uint(Bs[r * TPAD + kk + tq + 4]);
            }
#pragma unroll
            for (int mi = 0; mi < 4; mi++)
#pragma unroll
                for (int ni = 0; ni < 4; ni++)
                    mma_tf32(acc[mi][ni], af[mi][0], af[mi][1], af[mi][2], af[mi][3],
                             bf[ni][0], bf[ni][1]);
        }

        if (c < 15) {
#pragma unroll
            for (int i = 0; i < 4; i++) {
                uint4* pa = (uint4*)&Asm[nxt][lrow[i] * TPAD + lseg * 4];
                uint4* pb = (uint4*)&Bsm[nxt][lrow[i] * TPAD + lseg * 4];
                *pa = make_uint4(cvt_tf32(sa[i].x), cvt_tf32(sa[i].y),
                                 cvt_tf32(sa[i].z), cvt_tf32(sa[i].w));
                *pb = make_uint4(cvt_tf32(sb[i].x), cvt_tf32(sb[i].y),
                                 cvt_tf32(sb[i].z), cvt_tf32(sb[i].w));
            }
        }
        __syncthreads();
    }

    // epilogue: c0/c1 -> (row, 2tq), c2/c3 -> (row+8, 2tq)
#pragma unroll
    for (int mi = 0; mi < 4; mi++) {
        const int row = m0 + m0w + mi * 16 + g;
#pragma unroll
        for (int ni = 0; ni < 4; ni++) {
            const int col = n0 + n0w + ni * 8 + 2 * tq;
            float v0 = acc[mi][ni][0], v1 = acc[mi][ni][1];
            float v2 = acc[mi][ni][2], v3 = acc[mi][ni][3];
            if (EPI >= 1) {
                const float b0 = bias[col], b1 = bias[col + 1];
                v0 += b0; v1 += b1; v2 += b0; v3 += b1;
            }
            if (EPI == 2) {
                v0 = gelu_exact(v0); v1 = gelu_exact(v1);
                v2 = gelu_exact(v2); v3 = gelu_exact(v3);
            }
            *(float2*)(C + (size_t)row * 512 + col)       = make_float2(v0, v1);
            *(float2*)(C + (size_t)(row + 8) * 512 + col) = make_float2(v2, v3);
        }
    }
}

// ---------------------------------------------------------------------------
// LayerNorm over last dim (512), one block per row, 128 threads x float4
// ---------------------------------------------------------------------------
__global__ void __launch_bounds__(128) ln_k(const float* __restrict__ x,
                                            const float* __restrict__ g,
                                            const float* __restrict__ b,
                                            float* __restrict__ y)
{
    const int row = blockIdx.x;
    const int t   = threadIdx.x;
    float4 v = ((const float4*)(x + (size_t)row * DIMF))[t];
    float s  = v.x + v.y + v.z + v.w;
    float s2 = v.x*v.x + v.y*v.y + v.z*v.z + v.w*v.w;
#pragma unroll
    for (int off = 16; off; off >>= 1) {
        s  += __shfl_xor_sync(0xffffffffu, s,  off);
        s2 += __shfl_xor_sync(0xffffffffu, s2, off);
    }
    __shared__ float sh[8];
    const int w = t >> 5, lane = t & 31;
    if (lane == 0) { sh[w] = s; sh[4 + w] = s2; }
    __syncthreads();
    s  = sh[0] + sh[1] + sh[2] + sh[3];
    s2 = sh[4] + sh[5] + sh[6] + sh[7];
    const float mu   = s * (1.0f / DIMF);
    const float var  = s2 * (1.0f / DIMF) - mu * mu;
    const float rstd = rsqrtf(var + 1e-5f);
    float4 gv = ((const float4*)g)[t];
    float4 bv = ((const float4*)b)[t];
    float4 r;
    r.x = (v.x - mu) * rstd * gv.x + bv.x;
    r.y = (v.y - mu) * rstd * gv.y + bv.y;
    r.z = (v.z - mu) * rstd * gv.z + bv.z;
    r.w = (v.w - mu) * rstd * gv.w + bv.w;
    ((float4*)(y + (size_t)row * DIMF))[t] = r;
}

// ---------------------------------------------------------------------------
// Fused attention: out = softmax_rows(|Q K^T|) @ V_flip / 8
// One CTA = one (b,h) x 64-row Q block. Online softmax over 16 key tiles.
// ---------------------------------------------------------------------------
__global__ void __launch_bounds__(256) attn_k(const float* __restrict__ Q,
                                              const float* __restrict__ K,
                                              const float* __restrict__ V,
                                              float* __restrict__ O)
{
    extern __shared__ float smf[];
    float* Qs  = smf;
    float* KsT = smf + 64 * 68;
    float* Vs  = smf + 2 * 64 * 68;
    float* Ps  = smf + 3 * 64 * 68;

    const int qb = blockIdx.x;
    const int bh = blockIdx.y;
    const int b = bh >> 3, h = bh & 7;
    const int tid = threadIdx.x;
    const int tx = tid & 15, ty = tid >> 4;

    const float* Qb_ = Q + ((size_t)b * NT) * DIMF + h * HD;
    const float* Kb_ = K + ((size_t)b * NT) * DIMF + h * HD;
    const float* Vb_ = V + ((size_t)b * NT) * DIMF + h * HD;

#pragma unroll 4
    for (int i = tid; i < 64 * 64; i += 256) {
        int r = i >> 6, c = i & 63;
        Qs[r * 68 + c] = Qb_[(size_t)(qb * 64 + r) * DIMF + c];
    }

    float m[4], l[4], o[4][4];
#pragma unroll
    for (int i = 0; i < 4; i++) {
        m[i] = -1e30f; l[i] = 0.0f;
#pragma unroll
        for (int j = 0; j < 4; j++) o[i][j] = 0.0f;
    }

    for (int kt = 0; kt < 16; kt++) {
        __syncthreads();
#pragma unroll 4
        for (int i = tid; i < 64 * 64; i += 256) {
            int r = i >> 6, c = i & 63;
            int kr = kt * 64 + r;
            KsT[c * 68 + r] = Kb_[(size_t)kr * DIMF + c];
            Vs[r * 68 + c] = Vb_[(size_t)((NT - kr) & (NT - 1)) * DIMF + c];
        }
        __syncthreads();

        float s[4][4] = {};
#pragma unroll
        for (int k4 = 0; k4 < 16; k4++) {
            float4 q4[4];
#pragma unroll
            for (int i = 0; i < 4; i++)
                q4[i] = *(const float4*)&Qs[(4 * ty + i) * 68 + 4 * k4];
#pragma unroll
            for (int kk = 0; kk < 4; kk++) {
                float4 kv = *(const float4*)&KsT[(4 * k4 + kk) * 68 + 4 * tx];
                float kvv[4] = {kv.x, kv.y, kv.z, kv.w};
#pragma unroll
                for (int i = 0; i < 4; i++) {
                    float qv = (kk == 0) ? q4[i].x : (kk == 1) ? q4[i].y
                             : (kk == 2) ? q4[i].z : q4[i].w;
#pragma unroll
                    for (int j = 0; j < 4; j++)
                        s[i][j] = fmaf(qv, kvv[j], s[i][j]);
                }
            }
        }

#pragma unroll
        for (int i = 0; i < 4; i++) {
            float mt = fmaxf(fmaxf(fabsf(s[i][0]), fabsf(s[i][1])),
                             fmaxf(fabsf(s[i][2]), fabsf(s[i][3])));
#pragma unroll
            for (int off = 8; off; off >>= 1)
                mt = fmaxf(mt, __shfl_xor_sync(0xffffffffu, mt, off, 16));
            float mn = fmaxf(m[i], mt);
            float corr = __expf(m[i] - mn);
            float4 p4;
            p4.x = __expf(fabsf(s[i][0]) - mn);
            p4.y = __expf(fabsf(s[i][1]) - mn);
            p4.z = __expf(fabsf(s[i][2]) - mn);
            p4.w = __expf(fabsf(s[i][3]) - mn);
            *(float4*)&Ps[(4 * ty + i) * 68 + 4 * tx] = p4;
            float ls = p4.x + p4.y + p4.z + p4.w;
#pragma unroll
            for (int off = 8; off; off >>= 1)
                ls += __shfl_xor_sync(0xffffffffu, ls, off, 16);
            l[i] = l[i] * corr + ls;
            m[i] = mn;
#pragma unroll
            for (int j = 0; j < 4; j++) o[i][j] *= corr;
        }
        __syncthreads();

#pragma unroll
        for (int c4 = 0; c4 < 16; c4++) {
            float4 p4[4];
#pragma unroll
            for (int i = 0; i < 4; i++)
                p4[i] = *(const float4*)&Ps[(4 * ty + i) * 68 + 4 * c4];
#pragma unroll
            for (int cc = 0; cc < 4; cc++) {
                float4 vv = *(const float4*)&Vs[(4 * c4 + cc) * 68 + 4 * tx];
                float vvv[4] = {vv.x, vv.y, vv.z, vv.w};
#pragma unroll
                for (int i = 0; i < 4; i++) {
                    float pv = (cc == 0) ? p4[i].x : (cc == 1) ? p4[i].y
                             : (cc == 2) ? p4[i].z : p4[i].w;
#pragma unroll
                    for (int j = 0; j < 4; j++)
                        o[i][j] = fmaf(pv, vvv[j], o[i][j]);
                }
            }
        }
    }

    float* Ob = O + ((size_t)(b * NT + qb * 64 + 4 * ty)) * DIMF + h * HD + 4 * tx;
#pragma unroll
    for (int i = 0; i < 4; i++) {
        float inv = 1.0f / (8.0f * l[i]);
        float4 r;
        r.x = o[i][0] * inv; r.y = o[i][1] * inv;
        r.z = o[i][2] * inv; r.w = o[i][3] * inv;
        *(float4*)(Ob + (size_t)i * DIMF) = r;
    }
}

// ---------------------------------------------------------------------------
// Per-sample mean / std (ddof=1) over (n, dim)
// ---------------------------------------------------------------------------
__global__ void __launch_bounds__(512) stats_k(const float* __restrict__ a,
                                               float* __restrict__ st)
{
    const int b = blockIdx.x;
    const float* p = a + (size_t)b * (NT * DIMF);
    float s = 0.0f, s2 = 0.0f;
    for (int i = threadIdx.x; i < NT * DIMF; i += 512) {
        float v = p[i];
        s += v;
        s2 = fmaf(v, v, s2);
    }
#pragma unroll
    for (int off = 16; off; off >>= 1) {
        s  += __shfl_xor_sync(0xffffffffu, s,  off);
        s2 += __shfl_xor_sync(0xffffffffu, s2, off);
    }
    __shared__ float sh[16], sh2[16];
    const int w = threadIdx.x >> 5;
    if ((threadIdx.x & 31) == 0) { sh[w] = s; sh2[w] = s2; }
    __syncthreads();
    if (threadIdx.x == 0) {
        float ts = 0.0f, ts2 = 0.0f;
        for (int i = 0; i < 16; i++) { ts += sh[i]; ts2 += sh2[i]; }
        double N   = (double)(NT * DIMF);
        double mu  = (double)ts / N;
        double var = ((double)ts2 - N * mu * mu) / (N - 1.0);
        st[b * 2 + 0] = (float)mu;
        st[b * 2 + 1] = (float)(1.0 / sqrt(var));
    }
}

// ---------------------------------------------------------------------------
// Time MLP (tiny)
// ---------------------------------------------------------------------------
__global__ void __launch_bounds__(256) tmlp1_k(const float* __restrict__ te,
                                               const float* __restrict__ w,
                                               const float* __restrict__ bb,
                                               float* __restrict__ h1)
{
    const int b = blockIdx.y;
    const int j = blockIdx.x * 256 + threadIdx.x;
    float acc = 0.0f;
    for (int k = 0; k < 512; k++)
        acc = fmaf(te[b * 512 + k], w[k * 1024 + j], acc);
    acc += bb[j];
    h1[b * 1024 + j] = acc / (1.0f + __expf(-acc));
}

__global__ void __launch_bounds__(256) tmlp2_k(const float* __restrict__ h1,
                                               const float* __restrict__ w,
                                               const float* __restrict__ bb,
                                               float* __restrict__ tout)
{
    const int b = blockIdx.y;
    const int j = blockIdx.x * 256 + threadIdx.x;
    float acc = 0.0f;
    for (int k = 0; k < 1024; k++)
        acc = fmaf(h1[b * 1024 + k], w[k * 1024 + j], acc);
    tout[b * 1024 + j] = acc + bb[j];
}

// ---------------------------------------------------------------------------
// FiLM apply
// ---------------------------------------------------------------------------
__global__ void __launch_bounds__(256) film_k(const float* __restrict__ a,
                                              const float* __restrict__ t,
                                              const float* __restrict__ st,
                                              float* __restrict__ x)
{
    const int idx = blockIdx.x * 256 + threadIdx.x;
    const int c = idx & 511;
    const int b = idx >> 19;
    const float mu = st[b * 2], rstd = st[b * 2 + 1];
    x[idx] = (a[idx] - mu) * rstd * t[b * 1024 + 512 + c] + t[b * 1024 + c];
}

// ---------------------------------------------------------------------------
// Launch
// ---------------------------------------------------------------------------
extern "C" void kernel_launch(void* const* d_in, const int* in_sizes, int n_in,
                              void* d_out, int out_size)
{
    const float* con   = (const float*)d_in[0];
    const float* diff  = (const float*)d_in[1];
    const float* temb  = (const float*)d_in[2];
    const float* lncg  = (const float*)d_in[3];
    const float* lncb  = (const float*)d_in[4];
    const float* lndg  = (const float*)d_in[5];
    const float* lndb  = (const float*)d_in[6];
    const float* wq    = (const float*)d_in[7];
    const float* wk    = (const float*)d_in[8];
    const float* wv    = (const float*)d_in[9];
    const float* wout  = (const float*)d_in[10];
    const float* bout  = (const float*)d_in[11];
    const float* wemd1 = (const float*)d_in[12];
    const float* bemd1 = (const float*)d_in[13];
    const float* wemd2 = (const float*)d_in[14];
    const float* bemd2 = (const float*)d_in[15];
    const float* mlng  = (const float*)d_in[16];
    const float* mlnb  = (const float*)d_in[17];
    const float* mw1   = (const float*)d_in[18];
    const float* mb1   = (const float*)d_in[19];
    const float* mw2   = (const float*)d_in[20];
    const float* mb2   = (const float*)d_in[21];

    float* buf = nullptr;
    cudaGetSymbolAddress((void**)&buf, g_buf);

    const int attn_smem = 4 * 64 * 68 * 4;            // 69632 B
    cudaFuncSetAttribute(attn_k, cudaFuncAttributeMaxDynamicSharedMemorySize,
                         attn_smem);
    const int mg_smem = 4 * 128 * TPAD * 4;           // 73728 B
    cudaFuncSetAttribute(mgemm_k<0>, cudaFuncAttributeMaxDynamicSharedMemorySize, mg_smem);
    cudaFuncSetAttribute(mgemm_k<1>, cudaFuncAttributeMaxDynamicSharedMemorySize, mg_smem);
    cudaFuncSetAttribute(mgemm_k<2>, cudaFuncAttributeMaxDynamicSharedMemorySize, mg_smem);

    // 0) transpose the six 512x512 weights to [N,K]
    dim3 trg(16, 16);
    tr512_k<<<trg, 256>>>(wq,   buf + O_WT + 0 * WSTEP);
    tr512_k<<<trg, 256>>>(wk,   buf + O_WT + 1 * WSTEP);
    tr512_k<<<trg, 256>>>(wv,   buf + O_WT + 2 * WSTEP);
    tr512_k<<<trg, 256>>>(wout, buf + O_WT + 3 * WSTEP);
    tr512_k<<<trg, 256>>>(mw1,  buf + O_WT + 4 * WSTEP);
    tr512_k<<<trg, 256>>>(mw2,  buf + O_WT + 5 * WSTEP);

    // 1) LayerNorms
    ln_k<<<NB * NT, 128>>>(diff, lndg, lndb, buf + O_FEAQ);
    ln_k<<<NB * NT, 128>>>(con,  lncg, lncb, buf + O_FEAKV);

    // 2) Q/K/V projections (tensor-core tf32)
    dim3 mg(4, 32);
    mgemm_k<0><<<mg, 256, mg_smem>>>(buf + O_FEAQ,  buf + O_WT + 0 * WSTEP, nullptr, buf + O_Q);
    mgemm_k<0><<<mg, 256, mg_smem>>>(buf + O_FEAKV, buf + O_WT + 1 * WSTEP, nullptr, buf + O_K);
    mgemm_k<0><<<mg, 256, mg_smem>>>(buf + O_FEAKV, buf + O_WT + 2 * WSTEP, nullptr, buf + O_V);

    // 3) Fourier attention == softmax(|QK^T|) @ V_flip / 8
    attn_k<<<dim3(NT / 64, NB * NHD), 256, attn_smem>>>(
        buf + O_Q, buf + O_K, buf + O_V, buf + O_ATT);

    // 4) per-sample stats + time MLP + FiLM
    stats_k<<<NB, 512>>>(buf + O_ATT, buf + O_STATS);
    tmlp1_k<<<dim3(4, NB), 256>>>(temb, wemd1, bemd1, buf + O_T1);
    tmlp2_k<<<dim3(4, NB), 256>>>(buf + O_T1, wemd2, bemd2, buf + O_T);
    film_k<<<(int)(SZ / 256), 256>>>(buf + O_ATT, buf + O_T, buf + O_STATS,
                                     buf + O_X);

    // 5) output projection
    mgemm_k<1><<<mg, 256, mg_smem>>>(buf + O_X, buf + O_WT + 3 * WSTEP, bout, buf + O_OUT1);

    // 6) FeedForward: LN -> Linear+GELU -> Linear
    ln_k<<<NB * NT, 128>>>(buf + O_OUT1, mlng, mlnb, buf + O_H);
    mgemm_k<2><<<mg, 256, mg_smem>>>(buf + O_H,  buf + O_WT + 4 * WSTEP, mb1, buf + O_H2);
    mgemm_k<1><<<mg, 256, mg_smem>>>(buf + O_H2, buf + O_WT + 5 * WSTEP, mb2, (float*)d_out);
}

// round 5
// speedup vs baseline: 2.3416x; 1.7236x over previous
#include <cuda_runtime.h>
#include <cuda_fp16.h>
#include <math.h>
#include <stdint.h>

// ---------------------------------------------------------------------------
// Problem constants
// ---------------------------------------------------------------------------
#define NT   1024          // sequence length
#define DIMF 512           // model dim
#define NB   4             // batch
#define NHD  8             // heads
#define HD   64            // head dim

static constexpr size_t SZ = (size_t)NB * NT * DIMF;   // 2,097,152 floats

// one big scratch buffer (device global: no allocations allowed)
__device__ float g_buf[SZ * 10 + 2 * 1024 * 1024];

static constexpr size_t O_FEAQ  = 0;
static constexpr size_t O_FEAKV = 1 * SZ;
static constexpr size_t O_Q     = 2 * SZ;
static constexpr size_t O_K     = 3 * SZ;
static constexpr size_t O_V     = 4 * SZ;
static constexpr size_t O_ATT   = 5 * SZ;
static constexpr size_t O_X     = 6 * SZ;
static constexpr size_t O_OUT1  = 7 * SZ;
static constexpr size_t O_H     = 8 * SZ;
static constexpr size_t O_H2    = 9 * SZ;
static constexpr size_t O_T1    = 10 * SZ;          // 4096 floats
static constexpr size_t O_T     = 10 * SZ + 4096;   // 4096 floats
static constexpr size_t O_STATS = 10 * SZ + 8192;   // 8 floats
static constexpr size_t O_WT    = 10 * SZ + 16384;  // 6 x 512*512 transposed weights
static constexpr size_t WSTEP   = (size_t)DIMF * DIMF;

// ---------------------------------------------------------------------------
// helpers
// ---------------------------------------------------------------------------
__device__ __forceinline__ uint32_t pack_h2(float a, float b)
{
    __half2 h = __floats2half2_rn(a, b);
    return *(uint32_t*)&h;
}

__device__ __forceinline__ void mma_f16(float c[4],
                                        uint32_t a0, uint32_t a1,
                                        uint32_t a2, uint32_t a3,
                                        uint32_t b0, uint32_t b1)
{
    asm volatile(
        "mma.sync.aligned.m16n8k16.row.col.f32.f16.f16.f32 "
        "{%0,%1,%2,%3}, {%4,%5,%6,%7}, {%8,%9}, {%0,%1,%2,%3};"
        : "+f"(c[0]), "+f"(c[1]), "+f"(c[2]), "+f"(c[3])
        : "r"(a0), "r"(a1), "r"(a2), "r"(a3), "r"(b0), "r"(b1));
}

__device__ __forceinline__ float gelu_exact(float x)
{
    return 0.5f * x * (1.0f + erff(x * 0.70710678118654752f));
}

// ---------------------------------------------------------------------------
// Batched 512x512 transpose: 6 weights -> [N][K] (fp32)
// ---------------------------------------------------------------------------
__global__ void __launch_bounds__(256) tr512x6_k(const float* __restrict__ w0,
                                                 const float* __restrict__ w1,
                                                 const float* __restrict__ w2,
                                                 const float* __restrict__ w3,
                                                 const float* __restrict__ w4,
                                                 const float* __restrict__ w5,
                                                 float* __restrict__ out)
{
    const float* srcs[6] = {w0, w1, w2, w3, w4, w5};
    const float* w = srcs[blockIdx.z];
    float* wt = out + (size_t)blockIdx.z * WSTEP;

    __shared__ float t[32][33];
    const int tx = threadIdx.x & 31, ty = threadIdx.x >> 5;  // 32x8
    const int x = blockIdx.x * 32 + tx;
    const int y0 = blockIdx.y * 32;
#pragma unroll
    for (int j = 0; j < 32; j += 8)
        t[ty + j][tx] = w[(size_t)(y0 + ty + j) * 512 + x];
    __syncthreads();
    const int x2 = y0 + tx;
#pragma unroll
    for (int j = 0; j < 32; j += 8)
        wt[(size_t)(blockIdx.x * 32 + ty + j) * 512 + x2] = t[tx][ty + j];
}

// ---------------------------------------------------------------------------
// fp16 tensor-core GEMM: C[4096,512] = A[4096,512] @ Bt^T  (Bt is [N,K], fp32)
// mma.sync m16n8k16, CTA 128x128, 8 warps (warp tile 64x32), K chunks of 32,
// double-buffered half-precision smem. EPI: 0 none, 1 +bias, 2 +bias+GELU
// ---------------------------------------------------------------------------
#define KPH 40   // halves per smem row (20 words -> conflict-free frag loads)

template <int EPI>
__global__ void __launch_bounds__(256, 1) hgemm_k(const float* __restrict__ A,
                                                  const float* __restrict__ Bt,
                                                  const float* __restrict__ bias,
                                                  float* __restrict__ C)
{
    __shared__ __half Ash[2][128 * KPH];
    __shared__ __half Bsh[2][128 * KPH];

    const int tid = threadIdx.x;
    const int wid = tid >> 5, lane = tid & 31;
    const int g = lane >> 2, tq = lane & 3;
    const int m0w = (wid >> 2) * 64;
    const int n0w = (wid & 3) * 32;

    const int m0 = blockIdx.y * 128, n0 = blockIdx.x * 128;
    const float* Ab = A  + (size_t)m0 * 512;
    const float* Bb = Bt + (size_t)n0 * 512;

    const int lr = tid >> 3;   // 32 rows per pass, 4 passes
    const int ls = tid & 7;    // float4 segment

    float acc[4][4][4] = {};

    // prologue: chunk 0 -> buffer 0
#pragma unroll
    for (int p = 0; p < 4; p++) {
        const int row = lr + 32 * p;
        float4 a4 = *(const float4*)(Ab + (size_t)row * 512 + ls * 4);
        float4 b4 = *(const float4*)(Bb + (size_t)row * 512 + ls * 4);
        *(uint2*)&Ash[0][row * KPH + ls * 4] =
            make_uint2(pack_h2(a4.x, a4.y), pack_h2(a4.z, a4.w));
        *(uint2*)&Bsh[0][row * KPH + ls * 4] =
            make_uint2(pack_h2(b4.x, b4.y), pack_h2(b4.z, b4.w));
    }
    __syncthreads();

    for (int c = 0; c < 16; c++) {
        const int cur = c & 1, nxt = cur ^ 1;

        float4 sa[4], sb[4];
        if (c < 15) {
#pragma unroll
            for (int p = 0; p < 4; p++) {
                const int row = lr + 32 * p;
                sa[p] = *(const float4*)(Ab + (size_t)row * 512 + (c + 1) * 32 + ls * 4);
                sb[p] = *(const float4*)(Bb + (size_t)row * 512 + (c + 1) * 32 + ls * 4);
            }
        }

        const __half* As = Ash[cur];
        const __half* Bs = Bsh[cur];
#pragma unroll
        for (int ks = 0; ks < 2; ks++) {
            const int kk = ks * 16;
            uint32_t af[4][4], bf[4][2];
#pragma unroll
            for (int mi = 0; mi < 4; mi++) {
                const int r = m0w + mi * 16 + g;
                af[mi][0] = *(const uint32_t*)&As[(r    ) * KPH + kk + 2 * tq];
                af[mi][1] = *(const uint32_t*)&As[(r + 8) * KPH + kk + 2 * tq];
                af[mi][2] = *(const uint32_t*)&As[(r    ) * KPH + kk + 8 + 2 * tq];
                af[mi][3] = *(const uint32_t*)&As[(r + 8) * KPH + kk + 8 + 2 * tq];
            }
#pragma unroll
            for (int ni = 0; ni < 4; ni++) {
                const int r = n0w + ni * 8 + g;
                bf[ni][0] = *(const uint32_t*)&Bs[r * KPH + kk + 2 * tq];
                bf[ni][1] = *(const uint32_t*)&Bs[r * KPH + kk + 8 + 2 * tq];
            }
#pragma unroll
            for (int mi = 0; mi < 4; mi++)
#pragma unroll
                for (int ni = 0; ni < 4; ni++)
                    mma_f16(acc[mi][ni], af[mi][0], af[mi][1], af[mi][2], af[mi][3],
                            bf[ni][0], bf[ni][1]);
        }

        if (c < 15) {
#pragma unroll
            for (int p = 0; p < 4; p++) {
                const int row = lr + 32 * p;
                *(uint2*)&Ash[nxt][row * KPH + ls * 4] =
                    make_uint2(pack_h2(sa[p].x, sa[p].y), pack_h2(sa[p].z, sa[p].w));
                *(uint2*)&Bsh[nxt][row * KPH + ls * 4] =
                    make_uint2(pack_h2(sb[p].x, sb[p].y), pack_h2(sb[p].z, sb[p].w));
            }
        }
        __syncthreads();
    }

#pragma unroll
    for (int mi = 0; mi < 4; mi++) {
        const int row = m0 + m0w + mi * 16 + g;
#pragma unroll
        for (int ni = 0; ni < 4; ni++) {
            const int col = n0 + n0w + ni * 8 + 2 * tq;
            float v0 = acc[mi][ni][0], v1 = acc[mi][ni][1];
            float v2 = acc[mi][ni][2], v3 = acc[mi][ni][3];
            if (EPI >= 1) {
                const float b0 = bias[col], b1 = bias[col + 1];
                v0 += b0; v1 += b1; v2 += b0; v3 += b1;
            }
            if (EPI == 2) {
                v0 = gelu_exact(v0); v1 = gelu_exact(v1);
                v2 = gelu_exact(v2); v3 = gelu_exact(v3);
            }
            *(float2*)(C + (size_t)row * 512 + col)       = make_float2(v0, v1);
            *(float2*)(C + (size_t)(row + 8) * 512 + col) = make_float2(v2, v3);
        }
    }
}

// ---------------------------------------------------------------------------
// Tensor-core attention: out = softmax_rows(|Q K^T|) @ V_flip / 8
// One CTA (4 warps) = one (b,h) x 64-row Q block; 16 key tiles of 64.
// QK^T in exact hi/lo fp16 split (3 mmas), PV in fp16 (P direct from regs).
// ---------------------------------------------------------------------------
#define APH 72   // halves per smem row (36 words -> conflict-free frag loads)

__global__ void __launch_bounds__(128) attnh_k(const float* __restrict__ Q,
                                               const float* __restrict__ K,
                                               const float* __restrict__ V,
                                               float* __restrict__ O)
{
    __shared__ __half Qhi[64 * APH], Qlo[64 * APH];
    __shared__ __half Khi[64 * APH], Klo[64 * APH];
    __shared__ __half Vt[64 * APH];          // [d][kpos]

    const int qb = blockIdx.x;               // 0..15
    const int bh = blockIdx.y;               // 0..31
    const int b = bh >> 3, h = bh & 7;
    const int tid = threadIdx.x;
    const int wid = tid >> 5, lane = tid & 31;
    const int g = lane >> 2, tq = lane & 3;

    const float* Qb = Q + ((size_t)b * NT + qb * 64) * DIMF + h * HD;
    const float* Kb = K + (size_t)b * NT * DIMF + h * HD;
    const float* Vb = V + (size_t)b * NT * DIMF + h * HD;

    // load Q tile, split hi/lo
    for (int i = tid; i < 64 * 64; i += 128) {
        const int r = i >> 6, c = i & 63;
        const float v = Qb[(size_t)r * DIMF + c];
        const __half hi = __float2half_rn(v);
        Qhi[r * APH + c] = hi;
        Qlo[r * APH + c] = __float2half_rn(v - __half2float(hi));
    }

    float m0 = -1e30f, m1 = -1e30f, l0 = 0.0f, l1 = 0.0f;
    float o[8][4];
#pragma unroll
    for (int i = 0; i < 8; i++)
#pragma unroll
        for (int j = 0; j < 4; j++) o[i][j] = 0.0f;

    const int qrow0 = wid * 16 + g;

    for (int kt = 0; kt < 16; kt++) {
        __syncthreads();
        for (int i = tid; i < 64 * 64; i += 128) {
            const int r = i >> 6, c = i & 63;
            const int kr = kt * 64 + r;
            const float kv = Kb[(size_t)kr * DIMF + c];
            const __half khi = __float2half_rn(kv);
            Khi[r * APH + c] = khi;
            Klo[r * APH + c] = __float2half_rn(kv - __half2float(khi));
            const float vv = Vb[(size_t)((NT - kr) & (NT - 1)) * DIMF + c];
            Vt[c * APH + r] = __float2half_rn(vv);   // transposed
        }
        __syncthreads();

        // ---- S = Q K^T (hi/lo split) ----
        float s[8][4];
#pragma unroll
        for (int i = 0; i < 8; i++)
#pragma unroll
            for (int j = 0; j < 4; j++) s[i][j] = 0.0f;

#pragma unroll
        for (int ks = 0; ks < 4; ks++) {
            const int kk = ks * 16;
            const uint32_t ah0 = *(const uint32_t*)&Qhi[(qrow0    ) * APH + kk + 2 * tq];
            const uint32_t ah1 = *(const uint32_t*)&Qhi[(qrow0 + 8) * APH + kk + 2 * tq];
            const uint32_t ah2 = *(const uint32_t*)&Qhi[(qrow0    ) * APH + kk + 8 + 2 * tq];
            const uint32_t ah3 = *(const uint32_t*)&Qhi[(qrow0 + 8) * APH + kk + 8 + 2 * tq];
            const uint32_t al0 = *(const uint32_t*)&Qlo[(qrow0    ) * APH + kk + 2 * tq];
            const uint32_t al1 = *(const uint32_t*)&Qlo[(qrow0 + 8) * APH + kk + 2 * tq];
            const uint32_t al2 = *(const uint32_t*)&Qlo[(qrow0    ) * APH + kk + 8 + 2 * tq];
            const uint32_t al3 = *(const uint32_t*)&Qlo[(qrow0 + 8) * APH + kk + 8 + 2 * tq];
#pragma unroll
            for (int ni = 0; ni < 8; ni++) {
                const int kr = ni * 8 + g;
                const uint32_t bh0 = *(const uint32_t*)&Khi[kr * APH + kk + 2 * tq];
                const uint32_t bh1 = *(const uint32_t*)&Khi[kr * APH + kk + 8 + 2 * tq];
                const uint32_t bl0 = *(const uint32_t*)&Klo[kr * APH + kk + 2 * tq];
                const uint32_t bl1 = *(const uint32_t*)&Klo[kr * APH + kk + 8 + 2 * tq];
                mma_f16(s[ni], ah0, ah1, ah2, ah3, bh0, bh1);
                mma_f16(s[ni], ah0, ah1, ah2, ah3, bl0, bl1);
                mma_f16(s[ni], al0, al1, al2, al3, bh0, bh1);
            }
        }

        // ---- online softmax on |s| (rows g and g+8) ----
        float mt0 = -1e30f, mt1 = -1e30f;
#pragma unroll
        for (int ni = 0; ni < 8; ni++) {
            mt0 = fmaxf(mt0, fmaxf(fabsf(s[ni][0]), fabsf(s[ni][1])));
            mt1 = fmaxf(mt1, fmaxf(fabsf(s[ni][2]), fabsf(s[ni][3])));
        }
        mt0 = fmaxf(mt0, __shfl_xor_sync(0xffffffffu, mt0, 1));
        mt0 = fmaxf(mt0, __shfl_xor_sync(0xffffffffu, mt0, 2));
        mt1 = fmaxf(mt1, __shfl_xor_sync(0xffffffffu, mt1, 1));
        mt1 = fmaxf(mt1, __shfl_xor_sync(0xffffffffu, mt1, 2));

        const float mn0 = fmaxf(m0, mt0), mn1 = fmaxf(m1, mt1);
        const float corr0 = __expf(m0 - mn0), corr1 = __expf(m1 - mn1);

        uint32_t ph[8][2];
        float la0 = 0.0f, la1 = 0.0f;
#pragma unroll
        for (int ni = 0; ni < 8; ni++) {
            const float p0 = __expf(fabsf(s[ni][0]) - mn0);
            const float p1 = __expf(fabsf(s[ni][1]) - mn0);
            const float p2 = __expf(fabsf(s[ni][2]) - mn1);
            const float p3 = __expf(fabsf(s[ni][3]) - mn1);
            ph[ni][0] = pack_h2(p0, p1);
            ph[ni][1] = pack_h2(p2, p3);
            la0 += p0 + p1;
            la1 += p2 + p3;
        }
        la0 += __shfl_xor_sync(0xffffffffu, la0, 1);
        la0 += __shfl_xor_sync(0xffffffffu, la0, 2);
        la1 += __shfl_xor_sync(0xffffffffu, la1, 1);
        la1 += __shfl_xor_sync(0xffffffffu, la1, 2);

        l0 = l0 * corr0 + la0; m0 = mn0;
        l1 = l1 * corr1 + la1; m1 = mn1;
#pragma unroll
        for (int nd = 0; nd < 8; nd++) {
            o[nd][0] *= corr0; o[nd][1] *= corr0;
            o[nd][2] *= corr1; o[nd][3] *= corr1;
        }

        // ---- O += P @ Vt (P direct from registers) ----
#pragma unroll
        for (int ks = 0; ks < 4; ks++) {
            const int kk = ks * 16;
            const uint32_t a0 = ph[2 * ks][0];
            const uint32_t a1 = ph[2 * ks][1];
            const uint32_t a2 = ph[2 * ks + 1][0];
            const uint32_t a3 = ph[2 * ks + 1][1];
#pragma unroll
            for (int nd = 0; nd < 8; nd++) {
                const int dr = nd * 8 + g;
                const uint32_t b0 = *(const uint32_t*)&Vt[dr * APH + kk + 2 * tq];
                const uint32_t b1 = *(const uint32_t*)&Vt[dr * APH + kk + 8 + 2 * tq];
                mma_f16(o[nd], a0, a1, a2, a3, b0, b1);
            }
        }
    }

    // ---- write out: rows qb*64 + qrow0 (+8), cols h*64 + nd*8 + 2tq ----
    const float inv0 = 1.0f / (8.0f * l0);
    const float inv1 = 1.0f / (8.0f * l1);
    float* Ob0 = O + ((size_t)(b * NT + qb * 64 + qrow0)) * DIMF + h * HD;
    float* Ob1 = Ob0 + (size_t)8 * DIMF;
#pragma unroll
    for (int nd = 0; nd < 8; nd++) {
        const int col = nd * 8 + 2 * tq;
        *(float2*)(Ob0 + col) = make_float2(o[nd][0] * inv0, o[nd][1] * inv0);
        *(float2*)(Ob1 + col) = make_float2(o[nd][2] * inv1, o[nd][3] * inv1);
    }
}

// ---------------------------------------------------------------------------
// LayerNorm over last dim (512), one block per row, 128 threads x float4
// ---------------------------------------------------------------------------
__global__ void __launch_bounds__(128) ln_k(const float* __restrict__ x,
                                            const float* __restrict__ g,
                                            const float* __restrict__ b,
                                            float* __restrict__ y)
{
    const int row = blockIdx.x;
    const int t   = threadIdx.x;
    float4 v = ((const float4*)(x + (size_t)row * DIMF))[t];
    float s  = v.x + v.y + v.z + v.w;
    float s2 = v.x*v.x + v.y*v.y + v.z*v.z + v.w*v.w;
#pragma unroll
    for (int off = 16; off; off >>= 1) {
        s  += __shfl_xor_sync(0xffffffffu, s,  off);
        s2 += __shfl_xor_sync(0xffffffffu, s2, off);
    }
    __shared__ float sh[8];
    const int w = t >> 5, lane = t & 31;
    if (lane == 0) { sh[w] = s; sh[4 + w] = s2; }
    __syncthreads();
    s  = sh[0] + sh[1] + sh[2] + sh[3];
    s2 = sh[4] + sh[5] + sh[6] + sh[7];
    const float mu   = s * (1.0f / DIMF);
    const float var  = s2 * (1.0f / DIMF) - mu * mu;
    const float rstd = rsqrtf(var + 1e-5f);
    float4 gv = ((const float4*)g)[t];
    float4 bv = ((const float4*)b)[t];
    float4 r;
    r.x = (v.x - mu) * rstd * gv.x + bv.x;
    r.y = (v.y - mu) * rstd * gv.y + bv.y;
    r.z = (v.z - mu) * rstd * gv.z + bv.z;
    r.w = (v.w - mu) * rstd * gv.w + bv.w;
    ((float4*)(y + (size_t)row * DIMF))[t] = r;
}

// ---------------------------------------------------------------------------
// Per-sample mean / std (ddof=1) over (n, dim)
// ---------------------------------------------------------------------------
__global__ void __launch_bounds__(512) stats_k(const float* __restrict__ a,
                                               float* __restrict__ st)
{
    const int b = blockIdx.x;
    const float* p = a + (size_t)b * (NT * DIMF);
    float s = 0.0f, s2 = 0.0f;
    for (int i = threadIdx.x; i < NT * DIMF; i += 512) {
        float v = p[i];
        s += v;
        s2 = fmaf(v, v, s2);
    }
#pragma unroll
    for (int off = 16; off; off >>= 1) {
        s  += __shfl_xor_sync(0xffffffffu, s,  off);
        s2 += __shfl_xor_sync(0xffffffffu, s2, off);
    }
    __shared__ float sh[16], sh2[16];
    const int w = threadIdx.x >> 5;
    if ((threadIdx.x & 31) == 0) { sh[w] = s; sh2[w] = s2; }
    __syncthreads();
    if (threadIdx.x == 0) {
        float ts = 0.0f, ts2 = 0.0f;
        for (int i = 0; i < 16; i++) { ts += sh[i]; ts2 += sh2[i]; }
        double N   = (double)(NT * DIMF);
        double mu  = (double)ts / N;
        double var = ((double)ts2 - N * mu * mu) / (N - 1.0);
        st[b * 2 + 0] = (float)mu;
        st[b * 2 + 1] = (float)(1.0 / sqrt(var));
    }
}

// ---------------------------------------------------------------------------
// Time MLP (tiny)
// ---------------------------------------------------------------------------
__global__ void __launch_bounds__(256) tmlp1_k(const float* __restrict__ te,
                                               const float* __restrict__ w,
                                               const float* __restrict__ bb,
                                               float* __restrict__ h1)
{
    const int b = blockIdx.y;
    const int j = blockIdx.x * 256 + threadIdx.x;
    float acc = 0.0f;
    for (int k = 0; k < 512; k++)
        acc = fmaf(te[b * 512 + k], w[k * 1024 + j], acc);
    acc += bb[j];
    h1[b * 1024 + j] = acc / (1.0f + __expf(-acc));
}

__global__ void __launch_bounds__(256) tmlp2_k(const float* __restrict__ h1,
                                               const float* __restrict__ w,
                                               const float* __restrict__ bb,
                                               float* __restrict__ tout)
{
    const int b = blockIdx.y;
    const int j = blockIdx.x * 256 + threadIdx.x;
    float acc = 0.0f;
    for (int k = 0; k < 1024; k++)
        acc = fmaf(h1[b * 1024 + k], w[k * 1024 + j], acc);
    tout[b * 1024 + j] = acc + bb[j];
}

// ---------------------------------------------------------------------------
// FiLM apply
// ---------------------------------------------------------------------------
__global__ void __launch_bounds__(256) film_k(const float* __restrict__ a,
                                              const float* __restrict__ t,
                                              const float* __restrict__ st,
                                              float* __restrict__ x)
{
    const int idx = blockIdx.x * 256 + threadIdx.x;
    const int c = idx & 511;
    const int b = idx >> 19;
    const float mu = st[b * 2], rstd = st[b * 2 + 1];
    x[idx] = (a[idx] - mu) * rstd * t[b * 1024 + 512 + c] + t[b * 1024 + c];
}

// ---------------------------------------------------------------------------
// Launch
// ---------------------------------------------------------------------------
extern "C" void kernel_launch(void* const* d_in, const int* in_sizes, int n_in,
                              void* d_out, int out_size)
{
    const float* con   = (const float*)d_in[0];
    const float* diff  = (const float*)d_in[1];
    const float* temb  = (const float*)d_in[2];
    const float* lncg  = (const float*)d_in[3];
    const float* lncb  = (const float*)d_in[4];
    const float* lndg  = (const float*)d_in[5];
    const float* lndb  = (const float*)d_in[6];
    const float* wq    = (const float*)d_in[7];
    const float* wk    = (const float*)d_in[8];
    const float* wv    = (const float*)d_in[9];
    const float* wout  = (const float*)d_in[10];
    const float* bout  = (const float*)d_in[11];
    const float* wemd1 = (const float*)d_in[12];
    const float* bemd1 = (const float*)d_in[13];
    const float* wemd2 = (const float*)d_in[14];
    const float* bemd2 = (const float*)d_in[15];
    const float* mlng  = (const float*)d_in[16];
    const float* mlnb  = (const float*)d_in[17];
    const float* mw1   = (const float*)d_in[18];
    const float* mb1   = (const float*)d_in[19];
    const float* mw2   = (const float*)d_in[20];
    const float* mb2   = (const float*)d_in[21];

    float* buf = nullptr;
    cudaGetSymbolAddress((void**)&buf, g_buf);

    // 0) transpose the six 512x512 weights to [N,K] (one batched launch)
    tr512x6_k<<<dim3(16, 16, 6), 256>>>(wq, wk, wv, wout, mw1, mw2, buf + O_WT);

    // 1) LayerNorms
    ln_k<<<NB * NT, 128>>>(diff, lndg, lndb, buf + O_FEAQ);
    ln_k<<<NB * NT, 128>>>(con,  lncg, lncb, buf + O_FEAKV);

    // 2) Q/K/V projections (fp16 tensor cores)
    dim3 mg(4, 32);
    hgemm_k<0><<<mg, 256>>>(buf + O_FEAQ,  buf + O_WT + 0 * WSTEP, nullptr, buf + O_Q);
    hgemm_k<0><<<mg, 256>>>(buf + O_FEAKV, buf + O_WT + 1 * WSTEP, nullptr, buf + O_K);
    hgemm_k<0><<<mg, 256>>>(buf + O_FEAKV, buf + O_WT + 2 * WSTEP, nullptr, buf + O_V);

    // 3) Fourier attention == softmax(|QK^T|) @ V_flip / 8 (fp16 tensor cores)
    attnh_k<<<dim3(NT / 64, NB * NHD), 128>>>(
        buf + O_Q, buf + O_K, buf + O_V, buf + O_ATT);

    // 4) per-sample stats + time MLP + FiLM
    stats_k<<<NB, 512>>>(buf + O_ATT, buf + O_STATS);
    tmlp1_k<<<dim3(4, NB), 256>>>(temb, wemd1, bemd1, buf + O_T1);
    tmlp2_k<<<dim3(4, NB), 256>>>(buf + O_T1, wemd2, bemd2, buf + O_T);
    film_k<<<(int)(SZ / 256), 256>>>(buf + O_ATT, buf + O_T, buf + O_STATS,
                                     buf + O_X);

    // 5) output projection
    hgemm_k<1><<<mg, 256>>>(buf + O_X, buf + O_WT + 3 * WSTEP, bout, buf + O_OUT1);

    // 6) FeedForward: LN -> Linear+GELU -> Linear
    ln_k<<<NB * NT, 128>>>(buf + O_OUT1, mlng, mlnb, buf + O_H);
    hgemm_k<2><<<mg, 256>>>(buf + O_H,  buf + O_WT + 4 * WSTEP, mb1, buf + O_H2);
    hgemm_k<1><<<mg, 256>>>(buf + O_H2, buf + O_WT + 5 * WSTEP, mb2, (float*)d_out);
}

// round 6
// speedup vs baseline: 2.5642x; 1.0951x over previous
#include <cuda_runtime.h>
#include <cuda_fp16.h>
#include <math.h>
#include <stdint.h>

// ---------------------------------------------------------------------------
// Problem constants
// ---------------------------------------------------------------------------
#define NT   1024
#define DIMF 512
#define NB   4
#define NHD  8
#define HD   64

static constexpr size_t SZ = (size_t)NB * NT * DIMF;   // 2,097,152

__device__ float g_buf[SZ * 10 + 2 * 1024 * 1024];

// fp32 region
static constexpr size_t O_ATT   = 0;
static constexpr size_t O_OUT1  = 1 * SZ;
static constexpr size_t O_T1    = 2 * SZ;           // 4096 floats
static constexpr size_t O_T     = 2 * SZ + 4096;    // 4096 floats
static constexpr size_t O_STATS = 2 * SZ + 8192;    // 8 floats
static constexpr size_t O_HB    = 2 * SZ + 8448;    // half region starts here (floats)

// half-region offsets (in halves)
static constexpr size_t H_FEAQ  = 0;
static constexpr size_t H_FEAKV = 1 * SZ;
static constexpr size_t H_QHI   = 2 * SZ;
static constexpr size_t H_QLO   = 3 * SZ;
static constexpr size_t H_KHI   = 4 * SZ;
static constexpr size_t H_KLO   = 5 * SZ;
static constexpr size_t H_VH    = 6 * SZ;
static constexpr size_t H_VT    = 7 * SZ;           // [32][64][1024]
static constexpr size_t H_X     = 8 * SZ;
static constexpr size_t H_H     = 9 * SZ;
static constexpr size_t H_H2    = 10 * SZ;
static constexpr size_t H_WT    = 11 * SZ;          // 6 x 512*512 halves
static constexpr size_t WSTEP   = (size_t)DIMF * DIMF;

// ---------------------------------------------------------------------------
// helpers
// ---------------------------------------------------------------------------
__device__ __forceinline__ uint32_t pack_h2(float a, float b)
{
    __half2 h = __floats2half2_rn(a, b);
    return *(uint32_t*)&h;
}

__device__ __forceinline__ void mma_f16(float c[4],
                                        uint32_t a0, uint32_t a1,
                                        uint32_t a2, uint32_t a3,
                                        uint32_t b0, uint32_t b1)
{
    asm volatile(
        "mma.sync.aligned.m16n8k16.row.col.f32.f16.f16.f32 "
        "{%0,%1,%2,%3}, {%4,%5,%6,%7}, {%8,%9}, {%0,%1,%2,%3};"
        : "+f"(c[0]), "+f"(c[1]), "+f"(c[2]), "+f"(c[3])
        : "r"(a0), "r"(a1), "r"(a2), "r"(a3), "r"(b0), "r"(b1));
}

__device__ __forceinline__ void cp16(uint32_t saddr, const void* gaddr)
{
    asm volatile("cp.async.ca.shared.global [%0], [%1], 16;"
                 :: "r"(saddr), "l"(gaddr) : "memory");
}
#define CP_COMMIT() asm volatile("cp.async.commit_group;" ::: "memory")
#define CP_WAIT(n)  asm volatile("cp.async.wait_group %0;" :: "n"(n) : "memory")

__device__ __forceinline__ float gelu_exact(float x)
{
    return 0.5f * x * (1.0f + erff(x * 0.70710678118654752f));
}

// ---------------------------------------------------------------------------
// Batched 512x512 transpose: 6 fp32 weights -> [N][K] fp16
// ---------------------------------------------------------------------------
__global__ void __launch_bounds__(256) tr512x6_k(const float* __restrict__ w0,
                                                 const float* __restrict__ w1,
                                                 const float* __restrict__ w2,
                                                 const float* __restrict__ w3,
                                                 const float* __restrict__ w4,
                                                 const float* __restrict__ w5,
                                                 __half* __restrict__ out)
{
    const float* srcs[6] = {w0, w1, w2, w3, w4, w5};
    const float* w = srcs[blockIdx.z];
    __half* wt = out + (size_t)blockIdx.z * WSTEP;

    __shared__ float t[32][33];
    const int tx = threadIdx.x & 31, ty = threadIdx.x >> 5;
    const int x = blockIdx.x * 32 + tx;
    const int y0 = blockIdx.y * 32;
#pragma unroll
    for (int j = 0; j < 32; j += 8)
        t[ty + j][tx] = w[(size_t)(y0 + ty + j) * 512 + x];
    __syncthreads();
    const int x2 = y0 + tx;
#pragma unroll
    for (int j = 0; j < 32; j += 8)
        wt[(size_t)(blockIdx.x * 32 + ty + j) * 512 + x2] = __float2half_rn(t[tx][ty + j]);
}

// ---------------------------------------------------------------------------
// fp16 GEMM, cp.async 3-stage: C[4096,512] = A[4096,512] @ Bt^T (all fp16 in)
// CTA 128x128, 8 warps (64x32 warp tile).
// EPI: 0 none, 1 +bias, 2 +bias+GELU.  OUT: 0 fp32, 1 fp16, 2 fp16 hi/lo pair
// ---------------------------------------------------------------------------
#define KPH 40   // halves per smem row (20 words)

template <int EPI, int OUT>
__global__ void __launch_bounds__(256, 2)
hgemm_k(const __half* __restrict__ A, const __half* __restrict__ Bt,
        const float* __restrict__ bias, void* __restrict__ Cv,
        void* __restrict__ C2v)
{
    extern __shared__ __half gsm[];
    __half* Ash = gsm;                    // 3 stages x 128*KPH
    __half* Bsh = gsm + 3 * 128 * KPH;

    const int tid = threadIdx.x;
    const int wid = tid >> 5, lane = tid & 31;
    const int g = lane >> 2, tq = lane & 3;
    const int m0w = (wid >> 2) * 64;
    const int n0w = (wid & 3) * 32;
    const int m0 = blockIdx.y * 128, n0 = blockIdx.x * 128;

    const int lrow = tid >> 1;            // 0..127
    const int lseg = (tid & 1) * 32;      // 0 or 32 bytes within 64B chunk

    const uint32_t ashb = (uint32_t)__cvta_generic_to_shared(Ash);
    const uint32_t bshb = (uint32_t)__cvta_generic_to_shared(Bsh);
    const char* Ag = (const char*)(A  + (size_t)(m0 + lrow) * 512);
    const char* Bg = (const char*)(Bt + (size_t)(n0 + lrow) * 512);
    const uint32_t srow = lrow * KPH * 2 + lseg;

    float acc[4][4][4] = {};

#define HG_ISSUE(c, st) do {                                                  \
        uint32_t sa = ashb + (uint32_t)(st) * 128 * KPH * 2 + srow;           \
        uint32_t sb = bshb + (uint32_t)(st) * 128 * KPH * 2 + srow;           \
        const char* ga = Ag + (c) * 64 + lseg;                                \
        const char* gb = Bg + (c) * 64 + lseg;                                \
        cp16(sa, ga); cp16(sa + 16, ga + 16);                                 \
        cp16(sb, gb); cp16(sb + 16, gb + 16);                                 \
    } while (0)

    HG_ISSUE(0, 0); CP_COMMIT();
    HG_ISSUE(1, 1); CP_COMMIT();

    for (int c = 0; c < 16; c++) {
        const int st = c % 3;
        CP_WAIT(1);
        __syncthreads();
        if (c + 2 < 16) { HG_ISSUE(c + 2, (c + 2) % 3); }
        CP_COMMIT();

        const __half* As = Ash + st * 128 * KPH;
        const __half* Bs = Bsh + st * 128 * KPH;
#pragma unroll
        for (int ks = 0; ks < 2; ks++) {
            const int kk = ks * 16;
            uint32_t af[4][4], bf[4][2];
#pragma unroll
            for (int mi = 0; mi < 4; mi++) {
                const int r = m0w + mi * 16 + g;
                af[mi][0] = *(const uint32_t*)&As[(r    ) * KPH + kk + 2 * tq];
                af[mi][1] = *(const uint32_t*)&As[(r + 8) * KPH + kk + 2 * tq];
                af[mi][2] = *(const uint32_t*)&As[(r    ) * KPH + kk + 8 + 2 * tq];
                af[mi][3] = *(const uint32_t*)&As[(r + 8) * KPH + kk + 8 + 2 * tq];
            }
#pragma unroll
            for (int ni = 0; ni < 4; ni++) {
                const int r = n0w + ni * 8 + g;
                bf[ni][0] = *(const uint32_t*)&Bs[r * KPH + kk + 2 * tq];
                bf[ni][1] = *(const uint32_t*)&Bs[r * KPH + kk + 8 + 2 * tq];
            }
#pragma unroll
            for (int mi = 0; mi < 4; mi++)
#pragma unroll
                for (int ni = 0; ni < 4; ni++)
                    mma_f16(acc[mi][ni], af[mi][0], af[mi][1], af[mi][2], af[mi][3],
                            bf[ni][0], bf[ni][1]);
        }
    }
#undef HG_ISSUE

#pragma unroll
    for (int mi = 0; mi < 4; mi++) {
        const int row = m0 + m0w + mi * 16 + g;
#pragma unroll
        for (int ni = 0; ni < 4; ni++) {
            const int col = n0 + n0w + ni * 8 + 2 * tq;
            float v0 = acc[mi][ni][0], v1 = acc[mi][ni][1];
            float v2 = acc[mi][ni][2], v3 = acc[mi][ni][3];
            if (EPI >= 1) {
                const float b0 = bias[col], b1 = bias[col + 1];
                v0 += b0; v1 += b1; v2 += b0; v3 += b1;
            }
            if (EPI == 2) {
                v0 = gelu_exact(v0); v1 = gelu_exact(v1);
                v2 = gelu_exact(v2); v3 = gelu_exact(v3);
            }
            if (OUT == 0) {
                float* C = (float*)Cv;
                *(float2*)(C + (size_t)row * 512 + col)       = make_float2(v0, v1);
                *(float2*)(C + (size_t)(row + 8) * 512 + col) = make_float2(v2, v3);
            } else if (OUT == 1) {
                __half* C = (__half*)Cv;
                *(__half2*)(C + (size_t)row * 512 + col)       = __floats2half2_rn(v0, v1);
                *(__half2*)(C + (size_t)(row + 8) * 512 + col) = __floats2half2_rn(v2, v3);
            } else {
                __half* Ch = (__half*)Cv;
                __half* Cl = (__half*)C2v;
                const __half h0 = __float2half_rn(v0), h1 = __float2half_rn(v1);
                const __half h2 = __float2half_rn(v2), h3 = __float2half_rn(v3);
                *(__half2*)(Ch + (size_t)row * 512 + col) = __halves2half2(h0, h1);
                *(__half2*)(Ch + (size_t)(row + 8) * 512 + col) = __halves2half2(h2, h3);
                *(__half2*)(Cl + (size_t)row * 512 + col) = __floats2half2_rn(
                    v0 - __half2float(h0), v1 - __half2float(h1));
                *(__half2*)(Cl + (size_t)(row + 8) * 512 + col) = __floats2half2_rn(
                    v2 - __half2float(h2), v3 - __half2float(h3));
            }
        }
    }
}

// ---------------------------------------------------------------------------
// V prep: Vh fp16 [b][n][h*64+d]  ->  Vt fp16 [bh][d][(1024-n)&1023]
// ---------------------------------------------------------------------------
__global__ void __launch_bounds__(256) vprep_k(const __half* __restrict__ Vh,
                                               __half* __restrict__ Vt)
{
    __shared__ __half sm[64][68];
    const int t = blockIdx.x;       // n tile 0..15
    const int bh = blockIdx.y;      // 0..31
    const int b = bh >> 3, h = bh & 7;
    const int tid = threadIdx.x;
    for (int i = tid; i < 4096; i += 256) {
        const int n = i >> 6, d = i & 63;
        sm[n][d] = Vh[((size_t)(b * NT) + t * 64 + n) * 512 + h * 64 + d];
    }
    __syncthreads();
    for (int i = tid; i < 4096; i += 256) {
        const int d = i >> 6, n = i & 63;
        const int j = (1024 - (t * 64 + n)) & 1023;
        Vt[((size_t)bh * 64 + d) * 1024 + j] = sm[n][d];
    }
}

// ---------------------------------------------------------------------------
// Tensor-core attention with cp.async pipeline (all-fp16 operands)
// out = softmax_rows(|Q K^T|) @ V_flip / 8;  QK^T via exact hi/lo split.
// ---------------------------------------------------------------------------
#define APH 72

__global__ void __launch_bounds__(128) attnh_k(const __half* __restrict__ Qhi_g,
                                               const __half* __restrict__ Qlo_g,
                                               const __half* __restrict__ Khi_g,
                                               const __half* __restrict__ Klo_g,
                                               const __half* __restrict__ Vt_g,
                                               float* __restrict__ O)
{
    extern __shared__ __half hsm[];
    __half* Qhi = hsm;                     // 64*APH
    __half* Qlo = hsm + 4608;
    __half* Khb = hsm + 2 * 4608;          // 2 buffers
    __half* Klb = hsm + 4 * 4608;
    __half* Vtb = hsm + 6 * 4608;

    const int qb = blockIdx.x;
    const int bh = blockIdx.y;
    const int b = bh >> 3, h = bh & 7;
    const int tid = threadIdx.x;
    const int wid = tid >> 5, lane = tid & 31;
    const int g = lane >> 2, tq = lane & 3;

    const uint32_t base = (uint32_t)__cvta_generic_to_shared(hsm);

    const char* qh = (const char*)(Qhi_g + ((size_t)(b * NT) + qb * 64) * 512 + h * 64);
    const char* ql = (const char*)(Qlo_g + ((size_t)(b * NT) + qb * 64) * 512 + h * 64);
    const char* khg = (const char*)(Khi_g + (size_t)b * NT * 512 + h * 64);
    const char* klg = (const char*)(Klo_g + (size_t)b * NT * 512 + h * 64);
    const char* vtg = (const char*)(Vt_g + (size_t)bh * 64 * 1024);

#define AT_ISSUE(kt, bf) do {                                                 \
        const uint32_t kb = base + (uint32_t)(2 + (bf)) * 4608 * 2;           \
        const uint32_t lb = base + (uint32_t)(4 + (bf)) * 4608 * 2;           \
        const uint32_t vb = base + (uint32_t)(6 + (bf)) * 4608 * 2;           \
        for (int i = tid; i < 512; i += 128) {                                \
            const int r = i >> 3, sg = (i & 7) * 16;                          \
            const uint32_t so = (uint32_t)r * 144 + sg;                       \
            cp16(kb + so, khg + ((size_t)((kt) * 64 + r)) * 1024 + sg);       \
            cp16(lb + so, klg + ((size_t)((kt) * 64 + r)) * 1024 + sg);       \
            cp16(vb + so, vtg + (size_t)r * 2048 + (kt) * 128 + sg);          \
        }                                                                     \
    } while (0)

    // prologue: Q + tile 0 (one group)
    for (int i = tid; i < 512; i += 128) {
        const int r = i >> 3, sg = (i & 7) * 16;
        const uint32_t so = (uint32_t)r * 144 + sg;
        cp16(base + so, qh + (size_t)r * 1024 + sg);
        cp16(base + 4608 * 2 + so, ql + (size_t)r * 1024 + sg);
    }
    AT_ISSUE(0, 0);
    CP_COMMIT();

    float m0 = -1e30f, m1 = -1e30f, l0 = 0.0f, l1 = 0.0f;
    float o[8][4];
#pragma unroll
    for (int i = 0; i < 8; i++)
#pragma unroll
        for (int j = 0; j < 4; j++) o[i][j] = 0.0f;

    const int qrow0 = wid * 16 + g;

    for (int kt = 0; kt < 16; kt++) {
        CP_WAIT(0);
        __syncthreads();
        if (kt + 1 < 16) { AT_ISSUE(kt + 1, (kt + 1) & 1); }
        CP_COMMIT();

        const __half* Kh = Khb + (kt & 1) * 4608;
        const __half* Kl = Klb + (kt & 1) * 4608;
        const __half* Vt = Vtb + (kt & 1) * 4608;

        // ---- S = Q K^T (hi/lo split, 3 mmas) ----
        float s[8][4];
#pragma unroll
        for (int i = 0; i < 8; i++)
#pragma unroll
            for (int j = 0; j < 4; j++) s[i][j] = 0.0f;

#pragma unroll
        for (int ks = 0; ks < 4; ks++) {
            const int kk = ks * 16;
            const uint32_t ah0 = *(const uint32_t*)&Qhi[(qrow0    ) * APH + kk + 2 * tq];
            const uint32_t ah1 = *(const uint32_t*)&Qhi[(qrow0 + 8) * APH + kk + 2 * tq];
            const uint32_t ah2 = *(const uint32_t*)&Qhi[(qrow0    ) * APH + kk + 8 + 2 * tq];
            const uint32_t ah3 = *(const uint32_t*)&Qhi[(qrow0 + 8) * APH + kk + 8 + 2 * tq];
            const uint32_t al0 = *(const uint32_t*)&Qlo[(qrow0    ) * APH + kk + 2 * tq];
            const uint32_t al1 = *(const uint32_t*)&Qlo[(qrow0 + 8) * APH + kk + 2 * tq];
            const uint32_t al2 = *(const uint32_t*)&Qlo[(qrow0    ) * APH + kk + 8 + 2 * tq];
            const uint32_t al3 = *(const uint32_t*)&Qlo[(qrow0 + 8) * APH + kk + 8 + 2 * tq];
#pragma unroll
            for (int ni = 0; ni < 8; ni++) {
                const int kr = ni * 8 + g;
                const uint32_t bh0 = *(const uint32_t*)&Kh[kr * APH + kk + 2 * tq];
                const uint32_t bh1 = *(const uint32_t*)&Kh[kr * APH + kk + 8 + 2 * tq];
                const uint32_t bl0 = *(const uint32_t*)&Kl[kr * APH + kk + 2 * tq];
                const uint32_t bl1 = *(const uint32_t*)&Kl[kr * APH + kk + 8 + 2 * tq];
                mma_f16(s[ni], ah0, ah1, ah2, ah3, bh0, bh1);
                mma_f16(s[ni], ah0, ah1, ah2, ah3, bl0, bl1);
                mma_f16(s[ni], al0, al1, al2, al3, bh0, bh1);
            }
        }

        // ---- online softmax on |s| ----
        float mt0 = -1e30f, mt1 = -1e30f;
#pragma unroll
        for (int ni = 0; ni < 8; ni++) {
            mt0 = fmaxf(mt0, fmaxf(fabsf(s[ni][0]), fabsf(s[ni][1])));
            mt1 = fmaxf(mt1, fmaxf(fabsf(s[ni][2]), fabsf(s[ni][3])));
        }
        mt0 = fmaxf(mt0, __shfl_xor_sync(0xffffffffu, mt0, 1));
        mt0 = fmaxf(mt0, __shfl_xor_sync(0xffffffffu, mt0, 2));
        mt1 = fmaxf(mt1, __shfl_xor_sync(0xffffffffu, mt1, 1));
        mt1 = fmaxf(mt1, __shfl_xor_sync(0xffffffffu, mt1, 2));

        const float mn0 = fmaxf(m0, mt0), mn1 = fmaxf(m1, mt1);
        const float corr0 = __expf(m0 - mn0), corr1 = __expf(m1 - mn1);

        uint32_t ph[8][2];
        float la0 = 0.0f, la1 = 0.0f;
#pragma unroll
        for (int ni = 0; ni < 8; ni++) {
            const float p0 = __expf(fabsf(s[ni][0]) - mn0);
            const float p1 = __expf(fabsf(s[ni][1]) - mn0);
            const float p2 = __expf(fabsf(s[ni][2]) - mn1);
            const float p3 = __expf(fabsf(s[ni][3]) - mn1);
            ph[ni][0] = pack_h2(p0, p1);
            ph[ni][1] = pack_h2(p2, p3);
            la0 += p0 + p1;
            la1 += p2 + p3;
        }
        la0 += __shfl_xor_sync(0xffffffffu, la0, 1);
        la0 += __shfl_xor_sync(0xffffffffu, la0, 2);
        la1 += __shfl_xor_sync(0xffffffffu, la1, 1);
        la1 += __shfl_xor_sync(0xffffffffu, la1, 2);

        l0 = l0 * corr0 + la0; m0 = mn0;
        l1 = l1 * corr1 + la1; m1 = mn1;
#pragma unroll
        for (int nd = 0; nd < 8; nd++) {
            o[nd][0] *= corr0; o[nd][1] *= corr0;
            o[nd][2] *= corr1; o[nd][3] *= corr1;
        }

        // ---- O += P @ Vt ----
#pragma unroll
        for (int ks = 0; ks < 4; ks++) {
            const int kk = ks * 16;
            const uint32_t a0 = ph[2 * ks][0];
            const uint32_t a1 = ph[2 * ks][1];
            const uint32_t a2 = ph[2 * ks + 1][0];
            const uint32_t a3 = ph[2 * ks + 1][1];
#pragma unroll
            for (int nd = 0; nd < 8; nd++) {
                const int dr = nd * 8 + g;
                const uint32_t b0 = *(const uint32_t*)&Vt[dr * APH + kk + 2 * tq];
                const uint32_t b1 = *(const uint32_t*)&Vt[dr * APH + kk + 8 + 2 * tq];
                mma_f16(o[nd], a0, a1, a2, a3, b0, b1);
            }
        }
    }
#undef AT_ISSUE

    const float inv0 = 1.0f / (8.0f * l0);
    const float inv1 = 1.0f / (8.0f * l1);
    float* Ob0 = O + ((size_t)(b * NT + qb * 64 + qrow0)) * DIMF + h * HD;
    float* Ob1 = Ob0 + (size_t)8 * DIMF;
#pragma unroll
    for (int nd = 0; nd < 8; nd++) {
        const int col = nd * 8 + 2 * tq;
        *(float2*)(Ob0 + col) = make_float2(o[nd][0] * inv0, o[nd][1] * inv0);
        *(float2*)(Ob1 + col) = make_float2(o[nd][2] * inv1, o[nd][3] * inv1);
    }
}

// ---------------------------------------------------------------------------
// LayerNorm (fp32 in -> fp16 out), one block per row
// ---------------------------------------------------------------------------
__global__ void __launch_bounds__(128) ln_k(const float* __restrict__ x,
                                            const float* __restrict__ g,
                                            const float* __restrict__ b,
                                            __half* __restrict__ y)
{
    const int row = blockIdx.x;
    const int t   = threadIdx.x;
    float4 v = ((const float4*)(x + (size_t)row * DIMF))[t];
    float s  = v.x + v.y + v.z + v.w;
    float s2 = v.x*v.x + v.y*v.y + v.z*v.z + v.w*v.w;
#pragma unroll
    for (int off = 16; off; off >>= 1) {
        s  += __shfl_xor_sync(0xffffffffu, s,  off);
        s2 += __shfl_xor_sync(0xffffffffu, s2, off);
    }
    __shared__ float sh[8];
    const int w = t >> 5, lane = t & 31;
    if (lane == 0) { sh[w] = s; sh[4 + w] = s2; }
    __syncthreads();
    s  = sh[0] + sh[1] + sh[2] + sh[3];
    s2 = sh[4] + sh[5] + sh[6] + sh[7];
    const float mu   = s * (1.0f / DIMF);
    const float var  = s2 * (1.0f / DIMF) - mu * mu;
    const float rstd = rsqrtf(var + 1e-5f);
    float4 gv = ((const float4*)g)[t];
    float4 bv = ((const float4*)b)[t];
    __half2* yo = (__half2*)(y + (size_t)row * DIMF);
    yo[2 * t]     = __floats2half2_rn((v.x - mu) * rstd * gv.x + bv.x,
                                      (v.y - mu) * rstd * gv.y + bv.y);
    yo[2 * t + 1] = __floats2half2_rn((v.z - mu) * rstd * gv.z + bv.z,
                                      (v.w - mu) * rstd * gv.w + bv.w);
}

// ---------------------------------------------------------------------------
// Per-sample mean / std (ddof=1)
// ---------------------------------------------------------------------------
__global__ void __launch_bounds__(512) stats_k(const float* __restrict__ a,
                                               float* __restrict__ st)
{
    const int b = blockIdx.x;
    const float* p = a + (size_t)b * (NT * DIMF);
    float s = 0.0f, s2 = 0.0f;
    for (int i = threadIdx.x; i < NT * DIMF; i += 512) {
        float v = p[i];
        s += v;
        s2 = fmaf(v, v, s2);
    }
#pragma unroll
    for (int off = 16; off; off >>= 1) {
        s  += __shfl_xor_sync(0xffffffffu, s,  off);
        s2 += __shfl_xor_sync(0xffffffffu, s2, off);
    }
    __shared__ float sh[16], sh2[16];
    const int w = threadIdx.x >> 5;
    if ((threadIdx.x & 31) == 0) { sh[w] = s; sh2[w] = s2; }
    __syncthreads();
    if (threadIdx.x == 0) {
        float ts = 0.0f, ts2 = 0.0f;
        for (int i = 0; i < 16; i++) { ts += sh[i]; ts2 += sh2[i]; }
        double N   = (double)(NT * DIMF);
        double mu  = (double)ts / N;
        double var = ((double)ts2 - N * mu * mu) / (N - 1.0);
        st[b * 2 + 0] = (float)mu;
        st[b * 2 + 1] = (float)(1.0 / sqrt(var));
    }
}

// ---------------------------------------------------------------------------
// Time MLP (tiny, fp32)
// ---------------------------------------------------------------------------
__global__ void __launch_bounds__(256) tmlp1_k(const float* __restrict__ te,
                                               const float* __restrict__ w,
                                               const float* __restrict__ bb,
                                               float* __restrict__ h1)
{
    const int b = blockIdx.y;
    const int j = blockIdx.x * 256 + threadIdx.x;
    float acc = 0.0f;
    for (int k = 0; k < 512; k++)
        acc = fmaf(te[b * 512 + k], w[k * 1024 + j], acc);
    acc += bb[j];
    h1[b * 1024 + j] = acc / (1.0f + __expf(-acc));
}

__global__ void __launch_bounds__(256) tmlp2_k(const float* __restrict__ h1,
                                               const float* __restrict__ w,
                                               const float* __restrict__ bb,
                                               float* __restrict__ tout)
{
    const int b = blockIdx.y;
    const int j = blockIdx.x * 256 + threadIdx.x;
    float acc = 0.0f;
    for (int k = 0; k < 1024; k++)
        acc = fmaf(h1[b * 1024 + k], w[k * 1024 + j], acc);
    tout[b * 1024 + j] = acc + bb[j];
}

// ---------------------------------------------------------------------------
// FiLM apply (fp32 in -> fp16 out)
// ---------------------------------------------------------------------------
__global__ void __launch_bounds__(256) film_k(const float* __restrict__ a,
                                              const float* __restrict__ t,
                                              const float* __restrict__ st,
                                              __half* __restrict__ x)
{
    const int i = blockIdx.x * 256 + threadIdx.x;   // over SZ/2
    const int idx = i * 2;
    const int c = idx & 511;
    const int b = idx >> 19;
    const float mu = st[b * 2], rstd = st[b * 2 + 1];
    const float2 av = *(const float2*)(a + idx);
    const float s0 = t[b * 1024 + 512 + c], s1 = t[b * 1024 + 512 + c + 1];
    const float m0v = t[b * 1024 + c],      m1v = t[b * 1024 + c + 1];
    *(__half2*)(x + idx) = __floats2half2_rn((av.x - mu) * rstd * s0 + m0v,
                                             (av.y - mu) * rstd * s1 + m1v);
}

// ---------------------------------------------------------------------------
// Launch
// ---------------------------------------------------------------------------
extern "C" void kernel_launch(void* const* d_in, const int* in_sizes, int n_in,
                              void* d_out, int out_size)
{
    const float* con   = (const float*)d_in[0];
    const float* diff  = (const float*)d_in[1];
    const float* temb  = (const float*)d_in[2];
    const float* lncg  = (const float*)d_in[3];
    const float* lncb  = (const float*)d_in[4];
    const float* lndg  = (const float*)d_in[5];
    const float* lndb  = (const float*)d_in[6];
    const float* wq    = (const float*)d_in[7];
    const float* wk    = (const float*)d_in[8];
    const float* wv    = (const float*)d_in[9];
    const float* wout  = (const float*)d_in[10];
    const float* bout  = (const float*)d_in[11];
    const float* wemd1 = (const float*)d_in[12];
    const float* bemd1 = (const float*)d_in[13];
    const float* wemd2 = (const float*)d_in[14];
    const float* bemd2 = (const float*)d_in[15];
    const float* mlng  = (const float*)d_in[16];
    const float* mlnb  = (const float*)d_in[17];
    const float* mw1   = (const float*)d_in[18];
    const float* mb1   = (const float*)d_in[19];
    const float* mw2   = (const float*)d_in[20];
    const float* mb2   = (const float*)d_in[21];

    float* buf = nullptr;
    cudaGetSymbolAddress((void**)&buf, g_buf);
    __half* hb = (__half*)(buf + O_HB);

    const int hg_smem = 3 * 2 * 128 * KPH * 2;   // 61440
    cudaFuncSetAttribute(hgemm_k<0,2>, cudaFuncAttributeMaxDynamicSharedMemorySize, hg_smem);
    cudaFuncSetAttribute(hgemm_k<0,1>, cudaFuncAttributeMaxDynamicSharedMemorySize, hg_smem);
    cudaFuncSetAttribute(hgemm_k<1,0>, cudaFuncAttributeMaxDynamicSharedMemorySize, hg_smem);
    cudaFuncSetAttribute(hgemm_k<2,1>, cudaFuncAttributeMaxDynamicSharedMemorySize, hg_smem);
    const int at_smem = 8 * 4608 * 2;            // 73728
    cudaFuncSetAttribute(attnh_k, cudaFuncAttributeMaxDynamicSharedMemorySize, at_smem);

    // 0) weights -> [N][K] fp16
    tr512x6_k<<<dim3(16, 16, 6), 256>>>(wq, wk, wv, wout, mw1, mw2, hb + H_WT);

    // 1) LayerNorms -> fp16
    ln_k<<<NB * NT, 128>>>(diff, lndg, lndb, hb + H_FEAQ);
    ln_k<<<NB * NT, 128>>>(con,  lncg, lncb, hb + H_FEAKV);

    // 2) Q/K/V projections; Q,K emit exact hi/lo fp16 split, V emits fp16
    dim3 mg(4, 32);
    hgemm_k<0,2><<<mg, 256, hg_smem>>>(hb + H_FEAQ,  hb + H_WT + 0 * WSTEP, nullptr,
                                       hb + H_QHI, hb + H_QLO);
    hgemm_k<0,2><<<mg, 256, hg_smem>>>(hb + H_FEAKV, hb + H_WT + 1 * WSTEP, nullptr,
                                       hb + H_KHI, hb + H_KLO);
    hgemm_k<0,1><<<mg, 256, hg_smem>>>(hb + H_FEAKV, hb + H_WT + 2 * WSTEP, nullptr,
                                       hb + H_VH, nullptr);

    // 2b) flipped + transposed V
    vprep_k<<<dim3(16, 32), 256>>>(hb + H_VH, hb + H_VT);

    // 3) attention
    attnh_k<<<dim3(NT / 64, NB * NHD), 128, at_smem>>>(
        hb + H_QHI, hb + H_QLO, hb + H_KHI, hb + H_KLO, hb + H_VT, buf + O_ATT);

    // 4) stats + time MLP + FiLM (-> fp16 X)
    stats_k<<<NB, 512>>>(buf + O_ATT, buf + O_STATS);
    tmlp1_k<<<dim3(4, NB), 256>>>(temb, wemd1, bemd1, buf + O_T1);
    tmlp2_k<<<dim3(4, NB), 256>>>(buf + O_T1, wemd2, bemd2, buf + O_T);
    film_k<<<(int)(SZ / 512), 256>>>(buf + O_ATT, buf + O_T, buf + O_STATS,
                                     hb + H_X);

    // 5) output projection (fp32 out for next LN)
    hgemm_k<1,0><<<mg, 256, hg_smem>>>(hb + H_X, hb + H_WT + 3 * WSTEP, bout,
                                       buf + O_OUT1, nullptr);

    // 6) FeedForward
    ln_k<<<NB * NT, 128>>>(buf + O_OUT1, mlng, mlnb, hb + H_H);
    hgemm_k<2,1><<<mg, 256, hg_smem>>>(hb + H_H,  hb + H_WT + 4 * WSTEP, mb1,
                                       hb + H_H2, nullptr);
    hgemm_k<1,0><<<mg, 256, hg_smem>>>(hb + H_H2, hb + H_WT + 5 * WSTEP, mb2,
                                       (float*)d_out, nullptr);
}

// round 7
// speedup vs baseline: 3.1103x; 1.2129x over previous
#include <cuda_runtime.h>
#include <cuda_fp16.h>
#include <math.h>
#include <stdint.h>

// ---------------------------------------------------------------------------
// Problem constants
// ---------------------------------------------------------------------------
#define NT   1024
#define DIMF 512
#define NB   4
#define NHD  8
#define HD   64

static constexpr size_t SZ = (size_t)NB * NT * DIMF;   // 2,097,152

__device__ float g_buf[SZ * 10 + 2 * 1024 * 1024];

// fp32 region
static constexpr size_t O_ATT   = 0;
static constexpr size_t O_OUT1  = 1 * SZ;
static constexpr size_t O_T1    = 2 * SZ;           // 4096 floats
static constexpr size_t O_T     = 2 * SZ + 4096;    // 4096 floats
static constexpr size_t O_STATS = 2 * SZ + 8192;    // 8 floats
static constexpr size_t O_PART  = 2 * SZ + 8448;    // 256 floats partials
static constexpr size_t O_HB    = 2 * SZ + 9216;    // half region starts (floats)

// half-region offsets (in halves)
static constexpr size_t H_FEAQ  = 0;
static constexpr size_t H_FEAKV = 1 * SZ;
static constexpr size_t H_QHI   = 2 * SZ;
static constexpr size_t H_QLO   = 3 * SZ;
static constexpr size_t H_KHI   = 4 * SZ;
static constexpr size_t H_KLO   = 5 * SZ;
static constexpr size_t H_VH    = 6 * SZ;
static constexpr size_t H_VT    = 7 * SZ;           // [32][64][1024]
static constexpr size_t H_X     = 8 * SZ;
static constexpr size_t H_H     = 9 * SZ;
static constexpr size_t H_H2    = 10 * SZ;
static constexpr size_t H_WT    = 11 * SZ;          // 6 x 512*512 halves
static constexpr size_t WSTEP   = (size_t)DIMF * DIMF;

// ---------------------------------------------------------------------------
// helpers
// ---------------------------------------------------------------------------
__device__ __forceinline__ uint32_t pack_h2(float a, float b)
{
    __half2 h = __floats2half2_rn(a, b);
    return *(uint32_t*)&h;
}

__device__ __forceinline__ void mma_f16(float c[4],
                                        uint32_t a0, uint32_t a1,
                                        uint32_t a2, uint32_t a3,
                                        uint32_t b0, uint32_t b1)
{
    asm volatile(
        "mma.sync.aligned.m16n8k16.row.col.f32.f16.f16.f32 "
        "{%0,%1,%2,%3}, {%4,%5,%6,%7}, {%8,%9}, {%0,%1,%2,%3};"
        : "+f"(c[0]), "+f"(c[1]), "+f"(c[2]), "+f"(c[3])
        : "r"(a0), "r"(a1), "r"(a2), "r"(a3), "r"(b0), "r"(b1));
}

__device__ __forceinline__ void cp16(uint32_t saddr, const void* gaddr)
{
    asm volatile("cp.async.ca.shared.global [%0], [%1], 16;"
                 :: "r"(saddr), "l"(gaddr) : "memory");
}
#define CP_COMMIT() asm volatile("cp.async.commit_group;" ::: "memory")
#define CP_WAIT(n)  asm volatile("cp.async.wait_group %0;" :: "n"(n) : "memory")

__device__ __forceinline__ float gelu_exact(float x)
{
    return 0.5f * x * (1.0f + erff(x * 0.70710678118654752f));
}

// ---------------------------------------------------------------------------
// Batched 512x512 transpose: 6 fp32 weights -> [N][K] fp16
// ---------------------------------------------------------------------------
__global__ void __launch_bounds__(256) tr512x6_k(const float* __restrict__ w0,
                                                 const float* __restrict__ w1,
                                                 const float* __restrict__ w2,
                                                 const float* __restrict__ w3,
                                                 const float* __restrict__ w4,
                                                 const float* __restrict__ w5,
                                                 __half* __restrict__ out)
{
    const float* srcs[6] = {w0, w1, w2, w3, w4, w5};
    const float* w = srcs[blockIdx.z];
    __half* wt = out + (size_t)blockIdx.z * WSTEP;

    __shared__ float t[32][33];
    const int tx = threadIdx.x & 31, ty = threadIdx.x >> 5;
    const int x = blockIdx.x * 32 + tx;
    const int y0 = blockIdx.y * 32;
#pragma unroll
    for (int j = 0; j < 32; j += 8)
        t[ty + j][tx] = w[(size_t)(y0 + ty + j) * 512 + x];
    __syncthreads();
    const int x2 = y0 + tx;
#pragma unroll
    for (int j = 0; j < 32; j += 8)
        wt[(size_t)(blockIdx.x * 32 + ty + j) * 512 + x2] = __float2half_rn(t[tx][ty + j]);
}

// ---------------------------------------------------------------------------
// GEMM mainloop (shared by qkv_k and hgemm_k): 128x128 CTA tile, 8 warps
// ---------------------------------------------------------------------------
#define KPH 40

__device__ __forceinline__ void gemm_core(const __half* __restrict__ A,
                                          const __half* __restrict__ Bt,
                                          __half* Ash, __half* Bsh,
                                          int m0, int n0, int tid,
                                          float acc[4][4][4])
{
    const int wid = tid >> 5, lane = tid & 31;
    const int g = lane >> 2, tq = lane & 3;
    const int m0w = (wid >> 2) * 64;
    const int n0w = (wid & 3) * 32;

    const int lrow = tid >> 1;
    const int lseg = (tid & 1) * 32;

    const uint32_t ashb = (uint32_t)__cvta_generic_to_shared(Ash);
    const uint32_t bshb = (uint32_t)__cvta_generic_to_shared(Bsh);
    const char* Ag = (const char*)(A  + (size_t)(m0 + lrow) * 512);
    const char* Bg = (const char*)(Bt + (size_t)(n0 + lrow) * 512);
    const uint32_t srow = lrow * KPH * 2 + lseg;

#define HG_ISSUE(c, st) do {                                                  \
        uint32_t sa = ashb + (uint32_t)(st) * 128 * KPH * 2 + srow;           \
        uint32_t sb = bshb + (uint32_t)(st) * 128 * KPH * 2 + srow;           \
        const char* ga = Ag + (c) * 64 + lseg;                                \
        const char* gb = Bg + (c) * 64 + lseg;                                \
        cp16(sa, ga); cp16(sa + 16, ga + 16);                                 \
        cp16(sb, gb); cp16(sb + 16, gb + 16);                                 \
    } while (0)

    HG_ISSUE(0, 0); CP_COMMIT();
    HG_ISSUE(1, 1); CP_COMMIT();

    for (int c = 0; c < 16; c++) {
        const int st = c % 3;
        CP_WAIT(1);
        __syncthreads();
        if (c + 2 < 16) { HG_ISSUE(c + 2, (c + 2) % 3); }
        CP_COMMIT();

        const __half* As = Ash + st * 128 * KPH;
        const __half* Bs = Bsh + st * 128 * KPH;
#pragma unroll
        for (int ks = 0; ks < 2; ks++) {
            const int kk = ks * 16;
            uint32_t af[4][4], bf[4][2];
#pragma unroll
            for (int mi = 0; mi < 4; mi++) {
                const int r = m0w + mi * 16 + g;
                af[mi][0] = *(const uint32_t*)&As[(r    ) * KPH + kk + 2 * tq];
                af[mi][1] = *(const uint32_t*)&As[(r + 8) * KPH + kk + 2 * tq];
                af[mi][2] = *(const uint32_t*)&As[(r    ) * KPH + kk + 8 + 2 * tq];
                af[mi][3] = *(const uint32_t*)&As[(r + 8) * KPH + kk + 8 + 2 * tq];
            }
#pragma unroll
            for (int ni = 0; ni < 4; ni++) {
                const int r = n0w + ni * 8 + g;
                bf[ni][0] = *(const uint32_t*)&Bs[r * KPH + kk + 2 * tq];
                bf[ni][1] = *(const uint32_t*)&Bs[r * KPH + kk + 8 + 2 * tq];
            }
#pragma unroll
            for (int mi = 0; mi < 4; mi++)
#pragma unroll
                for (int ni = 0; ni < 4; ni++)
                    mma_f16(acc[mi][ni], af[mi][0], af[mi][1], af[mi][2], af[mi][3],
                            bf[ni][0], bf[ni][1]);
        }
    }
#undef HG_ISSUE
}

// ---------------------------------------------------------------------------
// Fused Q/K/V projection: grid.z selects operand pair + output mode
// ---------------------------------------------------------------------------
__global__ void __launch_bounds__(256, 2) qkv_k(__half* __restrict__ hb)
{
    extern __shared__ __half gsm[];
    __half* Ash = gsm;
    __half* Bsh = gsm + 3 * 128 * KPH;

    const int z = blockIdx.z;
    const __half* A  = hb + (z == 0 ? H_FEAQ : H_FEAKV);
    const __half* Bt = hb + H_WT + (size_t)z * WSTEP;

    const int tid = threadIdx.x;
    const int wid = tid >> 5, lane = tid & 31;
    const int g = lane >> 2, tq = lane & 3;
    const int m0w = (wid >> 2) * 64;
    const int n0w = (wid & 3) * 32;
    const int m0 = blockIdx.y * 128, n0 = blockIdx.x * 128;

    float acc[4][4][4] = {};
    gemm_core(A, Bt, Ash, Bsh, m0, n0, tid, acc);

    __half* Ch = hb + (z == 0 ? H_QHI : (z == 1 ? H_KHI : H_VH));
    __half* Cl = hb + (z == 0 ? H_QLO : H_KLO);   // unused for z==2

#pragma unroll
    for (int mi = 0; mi < 4; mi++) {
        const int row = m0 + m0w + mi * 16 + g;
#pragma unroll
        for (int ni = 0; ni < 4; ni++) {
            const int col = n0 + n0w + ni * 8 + 2 * tq;
            const float v0 = acc[mi][ni][0], v1 = acc[mi][ni][1];
            const float v2 = acc[mi][ni][2], v3 = acc[mi][ni][3];
            if (z < 2) {
                const __half h0 = __float2half_rn(v0), h1 = __float2half_rn(v1);
                const __half h2 = __float2half_rn(v2), h3 = __float2half_rn(v3);
                *(__half2*)(Ch + (size_t)row * 512 + col) = __halves2half2(h0, h1);
                *(__half2*)(Ch + (size_t)(row + 8) * 512 + col) = __halves2half2(h2, h3);
                *(__half2*)(Cl + (size_t)row * 512 + col) = __floats2half2_rn(
                    v0 - __half2float(h0), v1 - __half2float(h1));
                *(__half2*)(Cl + (size_t)(row + 8) * 512 + col) = __floats2half2_rn(
                    v2 - __half2float(h2), v3 - __half2float(h3));
            } else {
                *(__half2*)(Ch + (size_t)row * 512 + col)       = __floats2half2_rn(v0, v1);
                *(__half2*)(Ch + (size_t)(row + 8) * 512 + col) = __floats2half2_rn(v2, v3);
            }
        }
    }
}

// ---------------------------------------------------------------------------
// Standalone GEMM (for w_out / mlp): EPI 1 +bias, 2 +bias+GELU; OUT 0 fp32, 1 fp16
// ---------------------------------------------------------------------------
template <int EPI, int OUT>
__global__ void __launch_bounds__(256, 2)
hgemm_k(const __half* __restrict__ A, const __half* __restrict__ Bt,
        const float* __restrict__ bias, void* __restrict__ Cv)
{
    extern __shared__ __half gsm[];
    __half* Ash = gsm;
    __half* Bsh = gsm + 3 * 128 * KPH;

    const int tid = threadIdx.x;
    const int wid = tid >> 5, lane = tid & 31;
    const int g = lane >> 2, tq = lane & 3;
    const int m0w = (wid >> 2) * 64;
    const int n0w = (wid & 3) * 32;
    const int m0 = blockIdx.y * 128, n0 = blockIdx.x * 128;

    float acc[4][4][4] = {};
    gemm_core(A, Bt, Ash, Bsh, m0, n0, tid, acc);

#pragma unroll
    for (int mi = 0; mi < 4; mi++) {
        const int row = m0 + m0w + mi * 16 + g;
#pragma unroll
        for (int ni = 0; ni < 4; ni++) {
            const int col = n0 + n0w + ni * 8 + 2 * tq;
            float v0 = acc[mi][ni][0], v1 = acc[mi][ni][1];
            float v2 = acc[mi][ni][2], v3 = acc[mi][ni][3];
            if (EPI >= 1) {
                const float b0 = bias[col], b1 = bias[col + 1];
                v0 += b0; v1 += b1; v2 += b0; v3 += b1;
            }
            if (EPI == 2) {
                v0 = gelu_exact(v0); v1 = gelu_exact(v1);
                v2 = gelu_exact(v2); v3 = gelu_exact(v3);
            }
            if (OUT == 0) {
                float* C = (float*)Cv;
                *(float2*)(C + (size_t)row * 512 + col)       = make_float2(v0, v1);
                *(float2*)(C + (size_t)(row + 8) * 512 + col) = make_float2(v2, v3);
            } else {
                __half* C = (__half*)Cv;
                *(__half2*)(C + (size_t)row * 512 + col)       = __floats2half2_rn(v0, v1);
                *(__half2*)(C + (size_t)(row + 8) * 512 + col) = __floats2half2_rn(v2, v3);
            }
        }
    }
}

// ---------------------------------------------------------------------------
// V prep: Vh fp16 [b][n][h*64+d]  ->  Vt fp16 [bh][d][(1024-n)&1023]
// ---------------------------------------------------------------------------
__global__ void __launch_bounds__(256) vprep_k(const __half* __restrict__ Vh,
                                               __half* __restrict__ Vt)
{
    __shared__ __half sm[64][68];
    const int t = blockIdx.x;
    const int bh = blockIdx.y;
    const int b = bh >> 3, h = bh & 7;
    const int tid = threadIdx.x;
    for (int i = tid; i < 4096; i += 256) {
        const int n = i >> 6, d = i & 63;
        sm[n][d] = Vh[((size_t)(b * NT) + t * 64 + n) * 512 + h * 64 + d];
    }
    __syncthreads();
    for (int i = tid; i < 4096; i += 256) {
        const int d = i >> 6, n = i & 63;
        const int j = (1024 - (t * 64 + n)) & 1023;
        Vt[((size_t)bh * 64 + d) * 1024 + j] = sm[n][d];
    }
}

// ---------------------------------------------------------------------------
// Tensor-core attention with cp.async pipeline (all-fp16 operands)
// ---------------------------------------------------------------------------
#define APH 72

__global__ void __launch_bounds__(128) attnh_k(const __half* __restrict__ Qhi_g,
                                               const __half* __restrict__ Qlo_g,
                                               const __half* __restrict__ Khi_g,
                                               const __half* __restrict__ Klo_g,
                                               const __half* __restrict__ Vt_g,
                                               float* __restrict__ O)
{
    extern __shared__ __half hsm[];
    __half* Qhi = hsm;
    __half* Qlo = hsm + 4608;
    __half* Khb = hsm + 2 * 4608;
    __half* Klb = hsm + 4 * 4608;
    __half* Vtb = hsm + 6 * 4608;

    const int qb = blockIdx.x;
    const int bh = blockIdx.y;
    const int b = bh >> 3, h = bh & 7;
    const int tid = threadIdx.x;
    const int wid = tid >> 5, lane = tid & 31;
    const int g = lane >> 2, tq = lane & 3;

    const uint32_t base = (uint32_t)__cvta_generic_to_shared(hsm);

    const char* qh = (const char*)(Qhi_g + ((size_t)(b * NT) + qb * 64) * 512 + h * 64);
    const char* ql = (const char*)(Qlo_g + ((size_t)(b * NT) + qb * 64) * 512 + h * 64);
    const char* khg = (const char*)(Khi_g + (size_t)b * NT * 512 + h * 64);
    const char* klg = (const char*)(Klo_g + (size_t)b * NT * 512 + h * 64);
    const char* vtg = (const char*)(Vt_g + (size_t)bh * 64 * 1024);

#define AT_ISSUE(kt, bf) do {                                                 \
        const uint32_t kb = base + (uint32_t)(2 + (bf)) * 4608 * 2;           \
        const uint32_t lb = base + (uint32_t)(4 + (bf)) * 4608 * 2;           \
        const uint32_t vb = base + (uint32_t)(6 + (bf)) * 4608 * 2;           \
        for (int i = tid; i < 512; i += 128) {                                \
            const int r = i >> 3, sg = (i & 7) * 16;                          \
            const uint32_t so = (uint32_t)r * 144 + sg;                       \
            cp16(kb + so, khg + ((size_t)((kt) * 64 + r)) * 1024 + sg);       \
            cp16(lb + so, klg + ((size_t)((kt) * 64 + r)) * 1024 + sg);       \
            cp16(vb + so, vtg + (size_t)r * 2048 + (kt) * 128 + sg);          \
        }                                                                     \
    } while (0)

    for (int i = tid; i < 512; i += 128) {
        const int r = i >> 3, sg = (i & 7) * 16;
        const uint32_t so = (uint32_t)r * 144 + sg;
        cp16(base + so, qh + (size_t)r * 1024 + sg);
        cp16(base + 4608 * 2 + so, ql + (size_t)r * 1024 + sg);
    }
    AT_ISSUE(0, 0);
    CP_COMMIT();

    float m0 = -1e30f, m1 = -1e30f, l0 = 0.0f, l1 = 0.0f;
    float o[8][4];
#pragma unroll
    for (int i = 0; i < 8; i++)
#pragma unroll
        for (int j = 0; j < 4; j++) o[i][j] = 0.0f;

    const int qrow0 = wid * 16 + g;

    for (int kt = 0; kt < 16; kt++) {
        CP_WAIT(0);
        __syncthreads();
        if (kt + 1 < 16) { AT_ISSUE(kt + 1, (kt + 1) & 1); }
        CP_COMMIT();

        const __half* Kh = Khb + (kt & 1) * 4608;
        const __half* Kl = Klb + (kt & 1) * 4608;
        const __half* Vt = Vtb + (kt & 1) * 4608;

        float s[8][4];
#pragma unroll
        for (int i = 0; i < 8; i++)
#pragma unroll
            for (int j = 0; j < 4; j++) s[i][j] = 0.0f;

#pragma unroll
        for (int ks = 0; ks < 4; ks++) {
            const int kk = ks * 16;
            const uint32_t ah0 = *(const uint32_t*)&Qhi[(qrow0    ) * APH + kk + 2 * tq];
            const uint32_t ah1 = *(const uint32_t*)&Qhi[(qrow0 + 8) * APH + kk + 2 * tq];
            const uint32_t ah2 = *(const uint32_t*)&Qhi[(qrow0    ) * APH + kk + 8 + 2 * tq];
            const uint32_t ah3 = *(const uint32_t*)&Qhi[(qrow0 + 8) * APH + kk + 8 + 2 * tq];
            const uint32_t al0 = *(const uint32_t*)&Qlo[(qrow0    ) * APH + kk + 2 * tq];
            const uint32_t al1 = *(const uint32_t*)&Qlo[(qrow0 + 8) * APH + kk + 2 * tq];
            const uint32_t al2 = *(const uint32_t*)&Qlo[(qrow0    ) * APH + kk + 8 + 2 * tq];
            const uint32_t al3 = *(const uint32_t*)&Qlo[(qrow0 + 8) * APH + kk + 8 + 2 * tq];
#pragma unroll
            for (int ni = 0; ni < 8; ni++) {
                const int kr = ni * 8 + g;
                const uint32_t bh0 = *(const uint32_t*)&Kh[kr * APH + kk + 2 * tq];
                const uint32_t bh1 = *(const uint32_t*)&Kh[kr * APH + kk + 8 + 2 * tq];
                const uint32_t bl0 = *(const uint32_t*)&Kl[kr * APH + kk + 2 * tq];
                const uint32_t bl1 = *(const uint32_t*)&Kl[kr * APH + kk + 8 + 2 * tq];
                mma_f16(s[ni], ah0, ah1, ah2, ah3, bh0, bh1);
                mma_f16(s[ni], ah0, ah1, ah2, ah3, bl0, bl1);
                mma_f16(s[ni], al0, al1, al2, al3, bh0, bh1);
            }
        }

        float mt0 = -1e30f, mt1 = -1e30f;
#pragma unroll
        for (int ni = 0; ni < 8; ni++) {
            mt0 = fmaxf(mt0, fmaxf(fabsf(s[ni][0]), fabsf(s[ni][1])));
            mt1 = fmaxf(mt1, fmaxf(fabsf(s[ni][2]), fabsf(s[ni][3])));
        }
        mt0 = fmaxf(mt0, __shfl_xor_sync(0xffffffffu, mt0, 1));
        mt0 = fmaxf(mt0, __shfl_xor_sync(0xffffffffu, mt0, 2));
        mt1 = fmaxf(mt1, __shfl_xor_sync(0xffffffffu, mt1, 1));
        mt1 = fmaxf(mt1, __shfl_xor_sync(0xffffffffu, mt1, 2));

        const float mn0 = fmaxf(m0, mt0), mn1 = fmaxf(m1, mt1);
        const float corr0 = __expf(m0 - mn0), corr1 = __expf(m1 - mn1);

        uint32_t ph[8][2];
        float la0 = 0.0f, la1 = 0.0f;
#pragma unroll
        for (int ni = 0; ni < 8; ni++) {
            const float p0 = __expf(fabsf(s[ni][0]) - mn0);
            const float p1 = __expf(fabsf(s[ni][1]) - mn0);
            const float p2 = __expf(fabsf(s[ni][2]) - mn1);
            const float p3 = __expf(fabsf(s[ni][3]) - mn1);
            ph[ni][0] = pack_h2(p0, p1);
            ph[ni][1] = pack_h2(p2, p3);
            la0 += p0 + p1;
            la1 += p2 + p3;
        }
        la0 += __shfl_xor_sync(0xffffffffu, la0, 1);
        la0 += __shfl_xor_sync(0xffffffffu, la0, 2);
        la1 += __shfl_xor_sync(0xffffffffu, la1, 1);
        la1 += __shfl_xor_sync(0xffffffffu, la1, 2);

        l0 = l0 * corr0 + la0; m0 = mn0;
        l1 = l1 * corr1 + la1; m1 = mn1;
#pragma unroll
        for (int nd = 0; nd < 8; nd++) {
            o[nd][0] *= corr0; o[nd][1] *= corr0;
            o[nd][2] *= corr1; o[nd][3] *= corr1;
        }

#pragma unroll
        for (int ks = 0; ks < 4; ks++) {
            const int kk = ks * 16;
            const uint32_t a0 = ph[2 * ks][0];
            const uint32_t a1 = ph[2 * ks][1];
            const uint32_t a2 = ph[2 * ks + 1][0];
            const uint32_t a3 = ph[2 * ks + 1][1];
#pragma unroll
            for (int nd = 0; nd < 8; nd++) {
                const int dr = nd * 8 + g;
                const uint32_t b0 = *(const uint32_t*)&Vt[dr * APH + kk + 2 * tq];
                const uint32_t b1 = *(const uint32_t*)&Vt[dr * APH + kk + 8 + 2 * tq];
                mma_f16(o[nd], a0, a1, a2, a3, b0, b1);
            }
        }
    }
#undef AT_ISSUE

    const float inv0 = 1.0f / (8.0f * l0);
    const float inv1 = 1.0f / (8.0f * l1);
    float* Ob0 = O + ((size_t)(b * NT + qb * 64 + qrow0)) * DIMF + h * HD;
    float* Ob1 = Ob0 + (size_t)8 * DIMF;
#pragma unroll
    for (int nd = 0; nd < 8; nd++) {
        const int col = nd * 8 + 2 * tq;
        *(float2*)(Ob0 + col) = make_float2(o[nd][0] * inv0, o[nd][1] * inv0);
        *(float2*)(Ob1 + col) = make_float2(o[nd][2] * inv1, o[nd][3] * inv1);
    }
}

// ---------------------------------------------------------------------------
// LayerNorm fp32 -> fp16 (single-stream variant used in FFN)
// ---------------------------------------------------------------------------
__device__ __forceinline__ void ln_body(const float* __restrict__ xr,
                                        const float* __restrict__ g,
                                        const float* __restrict__ b,
                                        __half* __restrict__ yr, int t)
{
    float4 v = ((const float4*)xr)[t];
    float s  = v.x + v.y + v.z + v.w;
    float s2 = v.x*v.x + v.y*v.y + v.z*v.z + v.w*v.w;
#pragma unroll
    for (int off = 16; off; off >>= 1) {
        s  += __shfl_xor_sync(0xffffffffu, s,  off);
        s2 += __shfl_xor_sync(0xffffffffu, s2, off);
    }
    __shared__ float sh[8];
    const int w = t >> 5, lane = t & 31;
    if (lane == 0) { sh[w] = s; sh[4 + w] = s2; }
    __syncthreads();
    s  = sh[0] + sh[1] + sh[2] + sh[3];
    s2 = sh[4] + sh[5] + sh[6] + sh[7];
    const float mu   = s * (1.0f / DIMF);
    const float var  = s2 * (1.0f / DIMF) - mu * mu;
    const float rstd = rsqrtf(var + 1e-5f);
    float4 gv = ((const float4*)g)[t];
    float4 bv = ((const float4*)b)[t];
    __half2* yo = (__half2*)yr;
    yo[2 * t]     = __floats2half2_rn((v.x - mu) * rstd * gv.x + bv.x,
                                      (v.y - mu) * rstd * gv.y + bv.y);
    yo[2 * t + 1] = __floats2half2_rn((v.z - mu) * rstd * gv.z + bv.z,
                                      (v.w - mu) * rstd * gv.w + bv.w);
}

__global__ void __launch_bounds__(128) ln_k(const float* __restrict__ x,
                                            const float* __restrict__ g,
                                            const float* __restrict__ b,
                                            __half* __restrict__ y)
{
    ln_body(x + (size_t)blockIdx.x * DIMF, g, b,
            y + (size_t)blockIdx.x * DIMF, threadIdx.x);
}

// merged input LNs: grid.y = 0 -> diff/lnd -> FEAQ; 1 -> con/lnc -> FEAKV
__global__ void __launch_bounds__(128) ln2_k(const float* __restrict__ diff,
                                             const float* __restrict__ con,
                                             const float* __restrict__ lndg,
                                             const float* __restrict__ lndb,
                                             const float* __restrict__ lncg,
                                             const float* __restrict__ lncb,
                                             __half* __restrict__ hb)
{
    const int which = blockIdx.y;
    const float* x = (which == 0 ? diff : con) + (size_t)blockIdx.x * DIMF;
    __half* y = hb + (which == 0 ? H_FEAQ : H_FEAKV) + (size_t)blockIdx.x * DIMF;
    ln_body(x, which == 0 ? lndg : lncg, which == 0 ? lndb : lncb, y, threadIdx.x);
}

// ---------------------------------------------------------------------------
// Two-phase deterministic per-sample stats (ddof=1)
// ---------------------------------------------------------------------------
__global__ void __launch_bounds__(256) stats1_k(const float* __restrict__ a,
                                                float* __restrict__ part)
{
    const int b = blockIdx.x, c = blockIdx.y;    // (4, 32)
    const float* p = a + (size_t)b * (NT * DIMF) + (size_t)c * 16384;
    float s = 0.0f, s2 = 0.0f;
#pragma unroll 4
    for (int i = threadIdx.x; i < 4096; i += 256) {
        float4 v = ((const float4*)p)[i];
        s += v.x + v.y + v.z + v.w;
        s2 += v.x*v.x + v.y*v.y + v.z*v.z + v.w*v.w;
    }
#pragma unroll
    for (int off = 16; off; off >>= 1) {
        s  += __shfl_xor_sync(0xffffffffu, s,  off);
        s2 += __shfl_xor_sync(0xffffffffu, s2, off);
    }
    __shared__ float sh[16];
    const int w = threadIdx.x >> 5;
    if ((threadIdx.x & 31) == 0) { sh[w] = s; sh[8 + w] = s2; }
    __syncthreads();
    if (threadIdx.x == 0) {
        float ts = 0.0f, ts2 = 0.0f;
        for (int i = 0; i < 8; i++) { ts += sh[i]; ts2 += sh[8 + i]; }
        part[(b * 32 + c) * 2]     = ts;
        part[(b * 32 + c) * 2 + 1] = ts2;
    }
}

__global__ void __launch_bounds__(128) stats2_k(const float* __restrict__ part,
                                                float* __restrict__ st)
{
    const int w = threadIdx.x >> 5, lane = threadIdx.x & 31;
    double s = (double)part[(w * 32 + lane) * 2];
    double s2 = (double)part[(w * 32 + lane) * 2 + 1];
#pragma unroll
    for (int off = 16; off; off >>= 1) {
        s  += __shfl_xor_sync(0xffffffffu, s,  off);
        s2 += __shfl_xor_sync(0xffffffffu, s2, off);
    }
    if (lane == 0) {
        double N   = (double)(NT * DIMF);
        double mu  = s / N;
        double var = (s2 - N * mu * mu) / (N - 1.0);
        st[w * 2 + 0] = (float)mu;
        st[w * 2 + 1] = (float)(1.0 / sqrt(var));
    }
}

// ---------------------------------------------------------------------------
// Fused time MLP: h1 = silu(te@w1+b1); t = h1@w2+b2.  One CTA per batch.
// ---------------------------------------------------------------------------
__global__ void __launch_bounds__(1024) tmlp_k(const float* __restrict__ te,
                                               const float* __restrict__ w1,
                                               const float* __restrict__ b1,
                                               const float* __restrict__ w2,
                                               const float* __restrict__ b2,
                                               float* __restrict__ tout)
{
    __shared__ float tes[512];
    __shared__ float h1s[1024];
    const int b = blockIdx.x;
    const int j = threadIdx.x;
    if (j < 512) tes[j] = te[b * 512 + j];
    __syncthreads();
    float acc = 0.0f;
    for (int k = 0; k < 512; k++)
        acc = fmaf(tes[k], w1[k * 1024 + j], acc);
    acc += b1[j];
    h1s[j] = acc / (1.0f + __expf(-acc));
    __syncthreads();
    float acc2 = 0.0f;
    for (int k = 0; k < 1024; k++)
        acc2 = fmaf(h1s[k], w2[k * 1024 + j], acc2);
    tout[b * 1024 + j] = acc2 + b2[j];
}

// ---------------------------------------------------------------------------
// FiLM apply (fp32 in -> fp16 out)
// ---------------------------------------------------------------------------
__global__ void __launch_bounds__(256) film_k(const float* __restrict__ a,
                                              const float* __restrict__ t,
                                              const float* __restrict__ st,
                                              __half* __restrict__ x)
{
    const int i = blockIdx.x * 256 + threadIdx.x;
    const int idx = i * 2;
    const int c = idx & 511;
    const int b = idx >> 19;
    const float mu = st[b * 2], rstd = st[b * 2 + 1];
    const float2 av = *(const float2*)(a + idx);
    const float s0 = t[b * 1024 + 512 + c], s1 = t[b * 1024 + 512 + c + 1];
    const float m0v = t[b * 1024 + c],      m1v = t[b * 1024 + c + 1];
    *(__half2*)(x + idx) = __floats2half2_rn((av.x - mu) * rstd * s0 + m0v,
                                             (av.y - mu) * rstd * s1 + m1v);
}

// ---------------------------------------------------------------------------
// Launch
// ---------------------------------------------------------------------------
extern "C" void kernel_launch(void* const* d_in, const int* in_sizes, int n_in,
                              void* d_out, int out_size)
{
    const float* con   = (const float*)d_in[0];
    const float* diff  = (const float*)d_in[1];
    const float* temb  = (const float*)d_in[2];
    const float* lncg  = (const float*)d_in[3];
    const float* lncb  = (const float*)d_in[4];
    const float* lndg  = (const float*)d_in[5];
    const float* lndb  = (const float*)d_in[6];
    const float* wq    = (const float*)d_in[7];
    const float* wk    = (const float*)d_in[8];
    const float* wv    = (const float*)d_in[9];
    const float* wout  = (const float*)d_in[10];
    const float* bout  = (const float*)d_in[11];
    const float* wemd1 = (const float*)d_in[12];
    const float* bemd1 = (const float*)d_in[13];
    const float* wemd2 = (const float*)d_in[14];
    const float* bemd2 = (const float*)d_in[15];
    const float* mlng  = (const float*)d_in[16];
    const float* mlnb  = (const float*)d_in[17];
    const float* mw1   = (const float*)d_in[18];
    const float* mb1   = (const float*)d_in[19];
    const float* mw2   = (const float*)d_in[20];
    const float* mb2   = (const float*)d_in[21];

    float* buf = nullptr;
    cudaGetSymbolAddress((void**)&buf, g_buf);
    __half* hb = (__half*)(buf + O_HB);

    const int hg_smem = 3 * 2 * 128 * KPH * 2;   // 61440
    cudaFuncSetAttribute(qkv_k,        cudaFuncAttributeMaxDynamicSharedMemorySize, hg_smem);
    cudaFuncSetAttribute(hgemm_k<1,0>, cudaFuncAttributeMaxDynamicSharedMemorySize, hg_smem);
    cudaFuncSetAttribute(hgemm_k<2,1>, cudaFuncAttributeMaxDynamicSharedMemorySize, hg_smem);
    const int at_smem = 8 * 4608 * 2;            // 73728
    cudaFuncSetAttribute(attnh_k, cudaFuncAttributeMaxDynamicSharedMemorySize, at_smem);

    // 0) weights -> [N][K] fp16
    tr512x6_k<<<dim3(16, 16, 6), 256>>>(wq, wk, wv, wout, mw1, mw2, hb + H_WT);

    // 1) both input LayerNorms in one launch
    ln2_k<<<dim3(NB * NT, 2), 128>>>(diff, con, lndg, lndb, lncg, lncb, hb);

    // 2) fused Q/K/V projections (one launch, 384 CTAs)
    qkv_k<<<dim3(4, 32, 3), 256, hg_smem>>>(hb);

    // 2b) flipped + transposed V
    vprep_k<<<dim3(16, 32), 256>>>(hb + H_VH, hb + H_VT);

    // 3) attention
    attnh_k<<<dim3(NT / 64, NB * NHD), 128, at_smem>>>(
        hb + H_QHI, hb + H_QLO, hb + H_KHI, hb + H_KLO, hb + H_VT, buf + O_ATT);

    // 4) stats (two-phase) + fused time MLP + FiLM
    stats1_k<<<dim3(NB, 32), 256>>>(buf + O_ATT, buf + O_PART);
    stats2_k<<<1, 128>>>(buf + O_PART, buf + O_STATS);
    tmlp_k<<<NB, 1024>>>(temb, wemd1, bemd1, wemd2, bemd2, buf + O_T);
    film_k<<<(int)(SZ / 512), 256>>>(buf + O_ATT, buf + O_T, buf + O_STATS,
                                     hb + H_X);

    // 5) output projection
    hgemm_k<1,0><<<dim3(4, 32), 256, hg_smem>>>(hb + H_X, hb + H_WT + 3 * WSTEP,
                                                bout, buf + O_OUT1);

    // 6) FeedForward
    ln_k<<<NB * NT, 128>>>(buf + O_OUT1, mlng, mlnb, hb + H_H);
    hgemm_k<2,1><<<dim3(4, 32), 256, hg_smem>>>(hb + H_H, hb + H_WT + 4 * WSTEP,
                                                mb1, hb + H_H2);
    hgemm_k<1,0><<<dim3(4, 32), 256, hg_smem>>>(hb + H_H2, hb + H_WT + 5 * WSTEP,
                                                mb2, (float*)d_out);
}

// round 8
// speedup vs baseline: 3.2792x; 1.0543x over previous
#include <cuda_runtime.h>
#include <cuda_fp16.h>
#include <math.h>
#include <stdint.h>

// ---------------------------------------------------------------------------
// Problem constants
// ---------------------------------------------------------------------------
#define NT   1024
#define DIMF 512
#define NB   4
#define NHD  8
#define HD   64

static constexpr size_t SZ = (size_t)NB * NT * DIMF;   // 2,097,152

__device__ float g_buf[SZ * 10 + 2 * 1024 * 1024];

// fp32 region
static constexpr size_t O_ATT   = 0;
static constexpr size_t O_OUT1  = 1 * SZ;
static constexpr size_t O_T     = 2 * SZ + 4096;    // 4096 floats
static constexpr size_t O_STATS = 2 * SZ + 8192;    // 8 floats
static constexpr size_t O_PART  = 2 * SZ + 8448;    // 256 floats partials
static constexpr size_t O_HB    = 2 * SZ + 9216;    // half region starts (floats)

// half-region offsets (in halves)
static constexpr size_t H_FEAQ  = 0;
static constexpr size_t H_FEAKV = 1 * SZ;
static constexpr size_t H_QHI   = 2 * SZ;
static constexpr size_t H_KHI   = 4 * SZ;
static constexpr size_t H_KLO   = 5 * SZ;
static constexpr size_t H_VH    = 6 * SZ;
static constexpr size_t H_X     = 8 * SZ;
static constexpr size_t H_H     = 9 * SZ;
static constexpr size_t H_H2    = 10 * SZ;
static constexpr size_t H_WT    = 11 * SZ;          // 6 x 512*512 halves
static constexpr size_t WSTEP   = (size_t)DIMF * DIMF;

// ---------------------------------------------------------------------------
// helpers
// ---------------------------------------------------------------------------
__device__ __forceinline__ uint32_t pack_h2(float a, float b)
{
    __half2 h = __floats2half2_rn(a, b);
    return *(uint32_t*)&h;
}

__device__ __forceinline__ void mma_f16(float c[4],
                                        uint32_t a0, uint32_t a1,
                                        uint32_t a2, uint32_t a3,
                                        uint32_t b0, uint32_t b1)
{
    asm volatile(
        "mma.sync.aligned.m16n8k16.row.col.f32.f16.f16.f32 "
        "{%0,%1,%2,%3}, {%4,%5,%6,%7}, {%8,%9}, {%0,%1,%2,%3};"
        : "+f"(c[0]), "+f"(c[1]), "+f"(c[2]), "+f"(c[3])
        : "r"(a0), "r"(a1), "r"(a2), "r"(a3), "r"(b0), "r"(b1));
}

__device__ __forceinline__ void ldsm4t(uint32_t& r0, uint32_t& r1,
                                       uint32_t& r2, uint32_t& r3,
                                       uint32_t addr)
{
    asm volatile(
        "ldmatrix.sync.aligned.m8n8.x4.trans.shared.b16 {%0,%1,%2,%3}, [%4];"
        : "=r"(r0), "=r"(r1), "=r"(r2), "=r"(r3) : "r"(addr));
}

__device__ __forceinline__ void cp16(uint32_t saddr, const void* gaddr)
{
    asm volatile("cp.async.ca.shared.global [%0], [%1], 16;"
                 :: "r"(saddr), "l"(gaddr) : "memory");
}
#define CP_COMMIT() asm volatile("cp.async.commit_group;" ::: "memory")
#define CP_WAIT(n)  asm volatile("cp.async.wait_group %0;" :: "n"(n) : "memory")

__device__ __forceinline__ float gelu_exact(float x)
{
    return 0.5f * x * (1.0f + erff(x * 0.70710678118654752f));
}

// ---------------------------------------------------------------------------
// Batched 512x512 transpose: 6 fp32 weights -> [N][K] fp16
// ---------------------------------------------------------------------------
__global__ void __launch_bounds__(256) tr512x6_k(const float* __restrict__ w0,
                                                 const float* __restrict__ w1,
                                                 const float* __restrict__ w2,
                                                 const float* __restrict__ w3,
                                                 const float* __restrict__ w4,
                                                 const float* __restrict__ w5,
                                                 __half* __restrict__ out)
{
    const float* srcs[6] = {w0, w1, w2, w3, w4, w5};
    const float* w = srcs[blockIdx.z];
    __half* wt = out + (size_t)blockIdx.z * WSTEP;

    __shared__ float t[32][33];
    const int tx = threadIdx.x & 31, ty = threadIdx.x >> 5;
    const int x = blockIdx.x * 32 + tx;
    const int y0 = blockIdx.y * 32;
#pragma unroll
    for (int j = 0; j < 32; j += 8)
        t[ty + j][tx] = w[(size_t)(y0 + ty + j) * 512 + x];
    __syncthreads();
    const int x2 = y0 + tx;
#pragma unroll
    for (int j = 0; j < 32; j += 8)
        wt[(size_t)(blockIdx.x * 32 + ty + j) * 512 + x2] = __float2half_rn(t[tx][ty + j]);
}

// ---------------------------------------------------------------------------
// GEMM mainloop: 128x128 CTA tile, 8 warps, cp.async 3-stage
// ---------------------------------------------------------------------------
#define KPH 40

__device__ __forceinline__ void gemm_core(const __half* __restrict__ A,
                                          const __half* __restrict__ Bt,
                                          __half* Ash, __half* Bsh,
                                          int m0, int n0, int tid,
                                          float acc[4][4][4])
{
    const int wid = tid >> 5, lane = tid & 31;
    const int g = lane >> 2, tq = lane & 3;
    const int m0w = (wid >> 2) * 64;
    const int n0w = (wid & 3) * 32;

    const int lrow = tid >> 1;
    const int lseg = (tid & 1) * 32;

    const uint32_t ashb = (uint32_t)__cvta_generic_to_shared(Ash);
    const uint32_t bshb = (uint32_t)__cvta_generic_to_shared(Bsh);
    const char* Ag = (const char*)(A  + (size_t)(m0 + lrow) * 512);
    const char* Bg = (const char*)(Bt + (size_t)(n0 + lrow) * 512);
    const uint32_t srow = lrow * KPH * 2 + lseg;

#define HG_ISSUE(c, st) do {                                                  \
        uint32_t sa = ashb + (uint32_t)(st) * 128 * KPH * 2 + srow;           \
        uint32_t sb = bshb + (uint32_t)(st) * 128 * KPH * 2 + srow;           \
        const char* ga = Ag + (c) * 64 + lseg;                                \
        const char* gb = Bg + (c) * 64 + lseg;                                \
        cp16(sa, ga); cp16(sa + 16, ga + 16);                                 \
        cp16(sb, gb); cp16(sb + 16, gb + 16);                                 \
    } while (0)

    HG_ISSUE(0, 0); CP_COMMIT();
    HG_ISSUE(1, 1); CP_COMMIT();

    for (int c = 0; c < 16; c++) {
        const int st = c % 3;
        CP_WAIT(1);
        __syncthreads();
        if (c + 2 < 16) { HG_ISSUE(c + 2, (c + 2) % 3); }
        CP_COMMIT();

        const __half* As = Ash + st * 128 * KPH;
        const __half* Bs = Bsh + st * 128 * KPH;
#pragma unroll
        for (int ks = 0; ks < 2; ks++) {
            const int kk = ks * 16;
            uint32_t af[4][4], bf[4][2];
#pragma unroll
            for (int mi = 0; mi < 4; mi++) {
                const int r = m0w + mi * 16 + g;
                af[mi][0] = *(const uint32_t*)&As[(r    ) * KPH + kk + 2 * tq];
                af[mi][1] = *(const uint32_t*)&As[(r + 8) * KPH + kk + 2 * tq];
                af[mi][2] = *(const uint32_t*)&As[(r    ) * KPH + kk + 8 + 2 * tq];
                af[mi][3] = *(const uint32_t*)&As[(r + 8) * KPH + kk + 8 + 2 * tq];
            }
#pragma unroll
            for (int ni = 0; ni < 4; ni++) {
                const int r = n0w + ni * 8 + g;
                bf[ni][0] = *(const uint32_t*)&Bs[r * KPH + kk + 2 * tq];
                bf[ni][1] = *(const uint32_t*)&Bs[r * KPH + kk + 8 + 2 * tq];
            }
#pragma unroll
            for (int mi = 0; mi < 4; mi++)
#pragma unroll
                for (int ni = 0; ni < 4; ni++)
                    mma_f16(acc[mi][ni], af[mi][0], af[mi][1], af[mi][2], af[mi][3],
                            bf[ni][0], bf[ni][1]);
        }
    }
#undef HG_ISSUE
}

// ---------------------------------------------------------------------------
// Fused Q/K/V projection: grid.z selects operand pair + output mode
// z=0 -> Q (plain fp16), z=1 -> K (hi/lo split), z=2 -> V (plain fp16)
// ---------------------------------------------------------------------------
__global__ void __launch_bounds__(256, 2) qkv_k(__half* __restrict__ hb)
{
    extern __shared__ __half gsm[];
    __half* Ash = gsm;
    __half* Bsh = gsm + 3 * 128 * KPH;

    const int z = blockIdx.z;
    const __half* A  = hb + (z == 0 ? H_FEAQ : H_FEAKV);
    const __half* Bt = hb + H_WT + (size_t)z * WSTEP;

    const int tid = threadIdx.x;
    const int wid = tid >> 5, lane = tid & 31;
    const int g = lane >> 2, tq = lane & 3;
    const int m0w = (wid >> 2) * 64;
    const int n0w = (wid & 3) * 32;
    const int m0 = blockIdx.y * 128, n0 = blockIdx.x * 128;

    float acc[4][4][4] = {};
    gemm_core(A, Bt, Ash, Bsh, m0, n0, tid, acc);

    __half* Ch = hb + (z == 0 ? H_QHI : (z == 1 ? H_KHI : H_VH));
    __half* Cl = hb + H_KLO;

#pragma unroll
    for (int mi = 0; mi < 4; mi++) {
        const int row = m0 + m0w + mi * 16 + g;
#pragma unroll
        for (int ni = 0; ni < 4; ni++) {
            const int col = n0 + n0w + ni * 8 + 2 * tq;
            const float v0 = acc[mi][ni][0], v1 = acc[mi][ni][1];
            const float v2 = acc[mi][ni][2], v3 = acc[mi][ni][3];
            if (z == 1) {
                const __half h0 = __float2half_rn(v0), h1 = __float2half_rn(v1);
                const __half h2 = __float2half_rn(v2), h3 = __float2half_rn(v3);
                *(__half2*)(Ch + (size_t)row * 512 + col) = __halves2half2(h0, h1);
                *(__half2*)(Ch + (size_t)(row + 8) * 512 + col) = __halves2half2(h2, h3);
                *(__half2*)(Cl + (size_t)row * 512 + col) = __floats2half2_rn(
                    v0 - __half2float(h0), v1 - __half2float(h1));
                *(__half2*)(Cl + (size_t)(row + 8) * 512 + col) = __floats2half2_rn(
                    v2 - __half2float(h2), v3 - __half2float(h3));
            } else {
                *(__half2*)(Ch + (size_t)row * 512 + col)       = __floats2half2_rn(v0, v1);
                *(__half2*)(Ch + (size_t)(row + 8) * 512 + col) = __floats2half2_rn(v2, v3);
            }
        }
    }
}

// ---------------------------------------------------------------------------
// Standalone GEMM (for w_out / mlp): EPI 1 +bias, 2 +bias+GELU; OUT 0 fp32, 1 fp16
// ---------------------------------------------------------------------------
template <int EPI, int OUT>
__global__ void __launch_bounds__(256, 2)
hgemm_k(const __half* __restrict__ A, const __half* __restrict__ Bt,
        const float* __restrict__ bias, void* __restrict__ Cv)
{
    extern __shared__ __half gsm[];
    __half* Ash = gsm;
    __half* Bsh = gsm + 3 * 128 * KPH;

    const int tid = threadIdx.x;
    const int wid = tid >> 5, lane = tid & 31;
    const int g = lane >> 2, tq = lane & 3;
    const int m0w = (wid >> 2) * 64;
    const int n0w = (wid & 3) * 32;
    const int m0 = blockIdx.y * 128, n0 = blockIdx.x * 128;

    float acc[4][4][4] = {};
    gemm_core(A, Bt, Ash, Bsh, m0, n0, tid, acc);

#pragma unroll
    for (int mi = 0; mi < 4; mi++) {
        const int row = m0 + m0w + mi * 16 + g;
#pragma unroll
        for (int ni = 0; ni < 4; ni++) {
            const int col = n0 + n0w + ni * 8 + 2 * tq;
            float v0 = acc[mi][ni][0], v1 = acc[mi][ni][1];
            float v2 = acc[mi][ni][2], v3 = acc[mi][ni][3];
            if (EPI >= 1) {
                const float b0 = bias[col], b1 = bias[col + 1];
                v0 += b0; v1 += b1; v2 += b0; v3 += b1;
            }
            if (EPI == 2) {
                v0 = gelu_exact(v0); v1 = gelu_exact(v1);
                v2 = gelu_exact(v2); v3 = gelu_exact(v3);
            }
            if (OUT == 0) {
                float* C = (float*)Cv;
                *(float2*)(C + (size_t)row * 512 + col)       = make_float2(v0, v1);
                *(float2*)(C + (size_t)(row + 8) * 512 + col) = make_float2(v2, v3);
            } else {
                __half* C = (__half*)Cv;
                *(__half2*)(C + (size_t)row * 512 + col)       = __floats2half2_rn(v0, v1);
                *(__half2*)(C + (size_t)(row + 8) * 512 + col) = __floats2half2_rn(v2, v3);
            }
        }
    }
}

// ---------------------------------------------------------------------------
// Tensor-core attention, cp.async pipeline, 2-mma QK split, ldmatrix.trans V
// out = softmax_rows(|Q K^T|) @ V_flip / 8
// smem layout (bytes): Qhi [0,9216) | Khi x2 [9216,27648) | Klo x2 [27648,46080)
//                      | Vs x2 [46080,62464)  (V tiles 64x128B, XOR-swizzled)
// ---------------------------------------------------------------------------
#define APH 72

__global__ void __launch_bounds__(128) attnh_k(const __half* __restrict__ Qhi_g,
                                               const __half* __restrict__ Khi_g,
                                               const __half* __restrict__ Klo_g,
                                               const __half* __restrict__ Vh_g,
                                               float* __restrict__ O)
{
    extern __shared__ __half hsm[];
    __half* Qhi = hsm;

    const int qb = blockIdx.x;
    const int bh = blockIdx.y;
    const int b = bh >> 3, h = bh & 7;
    const int tid = threadIdx.x;
    const int wid = tid >> 5, lane = tid & 31;
    const int g = lane >> 2, tq = lane & 3;

    const uint32_t base = (uint32_t)__cvta_generic_to_shared(hsm);

    const char* qh  = (const char*)(Qhi_g + ((size_t)(b * NT) + qb * 64) * 512 + h * 64);
    const char* khg = (const char*)(Khi_g + (size_t)b * NT * 512 + h * 64);
    const char* klg = (const char*)(Klo_g + (size_t)b * NT * 512 + h * 64);
    const char* vhg = (const char*)(Vh_g  + (size_t)b * NT * 512 + h * 64);

#define AT_ISSUE(kt, bf) do {                                                 \
        const uint32_t kb = base + 9216u  + (uint32_t)(bf) * 9216u;           \
        const uint32_t lb = base + 27648u + (uint32_t)(bf) * 9216u;           \
        const uint32_t vb = base + 46080u + (uint32_t)(bf) * 8192u;           \
        for (int i = tid; i < 512; i += 128) {                                \
            const int r = i >> 3, c = i & 7;                                  \
            const uint32_t so = (uint32_t)r * 144 + c * 16;                   \
            cp16(kb + so, khg + ((size_t)((kt) * 64 + r)) * 1024 + c * 16);   \
            cp16(lb + so, klg + ((size_t)((kt) * 64 + r)) * 1024 + c * 16);   \
            const int n = (1024 - ((kt) * 64 + r)) & 1023;                    \
            cp16(vb + (uint32_t)r * 128 + (uint32_t)((c ^ (r & 7)) << 4),     \
                 vhg + (size_t)n * 1024 + c * 16);                            \
        }                                                                     \
    } while (0)

    // prologue: Q + key-tile 0 in one group
    for (int i = tid; i < 512; i += 128) {
        const int r = i >> 3, c = i & 7;
        cp16(base + (uint32_t)r * 144 + c * 16, qh + (size_t)r * 1024 + c * 16);
    }
    AT_ISSUE(0, 0);
    CP_COMMIT();

    float m0 = -1e30f, m1 = -1e30f, l0 = 0.0f, l1 = 0.0f;
    float o[8][4];
#pragma unroll
    for (int i = 0; i < 8; i++)
#pragma unroll
        for (int j = 0; j < 4; j++) o[i][j] = 0.0f;

    const int qrow0 = wid * 16 + g;

    for (int kt = 0; kt < 16; kt++) {
        CP_WAIT(0);
        __syncthreads();
        if (kt + 1 < 16) { AT_ISSUE(kt + 1, (kt + 1) & 1); }
        CP_COMMIT();

        const __half* Kh = hsm + 4608  + (kt & 1) * 4608;
        const __half* Kl = hsm + 13824 + (kt & 1) * 4608;
        const uint32_t vsb = base + 46080u + (uint32_t)(kt & 1) * 8192u;

        // ---- S = Qhi (Khi + Klo)^T : 2 mmas per fragment ----
        float s[8][4];
#pragma unroll
        for (int i = 0; i < 8; i++)
#pragma unroll
            for (int j = 0; j < 4; j++) s[i][j] = 0.0f;

#pragma unroll
        for (int ks = 0; ks < 4; ks++) {
            const int kk = ks * 16;
            const uint32_t ah0 = *(const uint32_t*)&Qhi[(qrow0    ) * APH + kk + 2 * tq];
            const uint32_t ah1 = *(const uint32_t*)&Qhi[(qrow0 + 8) * APH + kk + 2 * tq];
            const uint32_t ah2 = *(const uint32_t*)&Qhi[(qrow0    ) * APH + kk + 8 + 2 * tq];
            const uint32_t ah3 = *(const uint32_t*)&Qhi[(qrow0 + 8) * APH + kk + 8 + 2 * tq];
#pragma unroll
            for (int ni = 0; ni < 8; ni++) {
                const int kr = ni * 8 + g;
                const uint32_t bh0 = *(const uint32_t*)&Kh[kr * APH + kk + 2 * tq];
                const uint32_t bh1 = *(const uint32_t*)&Kh[kr * APH + kk + 8 + 2 * tq];
                const uint32_t bl0 = *(const uint32_t*)&Kl[kr * APH + kk + 2 * tq];
                const uint32_t bl1 = *(const uint32_t*)&Kl[kr * APH + kk + 8 + 2 * tq];
                mma_f16(s[ni], ah0, ah1, ah2, ah3, bh0, bh1);
                mma_f16(s[ni], ah0, ah1, ah2, ah3, bl0, bl1);
            }
        }

        // ---- online softmax on |s| ----
        float mt0 = -1e30f, mt1 = -1e30f;
#pragma unroll
        for (int ni = 0; ni < 8; ni++) {
            mt0 = fmaxf(mt0, fmaxf(fabsf(s[ni][0]), fabsf(s[ni][1])));
            mt1 = fmaxf(mt1, fmaxf(fabsf(s[ni][2]), fabsf(s[ni][3])));
        }
        mt0 = fmaxf(mt0, __shfl_xor_sync(0xffffffffu, mt0, 1));
        mt0 = fmaxf(mt0, __shfl_xor_sync(0xffffffffu, mt0, 2));
        mt1 = fmaxf(mt1, __shfl_xor_sync(0xffffffffu, mt1, 1));
        mt1 = fmaxf(mt1, __shfl_xor_sync(0xffffffffu, mt1, 2));

        const float mn0 = fmaxf(m0, mt0), mn1 = fmaxf(m1, mt1);
        const float corr0 = __expf(m0 - mn0), corr1 = __expf(m1 - mn1);

        uint32_t ph[8][2];
        float la0 = 0.0f, la1 = 0.0f;
#pragma unroll
        for (int ni = 0; ni < 8; ni++) {
            const float p0 = __expf(fabsf(s[ni][0]) - mn0);
            const float p1 = __expf(fabsf(s[ni][1]) - mn0);
            const float p2 = __expf(fabsf(s[ni][2]) - mn1);
            const float p3 = __expf(fabsf(s[ni][3]) - mn1);
            ph[ni][0] = pack_h2(p0, p1);
            ph[ni][1] = pack_h2(p2, p3);
            la0 += p0 + p1;
            la1 += p2 + p3;
        }
        la0 += __shfl_xor_sync(0xffffffffu, la0, 1);
        la0 += __shfl_xor_sync(0xffffffffu, la0, 2);
        la1 += __shfl_xor_sync(0xffffffffu, la1, 1);
        la1 += __shfl_xor_sync(0xffffffffu, la1, 2);

        l0 = l0 * corr0 + la0; m0 = mn0;
        l1 = l1 * corr1 + la1; m1 = mn1;
#pragma unroll
        for (int nd = 0; nd < 8; nd++) {
            o[nd][0] *= corr0; o[nd][1] *= corr0;
            o[nd][2] *= corr1; o[nd][3] *= corr1;
        }

        // ---- O += P @ V (V tile [kpos][d], ldmatrix.x4.trans) ----
#pragma unroll
        for (int ks = 0; ks < 4; ks++) {
            const uint32_t a0 = ph[2 * ks][0];
            const uint32_t a1 = ph[2 * ks][1];
            const uint32_t a2 = ph[2 * ks + 1][0];
            const uint32_t a3 = ph[2 * ks + 1][1];
            const int krow = ks * 16 + (lane & 15);
#pragma unroll
            for (int ndp = 0; ndp < 4; ndp++) {
                const int dch = ndp * 2 + (lane >> 4);
                const uint32_t addr = vsb + (uint32_t)krow * 128
                                    + (uint32_t)((dch ^ (krow & 7)) << 4);
                uint32_t v0, v1, v2, v3;
                ldsm4t(v0, v1, v2, v3, addr);
                mma_f16(o[2 * ndp],     a0, a1, a2, a3, v0, v1);
                mma_f16(o[2 * ndp + 1], a0, a1, a2, a3, v2, v3);
            }
        }
    }
#undef AT_ISSUE

    const float inv0 = 1.0f / (8.0f * l0);
    const float inv1 = 1.0f / (8.0f * l1);
    float* Ob0 = O + ((size_t)(b * NT + qb * 64 + qrow0)) * DIMF + h * HD;
    float* Ob1 = Ob0 + (size_t)8 * DIMF;
#pragma unroll
    for (int nd = 0; nd < 8; nd++) {
        const int col = nd * 8 + 2 * tq;
        *(float2*)(Ob0 + col) = make_float2(o[nd][0] * inv0, o[nd][1] * inv0);
        *(float2*)(Ob1 + col) = make_float2(o[nd][2] * inv1, o[nd][3] * inv1);
    }
}

// ---------------------------------------------------------------------------
// LayerNorm fp32 -> fp16
// ---------------------------------------------------------------------------
__device__ __forceinline__ void ln_body(const float* __restrict__ xr,
                                        const float* __restrict__ g,
                                        const float* __restrict__ b,
                                        __half* __restrict__ yr, int t)
{
    float4 v = ((const float4*)xr)[t];
    float s  = v.x + v.y + v.z + v.w;
    float s2 = v.x*v.x + v.y*v.y + v.z*v.z + v.w*v.w;
#pragma unroll
    for (int off = 16; off; off >>= 1) {
        s  += __shfl_xor_sync(0xffffffffu, s,  off);
        s2 += __shfl_xor_sync(0xffffffffu, s2, off);
    }
    __shared__ float sh[8];
    const int w = t >> 5, lane = t & 31;
    if (lane == 0) { sh[w] = s; sh[4 + w] = s2; }
    __syncthreads();
    s  = sh[0] + sh[1] + sh[2] + sh[3];
    s2 = sh[4] + sh[5] + sh[6] + sh[7];
    const float mu   = s * (1.0f / DIMF);
    const float var  = s2 * (1.0f / DIMF) - mu * mu;
    const float rstd = rsqrtf(var + 1e-5f);
    float4 gv = ((const float4*)g)[t];
    float4 bv = ((const float4*)b)[t];
    __half2* yo = (__half2*)yr;
    yo[2 * t]     = __floats2half2_rn((v.x - mu) * rstd * gv.x + bv.x,
                                      (v.y - mu) * rstd * gv.y + bv.y);
    yo[2 * t + 1] = __floats2half2_rn((v.z - mu) * rstd * gv.z + bv.z,
                                      (v.w - mu) * rstd * gv.w + bv.w);
}

__global__ void __launch_bounds__(128) ln_k(const float* __restrict__ x,
                                            const float* __restrict__ g,
                                            const float* __restrict__ b,
                                            __half* __restrict__ y)
{
    ln_body(x + (size_t)blockIdx.x * DIMF, g, b,
            y + (size_t)blockIdx.x * DIMF, threadIdx.x);
}

__global__ void __launch_bounds__(128) ln2_k(const float* __restrict__ diff,
                                             const float* __restrict__ con,
                                             const float* __restrict__ lndg,
                                             const float* __restrict__ lndb,
                                             const float* __restrict__ lncg,
                                             const float* __restrict__ lncb,
                                             __half* __restrict__ hb)
{
    const int which = blockIdx.y;
    const float* x = (which == 0 ? diff : con) + (size_t)blockIdx.x * DIMF;
    __half* y = hb + (which == 0 ? H_FEAQ : H_FEAKV) + (size_t)blockIdx.x * DIMF;
    ln_body(x, which == 0 ? lndg : lncg, which == 0 ? lndb : lncb, y, threadIdx.x);
}

// ---------------------------------------------------------------------------
// Two-phase deterministic per-sample stats (ddof=1)
// ---------------------------------------------------------------------------
__global__ void __launch_bounds__(256) stats1_k(const float* __restrict__ a,
                                                float* __restrict__ part)
{
    const int b = blockIdx.x, c = blockIdx.y;    // (4, 32)
    const float* p = a + (size_t)b * (NT * DIMF) + (size_t)c * 16384;
    float s = 0.0f, s2 = 0.0f;
#pragma unroll 4
    for (int i = threadIdx.x; i < 4096; i += 256) {
        float4 v = ((const float4*)p)[i];
        s += v.x + v.y + v.z + v.w;
        s2 += v.x*v.x + v.y*v.y + v.z*v.z + v.w*v.w;
    }
#pragma unroll
    for (int off = 16; off; off >>= 1) {
        s  += __shfl_xor_sync(0xffffffffu, s,  off);
        s2 += __shfl_xor_sync(0xffffffffu, s2, off);
    }
    __shared__ float sh[16];
    const int w = threadIdx.x >> 5;
    if ((threadIdx.x & 31) == 0) { sh[w] = s; sh[8 + w] = s2; }
    __syncthreads();
    if (threadIdx.x == 0) {
        float ts = 0.0f, ts2 = 0.0f;
        for (int i = 0; i < 8; i++) { ts += sh[i]; ts2 += sh[8 + i]; }
        part[(b * 32 + c) * 2]     = ts;
        part[(b * 32 + c) * 2 + 1] = ts2;
    }
}

__global__ void __launch_bounds__(128) stats2_k(const float* __restrict__ part,
                                                float* __restrict__ st)
{
    const int w = threadIdx.x >> 5, lane = threadIdx.x & 31;
    double s = (double)part[(w * 32 + lane) * 2];
    double s2 = (double)part[(w * 32 + lane) * 2 + 1];
#pragma unroll
    for (int off = 16; off; off >>= 1) {
        s  += __shfl_xor_sync(0xffffffffu, s,  off);
        s2 += __shfl_xor_sync(0xffffffffu, s2, off);
    }
    if (lane == 0) {
        double N   = (double)(NT * DIMF);
        double mu  = s / N;
        double var = (s2 - N * mu * mu) / (N - 1.0);
        st[w * 2 + 0] = (float)mu;
        st[w * 2 + 1] = (float)(1.0 / sqrt(var));
    }
}

// ---------------------------------------------------------------------------
// Fused time MLP: h1 = silu(te@w1+b1); t = h1@w2+b2.  One CTA per batch.
// ---------------------------------------------------------------------------
__global__ void __launch_bounds__(1024) tmlp_k(const float* __restrict__ te,
                                               const float* __restrict__ w1,
                                               const float* __restrict__ b1,
                                               const float* __restrict__ w2,
                                               const float* __restrict__ b2,
                                               float* __restrict__ tout)
{
    __shared__ float tes[512];
    __shared__ float h1s[1024];
    const int b = blockIdx.x;
    const int j = threadIdx.x;
    if (j < 512) tes[j] = te[b * 512 + j];
    __syncthreads();
    float acc = 0.0f;
    for (int k = 0; k < 512; k++)
        acc = fmaf(tes[k], w1[k * 1024 + j], acc);
    acc += b1[j];
    h1s[j] = acc / (1.0f + __expf(-acc));
    __syncthreads();
    float acc2 = 0.0f;
    for (int k = 0; k < 1024; k++)
        acc2 = fmaf(h1s[k], w2[k * 1024 + j], acc2);
    tout[b * 1024 + j] = acc2 + b2[j];
}

// ---------------------------------------------------------------------------
// FiLM apply (fp32 in -> fp16 out)
// ---------------------------------------------------------------------------
__global__ void __launch_bounds__(256) film_k(const float* __restrict__ a,
                                              const float* __restrict__ t,
                                              const float* __restrict__ st,
                                              __half* __restrict__ x)
{
    const int i = blockIdx.x * 256 + threadIdx.x;
    const int idx = i * 2;
    const int c = idx & 511;
    const int b = idx >> 19;
    const float mu = st[b * 2], rstd = st[b * 2 + 1];
    const float2 av = *(const float2*)(a + idx);
    const float s0 = t[b * 1024 + 512 + c], s1 = t[b * 1024 + 512 + c + 1];
    const float m0v = t[b * 1024 + c],      m1v = t[b * 1024 + c + 1];
    *(__half2*)(x + idx) = __floats2half2_rn((av.x - mu) * rstd * s0 + m0v,
                                             (av.y - mu) * rstd * s1 + m1v);
}

// ---------------------------------------------------------------------------
// Launch
// ---------------------------------------------------------------------------
extern "C" void kernel_launch(void* const* d_in, const int* in_sizes, int n_in,
                              void* d_out, int out_size)
{
    const float* con   = (const float*)d_in[0];
    const float* diff  = (const float*)d_in[1];
    const float* temb  = (const float*)d_in[2];
    const float* lncg  = (const float*)d_in[3];
    const float* lncb  = (const float*)d_in[4];
    const float* lndg  = (const float*)d_in[5];
    const float* lndb  = (const float*)d_in[6];
    const float* wq    = (const float*)d_in[7];
    const float* wk    = (const float*)d_in[8];
    const float* wv    = (const float*)d_in[9];
    const float* wout  = (const float*)d_in[10];
    const float* bout  = (const float*)d_in[11];
    const float* wemd1 = (const float*)d_in[12];
    const float* bemd1 = (const float*)d_in[13];
    const float* wemd2 = (const float*)d_in[14];
    const float* bemd2 = (const float*)d_in[15];
    const float* mlng  = (const float*)d_in[16];
    const float* mlnb  = (const float*)d_in[17];
    const float* mw1   = (const float*)d_in[18];
    const float* mb1   = (const float*)d_in[19];
    const float* mw2   = (const float*)d_in[20];
    const float* mb2   = (const float*)d_in[21];

    float* buf = nullptr;
    cudaGetSymbolAddress((void**)&buf, g_buf);
    __half* hb = (__half*)(buf + O_HB);

    const int hg_smem = 3 * 2 * 128 * KPH * 2;   // 61440
    cudaFuncSetAttribute(qkv_k,        cudaFuncAttributeMaxDynamicSharedMemorySize, hg_smem);
    cudaFuncSetAttribute(hgemm_k<1,0>, cudaFuncAttributeMaxDynamicSharedMemorySize, hg_smem);
    cudaFuncSetAttribute(hgemm_k<2,1>, cudaFuncAttributeMaxDynamicSharedMemorySize, hg_smem);
    const int at_smem = 62464;                   // Q + 2xKhi + 2xKlo + 2xVs
    cudaFuncSetAttribute(attnh_k, cudaFuncAttributeMaxDynamicSharedMemorySize, at_smem);

    // 0) weights -> [N][K] fp16
    tr512x6_k<<<dim3(16, 16, 6), 256>>>(wq, wk, wv, wout, mw1, mw2, hb + H_WT);

    // 1) both input LayerNorms in one launch
    ln2_k<<<dim3(NB * NT, 2), 128>>>(diff, con, lndg, lndb, lncg, lncb, hb);

    // 2) fused Q/K/V projections (one launch, 384 CTAs)
    qkv_k<<<dim3(4, 32, 3), 256, hg_smem>>>(hb);

    // 3) attention (flip+transpose of V folded in via ldmatrix.trans)
    attnh_k<<<dim3(NT / 64, NB * NHD), 128, at_smem>>>(
        hb + H_QHI, hb + H_KHI, hb + H_KLO, hb + H_VH, buf + O_ATT);

    // 4) stats (two-phase) + fused time MLP + FiLM
    stats1_k<<<dim3(NB, 32), 256>>>(buf + O_ATT, buf + O_PART);
    stats2_k<<<1, 128>>>(buf + O_PART, buf + O_STATS);
    tmlp_k<<<NB, 1024>>>(temb, wemd1, bemd1, wemd2, bemd2, buf + O_T);
    film_k<<<(int)(SZ / 512), 256>>>(buf + O_ATT, buf + O_T, buf + O_STATS,
                                     hb + H_X);

    // 5) output projection
    hgemm_k<1,0><<<dim3(4, 32), 256, hg_smem>>>(hb + H_X, hb + H_WT + 3 * WSTEP,
                                                bout, buf + O_OUT1);

    // 6) FeedForward
    ln_k<<<NB * NT, 128>>>(buf + O_OUT1, mlng, mlnb, hb + H_H);
    hgemm_k<2,1><<<dim3(4, 32), 256, hg_smem>>>(hb + H_H, hb + H_WT + 4 * WSTEP,
                                                mb1, hb + H_H2);
    hgemm_k<1,0><<<dim3(4, 32), 256, hg_smem>>>(hb + H_H2, hb + H_WT + 5 * WSTEP,
                                                mb2, (float*)d_out);
}

// round 9
// speedup vs baseline: 3.7163x; 1.1333x over previous
#include <cuda_runtime.h>
#include <cuda_fp16.h>
#include <math.h>
#include <stdint.h>

// ---------------------------------------------------------------------------
// Problem constants
// ---------------------------------------------------------------------------
#define NT   1024
#define DIMF 512
#define NB   4
#define NHD  8
#define HD   64

static constexpr size_t SZ = (size_t)NB * NT * DIMF;   // 2,097,152

__device__ float g_buf[SZ * 10 + 2 * 1024 * 1024];

// fp32 region
static constexpr size_t O_ATT   = 0;
static constexpr size_t O_OUT1  = 1 * SZ;
static constexpr size_t O_T     = 2 * SZ + 4096;
static constexpr size_t O_STATS = 2 * SZ + 8192;
static constexpr size_t O_PART  = 2 * SZ + 8448;
static constexpr size_t O_HB    = 2 * SZ + 9216;

// half-region offsets (in halves)
static constexpr size_t H_FEAQ  = 0;
static constexpr size_t H_FEAKV = 1 * SZ;
static constexpr size_t H_QHI   = 2 * SZ;
static constexpr size_t H_KHI   = 4 * SZ;
static constexpr size_t H_KLO   = 5 * SZ;
static constexpr size_t H_VH    = 6 * SZ;
static constexpr size_t H_X     = 8 * SZ;
static constexpr size_t H_H     = 9 * SZ;
static constexpr size_t H_H2    = 10 * SZ;
static constexpr size_t H_WT    = 11 * SZ;
static constexpr size_t WSTEP   = (size_t)DIMF * DIMF;

// ---------------------------------------------------------------------------
// helpers
// ---------------------------------------------------------------------------
__device__ __forceinline__ uint32_t pack_h2(float a, float b)
{
    __half2 h = __floats2half2_rn(a, b);
    return *(uint32_t*)&h;
}

__device__ __forceinline__ void mma_f16(float c[4],
                                        uint32_t a0, uint32_t a1,
                                        uint32_t a2, uint32_t a3,
                                        uint32_t b0, uint32_t b1)
{
    asm volatile(
        "mma.sync.aligned.m16n8k16.row.col.f32.f16.f16.f32 "
        "{%0,%1,%2,%3}, {%4,%5,%6,%7}, {%8,%9}, {%0,%1,%2,%3};"
        : "+f"(c[0]), "+f"(c[1]), "+f"(c[2]), "+f"(c[3])
        : "r"(a0), "r"(a1), "r"(a2), "r"(a3), "r"(b0), "r"(b1));
}

__device__ __forceinline__ void ldsm4(uint32_t& r0, uint32_t& r1,
                                      uint32_t& r2, uint32_t& r3,
                                      uint32_t addr)
{
    asm volatile(
        "ldmatrix.sync.aligned.m8n8.x4.shared.b16 {%0,%1,%2,%3}, [%4];"
        : "=r"(r0), "=r"(r1), "=r"(r2), "=r"(r3) : "r"(addr));
}

__device__ __forceinline__ void ldsm4t(uint32_t& r0, uint32_t& r1,
                                       uint32_t& r2, uint32_t& r3,
                                       uint32_t addr)
{
    asm volatile(
        "ldmatrix.sync.aligned.m8n8.x4.trans.shared.b16 {%0,%1,%2,%3}, [%4];"
        : "=r"(r0), "=r"(r1), "=r"(r2), "=r"(r3) : "r"(addr));
}

__device__ __forceinline__ void cp16(uint32_t saddr, const void* gaddr)
{
    asm volatile("cp.async.ca.shared.global [%0], [%1], 16;"
                 :: "r"(saddr), "l"(gaddr) : "memory");
}
#define CP_COMMIT() asm volatile("cp.async.commit_group;" ::: "memory")
#define CP_WAIT(n)  asm volatile("cp.async.wait_group %0;" :: "n"(n) : "memory")

__device__ __forceinline__ float gelu_exact(float x)
{
    return 0.5f * x * (1.0f + erff(x * 0.70710678118654752f));
}

// ---------------------------------------------------------------------------
// Batched 512x512 transpose: 6 fp32 weights -> [N][K] fp16
// ---------------------------------------------------------------------------
__global__ void __launch_bounds__(256) tr512x6_k(const float* __restrict__ w0,
                                                 const float* __restrict__ w1,
                                                 const float* __restrict__ w2,
                                                 const float* __restrict__ w3,
                                                 const float* __restrict__ w4,
                                                 const float* __restrict__ w5,
                                                 __half* __restrict__ out)
{
    const float* srcs[6] = {w0, w1, w2, w3, w4, w5};
    const float* w = srcs[blockIdx.z];
    __half* wt = out + (size_t)blockIdx.z * WSTEP;

    __shared__ float t[32][33];
    const int tx = threadIdx.x & 31, ty = threadIdx.x >> 5;
    const int x = blockIdx.x * 32 + tx;
    const int y0 = blockIdx.y * 32;
#pragma unroll
    for (int j = 0; j < 32; j += 8)
        t[ty + j][tx] = w[(size_t)(y0 + ty + j) * 512 + x];
    __syncthreads();
    const int x2 = y0 + tx;
#pragma unroll
    for (int j = 0; j < 32; j += 8)
        wt[(size_t)(blockIdx.x * 32 + ty + j) * 512 + x2] = __float2half_rn(t[tx][ty + j]);
}

// ---------------------------------------------------------------------------
// GEMM mainloop: 128x128 CTA tile, 8 warps, cp.async 3-stage,
// XOR-swizzled smem (64B rows) + ldmatrix fragment loads.
// ---------------------------------------------------------------------------
#define STG 8192   // bytes per operand stage (128 rows x 64 B)

__device__ __forceinline__ void gemm_core(const __half* __restrict__ A,
                                          const __half* __restrict__ Bt,
                                          uint32_t ashb, uint32_t bshb,
                                          int m0, int n0, int tid,
                                          float acc[4][4][4])
{
    const int wid = tid >> 5, lane = tid & 31;
    const int m0w = (wid >> 2) * 64;
    const int n0w = (wid & 3) * 32;

    // loader: thread -> row lr, chunks lc0,lc0+1 (16B each)
    const int lr = tid >> 1;
    const int lc0 = (tid & 1) * 2;
    const char* Ag = (const char*)(A  + (size_t)(m0 + lr) * 512);
    const char* Bg = (const char*)(Bt + (size_t)(n0 + lr) * 512);
    const uint32_t lsw = (lr >> 1) & 3;
    const uint32_t so0 = (uint32_t)lr * 64 + (((uint32_t)lc0 ^ lsw) << 4);
    const uint32_t so1 = (uint32_t)lr * 64 + ((((uint32_t)lc0 + 1) ^ lsw) << 4);

    // fragment address lanes
    const int ra = lane & 15, ca = lane >> 4;                       // A
    const int rb = (lane & 7) + ((lane >> 4) << 3), cb = (lane >> 3) & 1; // B

#define HG_ISSUE(c, st) do {                                                  \
        const uint32_t sa = ashb + (uint32_t)(st) * STG;                      \
        const uint32_t sb = bshb + (uint32_t)(st) * STG;                      \
        const char* ga = Ag + (c) * 64 + lc0 * 16;                            \
        const char* gb = Bg + (c) * 64 + lc0 * 16;                            \
        cp16(sa + so0, ga); cp16(sa + so1, ga + 16);                          \
        cp16(sb + so0, gb); cp16(sb + so1, gb + 16);                          \
    } while (0)

    HG_ISSUE(0, 0); CP_COMMIT();
    HG_ISSUE(1, 1); CP_COMMIT();

    for (int c = 0; c < 16; c++) {
        const int st = c % 3;
        CP_WAIT(1);
        __syncthreads();
        if (c + 2 < 16) { HG_ISSUE(c + 2, (c + 2) % 3); }
        CP_COMMIT();

        const uint32_t sA = ashb + (uint32_t)st * STG;
        const uint32_t sB = bshb + (uint32_t)st * STG;
#pragma unroll
        for (int ks = 0; ks < 2; ks++) {
            uint32_t af[4][4], bf[4][2];
#pragma unroll
            for (int mi = 0; mi < 4; mi++) {
                const int r = m0w + mi * 16 + ra;
                const uint32_t cc = (uint32_t)(ks * 2 + ca) ^ (((uint32_t)r >> 1) & 3);
                ldsm4(af[mi][0], af[mi][1], af[mi][2], af[mi][3],
                      sA + (uint32_t)r * 64 + (cc << 4));
            }
#pragma unroll
            for (int nip = 0; nip < 2; nip++) {
                const int r = n0w + nip * 16 + rb;
                const uint32_t cc = (uint32_t)(ks * 2 + cb) ^ (((uint32_t)r >> 1) & 3);
                ldsm4(bf[2 * nip][0], bf[2 * nip][1],
                      bf[2 * nip + 1][0], bf[2 * nip + 1][1],
                      sB + (uint32_t)r * 64 + (cc << 4));
            }
#pragma unroll
            for (int mi = 0; mi < 4; mi++)
#pragma unroll
                for (int ni = 0; ni < 4; ni++)
                    mma_f16(acc[mi][ni], af[mi][0], af[mi][1], af[mi][2], af[mi][3],
                            bf[ni][0], bf[ni][1]);
        }
    }
#undef HG_ISSUE
}

// ---------------------------------------------------------------------------
// Fused Q/K/V projection: z=0 Q (fp16), z=1 K (hi/lo), z=2 V (fp16)
// ---------------------------------------------------------------------------
__global__ void __launch_bounds__(256, 2) qkv_k(__half* __restrict__ hb)
{
    extern __shared__ __half gsm[];
    const uint32_t ashb = (uint32_t)__cvta_generic_to_shared(gsm);
    const uint32_t bshb = ashb + 3 * STG;

    const int z = blockIdx.z;
    const __half* A  = hb + (z == 0 ? H_FEAQ : H_FEAKV);
    const __half* Bt = hb + H_WT + (size_t)z * WSTEP;

    const int tid = threadIdx.x;
    const int wid = tid >> 5, lane = tid & 31;
    const int g = lane >> 2, tq = lane & 3;
    const int m0w = (wid >> 2) * 64;
    const int n0w = (wid & 3) * 32;
    const int m0 = blockIdx.y * 128, n0 = blockIdx.x * 128;

    float acc[4][4][4] = {};
    gemm_core(A, Bt, ashb, bshb, m0, n0, tid, acc);

    __half* Ch = hb + (z == 0 ? H_QHI : (z == 1 ? H_KHI : H_VH));
    __half* Cl = hb + H_KLO;

#pragma unroll
    for (int mi = 0; mi < 4; mi++) {
        const int row = m0 + m0w + mi * 16 + g;
#pragma unroll
        for (int ni = 0; ni < 4; ni++) {
            const int col = n0 + n0w + ni * 8 + 2 * tq;
            const float v0 = acc[mi][ni][0], v1 = acc[mi][ni][1];
            const float v2 = acc[mi][ni][2], v3 = acc[mi][ni][3];
            if (z == 1) {
                const __half h0 = __float2half_rn(v0), h1 = __float2half_rn(v1);
                const __half h2 = __float2half_rn(v2), h3 = __float2half_rn(v3);
                *(__half2*)(Ch + (size_t)row * 512 + col) = __halves2half2(h0, h1);
                *(__half2*)(Ch + (size_t)(row + 8) * 512 + col) = __halves2half2(h2, h3);
                *(__half2*)(Cl + (size_t)row * 512 + col) = __floats2half2_rn(
                    v0 - __half2float(h0), v1 - __half2float(h1));
                *(__half2*)(Cl + (size_t)(row + 8) * 512 + col) = __floats2half2_rn(
                    v2 - __half2float(h2), v3 - __half2float(h3));
            } else {
                *(__half2*)(Ch + (size_t)row * 512 + col)       = __floats2half2_rn(v0, v1);
                *(__half2*)(Ch + (size_t)(row + 8) * 512 + col) = __floats2half2_rn(v2, v3);
            }
        }
    }
}

// ---------------------------------------------------------------------------
// Standalone GEMM: EPI 1 +bias, 2 +bias+GELU; OUT 0 fp32, 1 fp16
// ---------------------------------------------------------------------------
template <int EPI, int OUT>
__global__ void __launch_bounds__(256, 2)
hgemm_k(const __half* __restrict__ A, const __half* __restrict__ Bt,
        const float* __restrict__ bias, void* __restrict__ Cv)
{
    extern __shared__ __half gsm[];
    const uint32_t ashb = (uint32_t)__cvta_generic_to_shared(gsm);
    const uint32_t bshb = ashb + 3 * STG;

    const int tid = threadIdx.x;
    const int wid = tid >> 5, lane = tid & 31;
    const int g = lane >> 2, tq = lane & 3;
    const int m0w = (wid >> 2) * 64;
    const int n0w = (wid & 3) * 32;
    const int m0 = blockIdx.y * 128, n0 = blockIdx.x * 128;

    float acc[4][4][4] = {};
    gemm_core(A, Bt, ashb, bshb, m0, n0, tid, acc);

#pragma unroll
    for (int mi = 0; mi < 4; mi++) {
        const int row = m0 + m0w + mi * 16 + g;
#pragma unroll
        for (int ni = 0; ni < 4; ni++) {
            const int col = n0 + n0w + ni * 8 + 2 * tq;
            float v0 = acc[mi][ni][0], v1 = acc[mi][ni][1];
            float v2 = acc[mi][ni][2], v3 = acc[mi][ni][3];
            if (EPI >= 1) {
                const float b0 = bias[col], b1 = bias[col + 1];
                v0 += b0; v1 += b1; v2 += b0; v3 += b1;
            }
            if (EPI == 2) {
                v0 = gelu_exact(v0); v1 = gelu_exact(v1);
                v2 = gelu_exact(v2); v3 = gelu_exact(v3);
            }
            if (OUT == 0) {
                float* C = (float*)Cv;
                *(float2*)(C + (size_t)row * 512 + col)       = make_float2(v0, v1);
                *(float2*)(C + (size_t)(row + 8) * 512 + col) = make_float2(v2, v3);
            } else {
                __half* C = (__half*)Cv;
                *(__half2*)(C + (size_t)row * 512 + col)       = __floats2half2_rn(v0, v1);
                *(__half2*)(C + (size_t)(row + 8) * 512 + col) = __floats2half2_rn(v2, v3);
            }
        }
    }
}

// ---------------------------------------------------------------------------
// Tensor-core attention: swizzled smem, ldmatrix frags, Q frags hoisted.
// smem bytes: Q [0,8K) | Khi x2 [8K,24K) | Klo x2 [24K,40K) | Vs x2 [40K,56K)
// ---------------------------------------------------------------------------
__global__ void __launch_bounds__(128) attnh_k(const __half* __restrict__ Qhi_g,
                                               const __half* __restrict__ Khi_g,
                                               const __half* __restrict__ Klo_g,
                                               const __half* __restrict__ Vh_g,
                                               float* __restrict__ O)
{
    extern __shared__ __half hsm[];
    const uint32_t base = (uint32_t)__cvta_generic_to_shared(hsm);

    const int qb = blockIdx.x;
    const int bh = blockIdx.y;
    const int b = bh >> 3, h = bh & 7;
    const int tid = threadIdx.x;
    const int wid = tid >> 5, lane = tid & 31;
    const int g = lane >> 2, tq = lane & 3;

    const char* qh  = (const char*)(Qhi_g + ((size_t)(b * NT) + qb * 64) * 512 + h * 64);
    const char* khg = (const char*)(Khi_g + (size_t)b * NT * 512 + h * 64);
    const char* klg = (const char*)(Klo_g + (size_t)b * NT * 512 + h * 64);
    const char* vhg = (const char*)(Vh_g  + (size_t)b * NT * 512 + h * 64);

    // loader pattern: 4 iterations, row r0+16j, chunk lc
    const int r0l = tid >> 3, lc = tid & 7;

#define AT_ISSUE(kt, bf) do {                                                 \
        const uint32_t kb = base + 8192u  + (uint32_t)(bf) * 8192u;           \
        const uint32_t lb = base + 24576u + (uint32_t)(bf) * 8192u;           \
        const uint32_t vb = base + 40960u + (uint32_t)(bf) * 8192u;           \
        _Pragma("unroll")                                                     \
        for (int j = 0; j < 4; j++) {                                         \
            const int r = r0l + 16 * j;                                       \
            const uint32_t so = (uint32_t)r * 128 + (((uint32_t)lc ^ (r & 7)) << 4); \
            cp16(kb + so, khg + ((size_t)((kt) * 64 + r)) * 1024 + lc * 16);  \
            cp16(lb + so, klg + ((size_t)((kt) * 64 + r)) * 1024 + lc * 16);  \
            const int n = (1024 - ((kt) * 64 + r)) & 1023;                    \
            cp16(vb + so, vhg + (size_t)n * 1024 + lc * 16);                  \
        }                                                                     \
    } while (0)

    // prologue: Q + key-tile 0 in one group
#pragma unroll
    for (int j = 0; j < 4; j++) {
        const int r = r0l + 16 * j;
        const uint32_t so = (uint32_t)r * 128 + (((uint32_t)lc ^ (r & 7)) << 4);
        cp16(base + so, qh + (size_t)r * 1024 + lc * 16);
    }
    AT_ISSUE(0, 0);
    CP_COMMIT();

    float m0 = -1e30f, m1 = -1e30f, l0 = 0.0f, l1 = 0.0f;
    float o[8][4];
#pragma unroll
    for (int i = 0; i < 8; i++)
#pragma unroll
        for (int j = 0; j < 4; j++) o[i][j] = 0.0f;

    const int qrow0 = wid * 16 + g;
    uint32_t qf[4][4];

    // fragment lane patterns
    const int raq = lane & 15, caq = lane >> 4;                     // Q (A-op)
    const int rbk = (lane & 7) + ((lane >> 4) << 3), cbk = (lane >> 3) & 1; // K (B-op)

    for (int kt = 0; kt < 16; kt++) {
        CP_WAIT(0);
        __syncthreads();
        if (kt == 0) {
            // hoist Q fragments into registers (reused across all key tiles)
#pragma unroll
            for (int ks = 0; ks < 4; ks++) {
                const int r = wid * 16 + raq;
                const uint32_t cc = (uint32_t)(ks * 2 + caq) ^ ((uint32_t)r & 7);
                ldsm4(qf[ks][0], qf[ks][1], qf[ks][2], qf[ks][3],
                      base + (uint32_t)r * 128 + (cc << 4));
            }
        }
        if (kt + 1 < 16) { AT_ISSUE(kt + 1, (kt + 1) & 1); }
        CP_COMMIT();

        const uint32_t kbase = base + 8192u  + (uint32_t)(kt & 1) * 8192u;
        const uint32_t lbase = base + 24576u + (uint32_t)(kt & 1) * 8192u;
        const uint32_t vsb   = base + 40960u + (uint32_t)(kt & 1) * 8192u;

        // ---- S = Qhi (Khi + Klo)^T ----
        float s[8][4];
#pragma unroll
        for (int i = 0; i < 8; i++)
#pragma unroll
            for (int j = 0; j < 4; j++) s[i][j] = 0.0f;

#pragma unroll
        for (int ks = 0; ks < 4; ks++) {
#pragma unroll
            for (int nip = 0; nip < 4; nip++) {
                const int r = nip * 16 + rbk;
                const uint32_t cc = (uint32_t)(ks * 2 + cbk) ^ ((uint32_t)r & 7);
                const uint32_t off = (uint32_t)r * 128 + (cc << 4);
                uint32_t b0, b1, b2, b3;
                ldsm4(b0, b1, b2, b3, kbase + off);
                mma_f16(s[2 * nip],     qf[ks][0], qf[ks][1], qf[ks][2], qf[ks][3], b0, b1);
                mma_f16(s[2 * nip + 1], qf[ks][0], qf[ks][1], qf[ks][2], qf[ks][3], b2, b3);
                ldsm4(b0, b1, b2, b3, lbase + off);
                mma_f16(s[2 * nip],     qf[ks][0], qf[ks][1], qf[ks][2], qf[ks][3], b0, b1);
                mma_f16(s[2 * nip + 1], qf[ks][0], qf[ks][1], qf[ks][2], qf[ks][3], b2, b3);
            }
        }

        // ---- online softmax on |s| ----
        float mt0 = -1e30f, mt1 = -1e30f;
#pragma unroll
        for (int ni = 0; ni < 8; ni++) {
            mt0 = fmaxf(mt0, fmaxf(fabsf(s[ni][0]), fabsf(s[ni][1])));
            mt1 = fmaxf(mt1, fmaxf(fabsf(s[ni][2]), fabsf(s[ni][3])));
        }
        mt0 = fmaxf(mt0, __shfl_xor_sync(0xffffffffu, mt0, 1));
        mt0 = fmaxf(mt0, __shfl_xor_sync(0xffffffffu, mt0, 2));
        mt1 = fmaxf(mt1, __shfl_xor_sync(0xffffffffu, mt1, 1));
        mt1 = fmaxf(mt1, __shfl_xor_sync(0xffffffffu, mt1, 2));

        const float mn0 = fmaxf(m0, mt0), mn1 = fmaxf(m1, mt1);
        const float corr0 = __expf(m0 - mn0), corr1 = __expf(m1 - mn1);

        uint32_t ph[8][2];
        float la0 = 0.0f, la1 = 0.0f;
#pragma unroll
        for (int ni = 0; ni < 8; ni++) {
            const float p0 = __expf(fabsf(s[ni][0]) - mn0);
            const float p1 = __expf(fabsf(s[ni][1]) - mn0);
            const float p2 = __expf(fabsf(s[ni][2]) - mn1);
            const float p3 = __expf(fabsf(s[ni][3]) - mn1);
            ph[ni][0] = pack_h2(p0, p1);
            ph[ni][1] = pack_h2(p2, p3);
            la0 += p0 + p1;
            la1 += p2 + p3;
        }
        la0 += __shfl_xor_sync(0xffffffffu, la0, 1);
        la0 += __shfl_xor_sync(0xffffffffu, la0, 2);
        la1 += __shfl_xor_sync(0xffffffffu, la1, 1);
        la1 += __shfl_xor_sync(0xffffffffu, la1, 2);

        l0 = l0 * corr0 + la0; m0 = mn0;
        l1 = l1 * corr1 + la1; m1 = mn1;
#pragma unroll
        for (int nd = 0; nd < 8; nd++) {
            o[nd][0] *= corr0; o[nd][1] *= corr0;
            o[nd][2] *= corr1; o[nd][3] *= corr1;
        }

        // ---- O += P @ V (V tile [kpos][d], ldmatrix.x4.trans) ----
#pragma unroll
        for (int ks = 0; ks < 4; ks++) {
            const uint32_t a0 = ph[2 * ks][0];
            const uint32_t a1 = ph[2 * ks][1];
            const uint32_t a2 = ph[2 * ks + 1][0];
            const uint32_t a3 = ph[2 * ks + 1][1];
            const int krow = ks * 16 + (lane & 15);
#pragma unroll
            for (int ndp = 0; ndp < 4; ndp++) {
                const int dch = ndp * 2 + (lane >> 4);
                const uint32_t addr = vsb + (uint32_t)krow * 128
                                    + (uint32_t)((dch ^ (krow & 7)) << 4);
                uint32_t v0, v1, v2, v3;
                ldsm4t(v0, v1, v2, v3, addr);
                mma_f16(o[2 * ndp],     a0, a1, a2, a3, v0, v1);
                mma_f16(o[2 * ndp + 1], a0, a1, a2, a3, v2, v3);
            }
        }
    }
#undef AT_ISSUE

    const float inv0 = 1.0f / (8.0f * l0);
    const float inv1 = 1.0f / (8.0f * l1);
    float* Ob0 = O + ((size_t)(b * NT + qb * 64 + qrow0)) * DIMF + h * HD;
    float* Ob1 = Ob0 + (size_t)8 * DIMF;
#pragma unroll
    for (int nd = 0; nd < 8; nd++) {
        const int col = nd * 8 + 2 * tq;
        *(float2*)(Ob0 + col) = make_float2(o[nd][0] * inv0, o[nd][1] * inv0);
        *(float2*)(Ob1 + col) = make_float2(o[nd][2] * inv1, o[nd][3] * inv1);
    }
}

// ---------------------------------------------------------------------------
// LayerNorm fp32 -> fp16
// ---------------------------------------------------------------------------
__device__ __forceinline__ void ln_body(const float* __restrict__ xr,
                                        const float* __restrict__ g,
                                        const float* __restrict__ b,
                                        __half* __restrict__ yr, int t)
{
    float4 v = ((const float4*)xr)[t];
    float s  = v.x + v.y + v.z + v.w;
    float s2 = v.x*v.x + v.y*v.y + v.z*v.z + v.w*v.w;
#pragma unroll
    for (int off = 16; off; off >>= 1) {
        s  += __shfl_xor_sync(0xffffffffu, s,  off);
        s2 += __shfl_xor_sync(0xffffffffu, s2, off);
    }
    __shared__ float sh[8];
    const int w = t >> 5, lane = t & 31;
    if (lane == 0) { sh[w] = s; sh[4 + w] = s2; }
    __syncthreads();
    s  = sh[0] + sh[1] + sh[2] + sh[3];
    s2 = sh[4] + sh[5] + sh[6] + sh[7];
    const float mu   = s * (1.0f / DIMF);
    const float var  = s2 * (1.0f / DIMF) - mu * mu;
    const float rstd = rsqrtf(var + 1e-5f);
    float4 gv = ((const float4*)g)[t];
    float4 bv = ((const float4*)b)[t];
    __half2* yo = (__half2*)yr;
    yo[2 * t]     = __floats2half2_rn((v.x - mu) * rstd * gv.x + bv.x,
                                      (v.y - mu) * rstd * gv.y + bv.y);
    yo[2 * t + 1] = __floats2half2_rn((v.z - mu) * rstd * gv.z + bv.z,
                                      (v.w - mu) * rstd * gv.w + bv.w);
}

__global__ void __launch_bounds__(128) ln_k(const float* __restrict__ x,
                                            const float* __restrict__ g,
                                            const float* __restrict__ b,
                                            __half* __restrict__ y)
{
    ln_body(x + (size_t)blockIdx.x * DIMF, g, b,
            y + (size_t)blockIdx.x * DIMF, threadIdx.x);
}

__global__ void __launch_bounds__(128) ln2_k(const float* __restrict__ diff,
                                             const float* __restrict__ con,
                                             const float* __restrict__ lndg,
                                             const float* __restrict__ lndb,
                                             const float* __restrict__ lncg,
                                             const float* __restrict__ lncb,
                                             __half* __restrict__ hb)
{
    const int which = blockIdx.y;
    const float* x = (which == 0 ? diff : con) + (size_t)blockIdx.x * DIMF;
    __half* y = hb + (which == 0 ? H_FEAQ : H_FEAKV) + (size_t)blockIdx.x * DIMF;
    ln_body(x, which == 0 ? lndg : lncg, which == 0 ? lndb : lncb, y, threadIdx.x);
}

// ---------------------------------------------------------------------------
// Two-phase deterministic per-sample stats (ddof=1)
// ---------------------------------------------------------------------------
__global__ void __launch_bounds__(256) stats1_k(const float* __restrict__ a,
                                                float* __restrict__ part)
{
    const int b = blockIdx.x, c = blockIdx.y;
    const float* p = a + (size_t)b * (NT * DIMF) + (size_t)c * 16384;
    float s = 0.0f, s2 = 0.0f;
#pragma unroll 4
    for (int i = threadIdx.x; i < 4096; i += 256) {
        float4 v = ((const float4*)p)[i];
        s += v.x + v.y + v.z + v.w;
        s2 += v.x*v.x + v.y*v.y + v.z*v.z + v.w*v.w;
    }
#pragma unroll
    for (int off = 16; off; off >>= 1) {
        s  += __shfl_xor_sync(0xffffffffu, s,  off);
        s2 += __shfl_xor_sync(0xffffffffu, s2, off);
    }
    __shared__ float sh[16];
    const int w = threadIdx.x >> 5;
    if ((threadIdx.x & 31) == 0) { sh[w] = s; sh[8 + w] = s2; }
    __syncthreads();
    if (threadIdx.x == 0) {
        float ts = 0.0f, ts2 = 0.0f;
        for (int i = 0; i < 8; i++) { ts += sh[i]; ts2 += sh[8 + i]; }
        part[(b * 32 + c) * 2]     = ts;
        part[(b * 32 + c) * 2 + 1] = ts2;
    }
}

__global__ void __launch_bounds__(128) stats2_k(const float* __restrict__ part,
                                                float* __restrict__ st)
{
    const int w = threadIdx.x >> 5, lane = threadIdx.x & 31;
    double s = (double)part[(w * 32 + lane) * 2];
    double s2 = (double)part[(w * 32 + lane) * 2 + 1];
#pragma unroll
    for (int off = 16; off; off >>= 1) {
        s  += __shfl_xor_sync(0xffffffffu, s,  off);
        s2 += __shfl_xor_sync(0xffffffffu, s2, off);
    }
    if (lane == 0) {
        double N   = (double)(NT * DIMF);
        double mu  = s / N;
        double var = (s2 - N * mu * mu) / (N - 1.0);
        st[w * 2 + 0] = (float)mu;
        st[w * 2 + 1] = (float)(1.0 / sqrt(var));
    }
}

// ---------------------------------------------------------------------------
// Fused time MLP
// ---------------------------------------------------------------------------
__global__ void __launch_bounds__(1024) tmlp_k(const float* __restrict__ te,
                                               const float* __restrict__ w1,
                                               const float* __restrict__ b1,
                                               const float* __restrict__ w2,
                                               const float* __restrict__ b2,
                                               float* __restrict__ tout)
{
    __shared__ float tes[512];
    __shared__ float h1s[1024];
    const int b = blockIdx.x;
    const int j = threadIdx.x;
    if (j < 512) tes[j] = te[b * 512 + j];
    __syncthreads();
    float acc = 0.0f;
    for (int k = 0; k < 512; k++)
        acc = fmaf(tes[k], w1[k * 1024 + j], acc);
    acc += b1[j];
    h1s[j] = acc / (1.0f + __expf(-acc));
    __syncthreads();
    float acc2 = 0.0f;
    for (int k = 0; k < 1024; k++)
        acc2 = fmaf(h1s[k], w2[k * 1024 + j], acc2);
    tout[b * 1024 + j] = acc2 + b2[j];
}

// ---------------------------------------------------------------------------
// FiLM apply (fp32 in -> fp16 out)
// ---------------------------------------------------------------------------
__global__ void __launch_bounds__(256) film_k(const float* __restrict__ a,
                                              const float* __restrict__ t,
                                              const float* __restrict__ st,
                                              __half* __restrict__ x)
{
    const int i = blockIdx.x * 256 + threadIdx.x;
    const int idx = i * 2;
    const int c = idx & 511;
    const int b = idx >> 19;
    const float mu = st[b * 2], rstd = st[b * 2 + 1];
    const float2 av = *(const float2*)(a + idx);
    const float s0 = t[b * 1024 + 512 + c], s1 = t[b * 1024 + 512 + c + 1];
    const float m0v = t[b * 1024 + c],      m1v = t[b * 1024 + c + 1];
    *(__half2*)(x + idx) = __floats2half2_rn((av.x - mu) * rstd * s0 + m0v,
                                             (av.y - mu) * rstd * s1 + m1v);
}

// ---------------------------------------------------------------------------
// Launch
// ---------------------------------------------------------------------------
extern "C" void kernel_launch(void* const* d_in, const int* in_sizes, int n_in,
                              void* d_out, int out_size)
{
    const float* con   = (const float*)d_in[0];
    const float* diff  = (const float*)d_in[1];
    const float* temb  = (const float*)d_in[2];
    const float* lncg  = (const float*)d_in[3];
    const float* lncb  = (const float*)d_in[4];
    const float* lndg  = (const float*)d_in[5];
    const float* lndb  = (const float*)d_in[6];
    const float* wq    = (const float*)d_in[7];
    const float* wk    = (const float*)d_in[8];
    const float* wv    = (const float*)d_in[9];
    const float* wout  = (const float*)d_in[10];
    const float* bout  = (const float*)d_in[11];
    const float* wemd1 = (const float*)d_in[12];
    const float* bemd1 = (const float*)d_in[13];
    const float* wemd2 = (const float*)d_in[14];
    const float* bemd2 = (const float*)d_in[15];
    const float* mlng  = (const float*)d_in[16];
    const float* mlnb  = (const float*)d_in[17];
    const float* mw1   = (const float*)d_in[18];
    const float* mb1   = (const float*)d_in[19];
    const float* mw2   = (const float*)d_in[20];
    const float* mb2   = (const float*)d_in[21];

    float* buf = nullptr;
    cudaGetSymbolAddress((void**)&buf, g_buf);
    __half* hb = (__half*)(buf + O_HB);

    const int hg_smem = 6 * STG;                 // 49152
    cudaFuncSetAttribute(qkv_k,        cudaFuncAttributeMaxDynamicSharedMemorySize, hg_smem);
    cudaFuncSetAttribute(hgemm_k<1,0>, cudaFuncAttributeMaxDynamicSharedMemorySize, hg_smem);
    cudaFuncSetAttribute(hgemm_k<2,1>, cudaFuncAttributeMaxDynamicSharedMemorySize, hg_smem);
    const int at_smem = 57344;                   // Q + 2xKhi + 2xKlo + 2xVs
    cudaFuncSetAttribute(attnh_k, cudaFuncAttributeMaxDynamicSharedMemorySize, at_smem);

    // 0) weights -> [N][K] fp16
    tr512x6_k<<<dim3(16, 16, 6), 256>>>(wq, wk, wv, wout, mw1, mw2, hb + H_WT);

    // 1) both input LayerNorms in one launch
    ln2_k<<<dim3(NB * NT, 2), 128>>>(diff, con, lndg, lndb, lncg, lncb, hb);

    // 2) fused Q/K/V projections
    qkv_k<<<dim3(4, 32, 3), 256, hg_smem>>>(hb);

    // 3) attention
    attnh_k<<<dim3(NT / 64, NB * NHD), 128, at_smem>>>(
        hb + H_QHI, hb + H_KHI, hb + H_KLO, hb + H_VH, buf + O_ATT);

    // 4) stats + time MLP + FiLM
    stats1_k<<<dim3(NB, 32), 256>>>(buf + O_ATT, buf + O_PART);
    stats2_k<<<1, 128>>>(buf + O_PART, buf + O_STATS);
    tmlp_k<<<NB, 1024>>>(temb, wemd1, bemd1, wemd2, bemd2, buf + O_T);
    film_k<<<(int)(SZ / 512), 256>>>(buf + O_ATT, buf + O_T, buf + O_STATS,
                                     hb + H_X);

    // 5) output projection
    hgemm_k<1,0><<<dim3(4, 32), 256, hg_smem>>>(hb + H_X, hb + H_WT + 3 * WSTEP,
                                                bout, buf + O_OUT1);

    // 6) FeedForward
    ln_k<<<NB * NT, 128>>>(buf + O_OUT1, mlng, mlnb, hb + H_H);
    hgemm_k<2,1><<<dim3(4, 32), 256, hg_smem>>>(hb + H_H, hb + H_WT + 4 * WSTEP,
                                                mb1, hb + H_H2);
    hgemm_k<1,0><<<dim3(4, 32), 256, hg_smem>>>(hb + H_H2, hb + H_WT + 5 * WSTEP,
                                                mb2, (float*)d_out);
}

// round 10
// speedup vs baseline: 3.7985x; 1.0221x over previous
#include <cuda_runtime.h>
#include <cuda_fp16.h>
#include <math.h>
#include <stdint.h>

// ---------------------------------------------------------------------------
// Problem constants
// ---------------------------------------------------------------------------
#define NT   1024
#define DIMF 512
#define NB   4
#define NHD  8
#define HD   64

static constexpr size_t SZ = (size_t)NB * NT * DIMF;   // 2,097,152

__device__ float g_buf[SZ * 10 + 2 * 1024 * 1024];

// fp32 region
static constexpr size_t O_ATT   = 0;
static constexpr size_t O_OUT1  = 1 * SZ;
static constexpr size_t O_T     = 2 * SZ + 4096;
static constexpr size_t O_STATS = 2 * SZ + 8192;
static constexpr size_t O_PART  = 2 * SZ + 8448;
static constexpr size_t O_HB    = 2 * SZ + 9216;

// half-region offsets (in halves)
static constexpr size_t H_FEAQ  = 0;
static constexpr size_t H_FEAKV = 1 * SZ;
static constexpr size_t H_QHI   = 2 * SZ;
static constexpr size_t H_KHI   = 4 * SZ;
static constexpr size_t H_KLO   = 5 * SZ;
static constexpr size_t H_VH    = 6 * SZ;
static constexpr size_t H_X     = 8 * SZ;
static constexpr size_t H_H     = 9 * SZ;
static constexpr size_t H_H2    = 10 * SZ;
static constexpr size_t H_WT    = 11 * SZ;
static constexpr size_t WSTEP   = (size_t)DIMF * DIMF;

// ---------------------------------------------------------------------------
// helpers
// ---------------------------------------------------------------------------
__device__ __forceinline__ uint32_t pack_h2(float a, float b)
{
    __half2 h = __floats2half2_rn(a, b);
    return *(uint32_t*)&h;
}

__device__ __forceinline__ void mma_f16(float c[4],
                                        uint32_t a0, uint32_t a1,
                                        uint32_t a2, uint32_t a3,
                                        uint32_t b0, uint32_t b1)
{
    asm volatile(
        "mma.sync.aligned.m16n8k16.row.col.f32.f16.f16.f32 "
        "{%0,%1,%2,%3}, {%4,%5,%6,%7}, {%8,%9}, {%0,%1,%2,%3};"
        : "+f"(c[0]), "+f"(c[1]), "+f"(c[2]), "+f"(c[3])
        : "r"(a0), "r"(a1), "r"(a2), "r"(a3), "r"(b0), "r"(b1));
}

__device__ __forceinline__ void ldsm4(uint32_t& r0, uint32_t& r1,
                                      uint32_t& r2, uint32_t& r3,
                                      uint32_t addr)
{
    asm volatile(
        "ldmatrix.sync.aligned.m8n8.x4.shared.b16 {%0,%1,%2,%3}, [%4];"
        : "=r"(r0), "=r"(r1), "=r"(r2), "=r"(r3) : "r"(addr));
}

__device__ __forceinline__ void ldsm4t(uint32_t& r0, uint32_t& r1,
                                       uint32_t& r2, uint32_t& r3,
                                       uint32_t addr)
{
    asm volatile(
        "ldmatrix.sync.aligned.m8n8.x4.trans.shared.b16 {%0,%1,%2,%3}, [%4];"
        : "=r"(r0), "=r"(r1), "=r"(r2), "=r"(r3) : "r"(addr));
}

__device__ __forceinline__ void cp16(uint32_t saddr, const void* gaddr)
{
    asm volatile("cp.async.ca.shared.global [%0], [%1], 16;"
                 :: "r"(saddr), "l"(gaddr) : "memory");
}
#define CP_COMMIT() asm volatile("cp.async.commit_group;" ::: "memory")
#define CP_WAIT(n)  asm volatile("cp.async.wait_group %0;" :: "n"(n) : "memory")

__device__ __forceinline__ float gelu_exact(float x)
{
    return 0.5f * x * (1.0f + erff(x * 0.70710678118654752f));
}

// ---------------------------------------------------------------------------
// Batched 512x512 transpose: 6 fp32 weights -> [N][K] fp16
// ---------------------------------------------------------------------------
__global__ void __launch_bounds__(256) tr512x6_k(const float* __restrict__ w0,
                                                 const float* __restrict__ w1,
                                                 const float* __restrict__ w2,
                                                 const float* __restrict__ w3,
                                                 const float* __restrict__ w4,
                                                 const float* __restrict__ w5,
                                                 __half* __restrict__ out)
{
    const float* srcs[6] = {w0, w1, w2, w3, w4, w5};
    const float* w = srcs[blockIdx.z];
    __half* wt = out + (size_t)blockIdx.z * WSTEP;

    __shared__ float t[32][33];
    const int tx = threadIdx.x & 31, ty = threadIdx.x >> 5;
    const int x = blockIdx.x * 32 + tx;
    const int y0 = blockIdx.y * 32;
#pragma unroll
    for (int j = 0; j < 32; j += 8)
        t[ty + j][tx] = w[(size_t)(y0 + ty + j) * 512 + x];
    __syncthreads();
    const int x2 = y0 + tx;
#pragma unroll
    for (int j = 0; j < 32; j += 8)
        wt[(size_t)(blockIdx.x * 32 + ty + j) * 512 + x2] = __float2half_rn(t[tx][ty + j]);
}

// ---------------------------------------------------------------------------
// GEMM mainloop: 128x128 CTA tile, 8 warps, cp.async 3-stage,
// XOR-swizzled smem (64B rows) + ldmatrix fragment loads.
// ---------------------------------------------------------------------------
#define STG 8192   // bytes per operand stage (128 rows x 64 B)

__device__ __forceinline__ void gemm_core(const __half* __restrict__ A,
                                          const __half* __restrict__ Bt,
                                          uint32_t ashb, uint32_t bshb,
                                          int m0, int n0, int tid,
                                          float acc[4][4][4])
{
    const int wid = tid >> 5, lane = tid & 31;
    const int m0w = (wid >> 2) * 64;
    const int n0w = (wid & 3) * 32;

    const int lr = tid >> 1;
    const int lc0 = (tid & 1) * 2;
    const char* Ag = (const char*)(A  + (size_t)(m0 + lr) * 512);
    const char* Bg = (const char*)(Bt + (size_t)(n0 + lr) * 512);
    const uint32_t lsw = (lr >> 1) & 3;
    const uint32_t so0 = (uint32_t)lr * 64 + (((uint32_t)lc0 ^ lsw) << 4);
    const uint32_t so1 = (uint32_t)lr * 64 + ((((uint32_t)lc0 + 1) ^ lsw) << 4);

    const int ra = lane & 15, ca = lane >> 4;
    const int rb = (lane & 7) + ((lane >> 4) << 3), cb = (lane >> 3) & 1;

#define HG_ISSUE(c, st) do {                                                  \
        const uint32_t sa = ashb + (uint32_t)(st) * STG;                      \
        const uint32_t sb = bshb + (uint32_t)(st) * STG;                      \
        const char* ga = Ag + (c) * 64 + lc0 * 16;                            \
        const char* gb = Bg + (c) * 64 + lc0 * 16;                            \
        cp16(sa + so0, ga); cp16(sa + so1, ga + 16);                          \
        cp16(sb + so0, gb); cp16(sb + so1, gb + 16);                          \
    } while (0)

    HG_ISSUE(0, 0); CP_COMMIT();
    HG_ISSUE(1, 1); CP_COMMIT();

    for (int c = 0; c < 16; c++) {
        const int st = c % 3;
        CP_WAIT(1);
        __syncthreads();
        if (c + 2 < 16) { HG_ISSUE(c + 2, (c + 2) % 3); }
        CP_COMMIT();

        const uint32_t sA = ashb + (uint32_t)st * STG;
        const uint32_t sB = bshb + (uint32_t)st * STG;
#pragma unroll
        for (int ks = 0; ks < 2; ks++) {
            uint32_t af[4][4], bf[4][2];
#pragma unroll
            for (int mi = 0; mi < 4; mi++) {
                const int r = m0w + mi * 16 + ra;
                const uint32_t cc = (uint32_t)(ks * 2 + ca) ^ (((uint32_t)r >> 1) & 3);
                ldsm4(af[mi][0], af[mi][1], af[mi][2], af[mi][3],
                      sA + (uint32_t)r * 64 + (cc << 4));
            }
#pragma unroll
            for (int nip = 0; nip < 2; nip++) {
                const int r = n0w + nip * 16 + rb;
                const uint32_t cc = (uint32_t)(ks * 2 + cb) ^ (((uint32_t)r >> 1) & 3);
                ldsm4(bf[2 * nip][0], bf[2 * nip][1],
                      bf[2 * nip + 1][0], bf[2 * nip + 1][1],
                      sB + (uint32_t)r * 64 + (cc << 4));
            }
#pragma unroll
            for (int mi = 0; mi < 4; mi++)
#pragma unroll
                for (int ni = 0; ni < 4; ni++)
                    mma_f16(acc[mi][ni], af[mi][0], af[mi][1], af[mi][2], af[mi][3],
                            bf[ni][0], bf[ni][1]);
        }
    }
#undef HG_ISSUE
}

// ---------------------------------------------------------------------------
// Fused Q/K/V projection: z=0 Q (fp16), z=1 K (hi/lo), z=2 V (fp16)
// ---------------------------------------------------------------------------
__global__ void __launch_bounds__(256, 2) qkv_k(__half* __restrict__ hb)
{
    extern __shared__ __half gsm[];
    const uint32_t ashb = (uint32_t)__cvta_generic_to_shared(gsm);
    const uint32_t bshb = ashb + 3 * STG;

    const int z = blockIdx.z;
    const __half* A  = hb + (z == 0 ? H_FEAQ : H_FEAKV);
    const __half* Bt = hb + H_WT + (size_t)z * WSTEP;

    const int tid = threadIdx.x;
    const int wid = tid >> 5, lane = tid & 31;
    const int g = lane >> 2, tq = lane & 3;
    const int m0w = (wid >> 2) * 64;
    const int n0w = (wid & 3) * 32;
    const int m0 = blockIdx.y * 128, n0 = blockIdx.x * 128;

    float acc[4][4][4] = {};
    gemm_core(A, Bt, ashb, bshb, m0, n0, tid, acc);

    __half* Ch = hb + (z == 0 ? H_QHI : (z == 1 ? H_KHI : H_VH));
    __half* Cl = hb + H_KLO;

#pragma unroll
    for (int mi = 0; mi < 4; mi++) {
        const int row = m0 + m0w + mi * 16 + g;
#pragma unroll
        for (int ni = 0; ni < 4; ni++) {
            const int col = n0 + n0w + ni * 8 + 2 * tq;
            const float v0 = acc[mi][ni][0], v1 = acc[mi][ni][1];
            const float v2 = acc[mi][ni][2], v3 = acc[mi][ni][3];
            if (z == 1) {
                const __half h0 = __float2half_rn(v0), h1 = __float2half_rn(v1);
                const __half h2 = __float2half_rn(v2), h3 = __float2half_rn(v3);
                *(__half2*)(Ch + (size_t)row * 512 + col) = __halves2half2(h0, h1);
                *(__half2*)(Ch + (size_t)(row + 8) * 512 + col) = __halves2half2(h2, h3);
                *(__half2*)(Cl + (size_t)row * 512 + col) = __floats2half2_rn(
                    v0 - __half2float(h0), v1 - __half2float(h1));
                *(__half2*)(Cl + (size_t)(row + 8) * 512 + col) = __floats2half2_rn(
                    v2 - __half2float(h2), v3 - __half2float(h3));
            } else {
                *(__half2*)(Ch + (size_t)row * 512 + col)       = __floats2half2_rn(v0, v1);
                *(__half2*)(Ch + (size_t)(row + 8) * 512 + col) = __floats2half2_rn(v2, v3);
            }
        }
    }
}

// ---------------------------------------------------------------------------
// Standalone GEMM: EPI 1 +bias, 2 +bias+GELU; OUT 0 fp32, 1 fp16
// ---------------------------------------------------------------------------
template <int EPI, int OUT>
__global__ void __launch_bounds__(256, 2)
hgemm_k(const __half* __restrict__ A, const __half* __restrict__ Bt,
        const float* __restrict__ bias, void* __restrict__ Cv)
{
    extern __shared__ __half gsm[];
    const uint32_t ashb = (uint32_t)__cvta_generic_to_shared(gsm);
    const uint32_t bshb = ashb + 3 * STG;

    const int tid = threadIdx.x;
    const int wid = tid >> 5, lane = tid & 31;
    const int g = lane >> 2, tq = lane & 3;
    const int m0w = (wid >> 2) * 64;
    const int n0w = (wid & 3) * 32;
    const int m0 = blockIdx.y * 128, n0 = blockIdx.x * 128;

    float acc[4][4][4] = {};
    gemm_core(A, Bt, ashb, bshb, m0, n0, tid, acc);

#pragma unroll
    for (int mi = 0; mi < 4; mi++) {
        const int row = m0 + m0w + mi * 16 + g;
#pragma unroll
        for (int ni = 0; ni < 4; ni++) {
            const int col = n0 + n0w + ni * 8 + 2 * tq;
            float v0 = acc[mi][ni][0], v1 = acc[mi][ni][1];
            float v2 = acc[mi][ni][2], v3 = acc[mi][ni][3];
            if (EPI >= 1) {
                const float b0 = bias[col], b1 = bias[col + 1];
                v0 += b0; v1 += b1; v2 += b0; v3 += b1;
            }
            if (EPI == 2) {
                v0 = gelu_exact(v0); v1 = gelu_exact(v1);
                v2 = gelu_exact(v2); v3 = gelu_exact(v3);
            }
            if (OUT == 0) {
                float* C = (float*)Cv;
                *(float2*)(C + (size_t)row * 512 + col)       = make_float2(v0, v1);
                *(float2*)(C + (size_t)(row + 8) * 512 + col) = make_float2(v2, v3);
            } else {
                __half* C = (__half*)Cv;
                *(__half2*)(C + (size_t)row * 512 + col)       = __floats2half2_rn(v0, v1);
                *(__half2*)(C + (size_t)(row + 8) * 512 + col) = __floats2half2_rn(v2, v3);
            }
        }
    }
}

// ---------------------------------------------------------------------------
// Tensor-core attention: 128-row Q tile, 8 warps, swizzled smem + ldmatrix.
// smem bytes: Q [0,16K) | Khi x2 [16K,32K) | Klo x2 [32K,48K) | Vs x2 [48K,64K)
// ---------------------------------------------------------------------------
__global__ void __launch_bounds__(256) attnh_k(const __half* __restrict__ Qhi_g,
                                               const __half* __restrict__ Khi_g,
                                               const __half* __restrict__ Klo_g,
                                               const __half* __restrict__ Vh_g,
                                               float* __restrict__ O)
{
    extern __shared__ __half hsm[];
    const uint32_t base = (uint32_t)__cvta_generic_to_shared(hsm);

    const int qb = blockIdx.x;                 // 0..7 (128-row blocks)
    const int bh = blockIdx.y;
    const int b = bh >> 3, h = bh & 7;
    const int tid = threadIdx.x;
    const int wid = tid >> 5, lane = tid & 31;
    const int g = lane >> 2, tq = lane & 3;

    const char* qh  = (const char*)(Qhi_g + ((size_t)(b * NT) + qb * 128) * 512 + h * 64);
    const char* khg = (const char*)(Khi_g + (size_t)b * NT * 512 + h * 64);
    const char* klg = (const char*)(Klo_g + (size_t)b * NT * 512 + h * 64);
    const char* vhg = (const char*)(Vh_g  + (size_t)b * NT * 512 + h * 64);

    const int r0l = tid >> 3, lc = tid & 7;    // loader: row base, chunk

#define AT_ISSUE(kt, bf) do {                                                 \
        const uint32_t kb = base + 16384u + (uint32_t)(bf) * 8192u;           \
        const uint32_t lb = base + 32768u + (uint32_t)(bf) * 8192u;           \
        const uint32_t vb = base + 49152u + (uint32_t)(bf) * 8192u;           \
        _Pragma("unroll")                                                     \
        for (int j = 0; j < 2; j++) {                                         \
            const int r = r0l + 32 * j;                                       \
            const uint32_t so = (uint32_t)r * 128 + (((uint32_t)lc ^ (r & 7)) << 4); \
            cp16(kb + so, khg + ((size_t)((kt) * 64 + r)) * 1024 + lc * 16);  \
            cp16(lb + so, klg + ((size_t)((kt) * 64 + r)) * 1024 + lc * 16);  \
            const int n = (1024 - ((kt) * 64 + r)) & 1023;                    \
            cp16(vb + so, vhg + (size_t)n * 1024 + lc * 16);                  \
        }                                                                     \
    } while (0)

    // prologue: Q (128 rows) + key-tile 0 in one group
#pragma unroll
    for (int j = 0; j < 4; j++) {
        const int r = r0l + 32 * j;
        const uint32_t so = (uint32_t)r * 128 + (((uint32_t)lc ^ (r & 7)) << 4);
        cp16(base + so, qh + (size_t)r * 1024 + lc * 16);
    }
    AT_ISSUE(0, 0);
    CP_COMMIT();

    float m0 = -1e30f, m1 = -1e30f, l0 = 0.0f, l1 = 0.0f;
    float o[8][4];
#pragma unroll
    for (int i = 0; i < 8; i++)
#pragma unroll
        for (int j = 0; j < 4; j++) o[i][j] = 0.0f;

    const int qrow0 = wid * 16 + g;
    uint32_t qf[4][4];

    const int raq = lane & 15, caq = lane >> 4;
    const int rbk = (lane & 7) + ((lane >> 4) << 3), cbk = (lane >> 3) & 1;

    for (int kt = 0; kt < 16; kt++) {
        CP_WAIT(0);
        __syncthreads();
        if (kt == 0) {
#pragma unroll
            for (int ks = 0; ks < 4; ks++) {
                const int r = wid * 16 + raq;
                const uint32_t cc = (uint32_t)(ks * 2 + caq) ^ ((uint32_t)r & 7);
                ldsm4(qf[ks][0], qf[ks][1], qf[ks][2], qf[ks][3],
                      base + (uint32_t)r * 128 + (cc << 4));
            }
        }
        if (kt + 1 < 16) { AT_ISSUE(kt + 1, (kt + 1) & 1); }
        CP_COMMIT();

        const uint32_t kbase = base + 16384u + (uint32_t)(kt & 1) * 8192u;
        const uint32_t lbase = base + 32768u + (uint32_t)(kt & 1) * 8192u;
        const uint32_t vsb   = base + 49152u + (uint32_t)(kt & 1) * 8192u;

        // ---- S = Qhi (Khi + Klo)^T ----
        float s[8][4];
#pragma unroll
        for (int i = 0; i < 8; i++)
#pragma unroll
            for (int j = 0; j < 4; j++) s[i][j] = 0.0f;

#pragma unroll
        for (int ks = 0; ks < 4; ks++) {
#pragma unroll
            for (int nip = 0; nip < 4; nip++) {
                const int r = nip * 16 + rbk;
                const uint32_t cc = (uint32_t)(ks * 2 + cbk) ^ ((uint32_t)r & 7);
                const uint32_t off = (uint32_t)r * 128 + (cc << 4);
                uint32_t b0, b1, b2, b3;
                ldsm4(b0, b1, b2, b3, kbase + off);
                mma_f16(s[2 * nip],     qf[ks][0], qf[ks][1], qf[ks][2], qf[ks][3], b0, b1);
                mma_f16(s[2 * nip + 1], qf[ks][0], qf[ks][1], qf[ks][2], qf[ks][3], b2, b3);
                ldsm4(b0, b1, b2, b3, lbase + off);
                mma_f16(s[2 * nip],     qf[ks][0], qf[ks][1], qf[ks][2], qf[ks][3], b0, b1);
                mma_f16(s[2 * nip + 1], qf[ks][0], qf[ks][1], qf[ks][2], qf[ks][3], b2, b3);
            }
        }

        // ---- online softmax on |s| ----
        float mt0 = -1e30f, mt1 = -1e30f;
#pragma unroll
        for (int ni = 0; ni < 8; ni++) {
            mt0 = fmaxf(mt0, fmaxf(fabsf(s[ni][0]), fabsf(s[ni][1])));
            mt1 = fmaxf(mt1, fmaxf(fabsf(s[ni][2]), fabsf(s[ni][3])));
        }
        mt0 = fmaxf(mt0, __shfl_xor_sync(0xffffffffu, mt0, 1));
        mt0 = fmaxf(mt0, __shfl_xor_sync(0xffffffffu, mt0, 2));
        mt1 = fmaxf(mt1, __shfl_xor_sync(0xffffffffu, mt1, 1));
        mt1 = fmaxf(mt1, __shfl_xor_sync(0xffffffffu, mt1, 2));

        const float mn0 = fmaxf(m0, mt0), mn1 = fmaxf(m1, mt1);
        const float corr0 = __expf(m0 - mn0), corr1 = __expf(m1 - mn1);

        uint32_t ph[8][2];
        float la0 = 0.0f, la1 = 0.0f;
#pragma unroll
        for (int ni = 0; ni < 8; ni++) {
            const float p0 = __expf(fabsf(s[ni][0]) - mn0);
            const float p1 = __expf(fabsf(s[ni][1]) - mn0);
            const float p2 = __expf(fabsf(s[ni][2]) - mn1);
            const float p3 = __expf(fabsf(s[ni][3]) - mn1);
            ph[ni][0] = pack_h2(p0, p1);
            ph[ni][1] = pack_h2(p2, p3);
            la0 += p0 + p1;
            la1 += p2 + p3;
        }
        la0 += __shfl_xor_sync(0xffffffffu, la0, 1);
        la0 += __shfl_xor_sync(0xffffffffu, la0, 2);
        la1 += __shfl_xor_sync(0xffffffffu, la1, 1);
        la1 += __shfl_xor_sync(0xffffffffu, la1, 2);

        l0 = l0 * corr0 + la0; m0 = mn0;
        l1 = l1 * corr1 + la1; m1 = mn1;
#pragma unroll
        for (int nd = 0; nd < 8; nd++) {
            o[nd][0] *= corr0; o[nd][1] *= corr0;
            o[nd][2] *= corr1; o[nd][3] *= corr1;
        }

        // ---- O += P @ V ----
#pragma unroll
        for (int ks = 0; ks < 4; ks++) {
            const uint32_t a0 = ph[2 * ks][0];
            const uint32_t a1 = ph[2 * ks][1];
            const uint32_t a2 = ph[2 * ks + 1][0];
            const uint32_t a3 = ph[2 * ks + 1][1];
            const int krow = ks * 16 + (lane & 15);
#pragma unroll
            for (int ndp = 0; ndp < 4; ndp++) {
                const int dch = ndp * 2 + (lane >> 4);
                const uint32_t addr = vsb + (uint32_t)krow * 128
                                    + (uint32_t)((dch ^ (krow & 7)) << 4);
                uint32_t v0, v1, v2, v3;
                ldsm4t(v0, v1, v2, v3, addr);
                mma_f16(o[2 * ndp],     a0, a1, a2, a3, v0, v1);
                mma_f16(o[2 * ndp + 1], a0, a1, a2, a3, v2, v3);
            }
        }
    }
#undef AT_ISSUE

    const float inv0 = 1.0f / (8.0f * l0);
    const float inv1 = 1.0f / (8.0f * l1);
    float* Ob0 = O + ((size_t)(b * NT + qb * 128 + qrow0)) * DIMF + h * HD;
    float* Ob1 = Ob0 + (size_t)8 * DIMF;
#pragma unroll
    for (int nd = 0; nd < 8; nd++) {
        const int col = nd * 8 + 2 * tq;
        *(float2*)(Ob0 + col) = make_float2(o[nd][0] * inv0, o[nd][1] * inv0);
        *(float2*)(Ob1 + col) = make_float2(o[nd][2] * inv1, o[nd][3] * inv1);
    }
}

// ---------------------------------------------------------------------------
// LayerNorm fp32 -> fp16
// ---------------------------------------------------------------------------
__device__ __forceinline__ void ln_body(const float* __restrict__ xr,
                                        const float* __restrict__ g,
                                        const float* __restrict__ b,
                                        __half* __restrict__ yr, int t)
{
    float4 v = ((const float4*)xr)[t];
    float s  = v.x + v.y + v.z + v.w;
    float s2 = v.x*v.x + v.y*v.y + v.z*v.z + v.w*v.w;
#pragma unroll
    for (int off = 16; off; off >>= 1) {
        s  += __shfl_xor_sync(0xffffffffu, s,  off);
        s2 += __shfl_xor_sync(0xffffffffu, s2, off);
    }
    __shared__ float sh[8];
    const int w = t >> 5, lane = t & 31;
    if (lane == 0) { sh[w] = s; sh[4 + w] = s2; }
    __syncthreads();
    s  = sh[0] + sh[1] + sh[2] + sh[3];
    s2 = sh[4] + sh[5] + sh[6] + sh[7];
    const float mu   = s * (1.0f / DIMF);
    const float var  = s2 * (1.0f / DIMF) - mu * mu;
    const float rstd = rsqrtf(var + 1e-5f);
    float4 gv = ((const float4*)g)[t];
    float4 bv = ((const float4*)b)[t];
    __half2* yo = (__half2*)yr;
    yo[2 * t]     = __floats2half2_rn((v.x - mu) * rstd * gv.x + bv.x,
                                      (v.y - mu) * rstd * gv.y + bv.y);
    yo[2 * t + 1] = __floats2half2_rn((v.z - mu) * rstd * gv.z + bv.z,
                                      (v.w - mu) * rstd * gv.w + bv.w);
}

__global__ void __launch_bounds__(128) ln_k(const float* __restrict__ x,
                                            const float* __restrict__ g,
                                            const float* __restrict__ b,
                                            __half* __restrict__ y)
{
    ln_body(x + (size_t)blockIdx.x * DIMF, g, b,
            y + (size_t)blockIdx.x * DIMF, threadIdx.x);
}

__global__ void __launch_bounds__(128) ln2_k(const float* __restrict__ diff,
                                             const float* __restrict__ con,
                                             const float* __restrict__ lndg,
                                             const float* __restrict__ lndb,
                                             const float* __restrict__ lncg,
                                             const float* __restrict__ lncb,
                                             __half* __restrict__ hb)
{
    const int which = blockIdx.y;
    const float* x = (which == 0 ? diff : con) + (size_t)blockIdx.x * DIMF;
    __half* y = hb + (which == 0 ? H_FEAQ : H_FEAKV) + (size_t)blockIdx.x * DIMF;
    ln_body(x, which == 0 ? lndg : lncg, which == 0 ? lndb : lncb, y, threadIdx.x);
}

// ---------------------------------------------------------------------------
// Two-phase deterministic per-sample stats (ddof=1)
// ---------------------------------------------------------------------------
__global__ void __launch_bounds__(256) stats1_k(const float* __restrict__ a,
                                                float* __restrict__ part)
{
    const int b = blockIdx.x, c = blockIdx.y;
    const float* p = a + (size_t)b * (NT * DIMF) + (size_t)c * 16384;
    float s = 0.0f, s2 = 0.0f;
#pragma unroll 4
    for (int i = threadIdx.x; i < 4096; i += 256) {
        float4 v = ((const float4*)p)[i];
        s += v.x + v.y + v.z + v.w;
        s2 += v.x*v.x + v.y*v.y + v.z*v.z + v.w*v.w;
    }
#pragma unroll
    for (int off = 16; off; off >>= 1) {
        s  += __shfl_xor_sync(0xffffffffu, s,  off);
        s2 += __shfl_xor_sync(0xffffffffu, s2, off);
    }
    __shared__ float sh[16];
    const int w = threadIdx.x >> 5;
    if ((threadIdx.x & 31) == 0) { sh[w] = s; sh[8 + w] = s2; }
    __syncthreads();
    if (threadIdx.x == 0) {
        float ts = 0.0f, ts2 = 0.0f;
        for (int i = 0; i < 8; i++) { ts += sh[i]; ts2 += sh[8 + i]; }
        part[(b * 32 + c) * 2]     = ts;
        part[(b * 32 + c) * 2 + 1] = ts2;
    }
}

__global__ void __launch_bounds__(128) stats2_k(const float* __restrict__ part,
                                                float* __restrict__ st)
{
    const int w = threadIdx.x >> 5, lane = threadIdx.x & 31;
    double s = (double)part[(w * 32 + lane) * 2];
    double s2 = (double)part[(w * 32 + lane) * 2 + 1];
#pragma unroll
    for (int off = 16; off; off >>= 1) {
        s  += __shfl_xor_sync(0xffffffffu, s,  off);
        s2 += __shfl_xor_sync(0xffffffffu, s2, off);
    }
    if (lane == 0) {
        double N   = (double)(NT * DIMF);
        double mu  = s / N;
        double var = (s2 - N * mu * mu) / (N - 1.0);
        st[w * 2 + 0] = (float)mu;
        st[w * 2 + 1] = (float)(1.0 / sqrt(var));
    }
}

// ---------------------------------------------------------------------------
// Fused time MLP
// ---------------------------------------------------------------------------
__global__ void __launch_bounds__(1024) tmlp_k(const float* __restrict__ te,
                                               const float* __restrict__ w1,
                                               const float* __restrict__ b1,
                                               const float* __restrict__ w2,
                                               const float* __restrict__ b2,
                                               float* __restrict__ tout)
{
    __shared__ float tes[512];
    __shared__ float h1s[1024];
    const int b = blockIdx.x;
    const int j = threadIdx.x;
    if (j < 512) tes[j] = te[b * 512 + j];
    __syncthreads();
    float acc = 0.0f;
    for (int k = 0; k < 512; k++)
        acc = fmaf(tes[k], w1[k * 1024 + j], acc);
    acc += b1[j];
    h1s[j] = acc / (1.0f + __expf(-acc));
    __syncthreads();
    float acc2 = 0.0f;
    for (int k = 0; k < 1024; k++)
        acc2 = fmaf(h1s[k], w2[k * 1024 + j], acc2);
    tout[b * 1024 + j] = acc2 + b2[j];
}

// ---------------------------------------------------------------------------
// FiLM apply (fp32 in -> fp16 out)
// ---------------------------------------------------------------------------
__global__ void __launch_bounds__(256) film_k(const float* __restrict__ a,
                                              const float* __restrict__ t,
                                              const float* __restrict__ st,
                                              __half* __restrict__ x)
{
    const int i = blockIdx.x * 256 + threadIdx.x;
    const int idx = i * 2;
    const int c = idx & 511;
    const int b = idx >> 19;
    const float mu = st[b * 2], rstd = st[b * 2 + 1];
    const float2 av = *(const float2*)(a + idx);
    const float s0 = t[b * 1024 + 512 + c], s1 = t[b * 1024 + 512 + c + 1];
    const float m0v = t[b * 1024 + c],      m1v = t[b * 1024 + c + 1];
    *(__half2*)(x + idx) = __floats2half2_rn((av.x - mu) * rstd * s0 + m0v,
                                             (av.y - mu) * rstd * s1 + m1v);
}

// ---------------------------------------------------------------------------
// Launch
// ---------------------------------------------------------------------------
extern "C" void kernel_launch(void* const* d_in, const int* in_sizes, int n_in,
                              void* d_out, int out_size)
{
    const float* con   = (const float*)d_in[0];
    const float* diff  = (const float*)d_in[1];
    const float* temb  = (const float*)d_in[2];
    const float* lncg  = (const float*)d_in[3];
    const float* lncb  = (const float*)d_in[4];
    const float* lndg  = (const float*)d_in[5];
    const float* lndb  = (const float*)d_in[6];
    const float* wq    = (const float*)d_in[7];
    const float* wk    = (const float*)d_in[8];
    const float* wv    = (const float*)d_in[9];
    const float* wout  = (const float*)d_in[10];
    const float* bout  = (const float*)d_in[11];
    const float* wemd1 = (const float*)d_in[12];
    const float* bemd1 = (const float*)d_in[13];
    const float* wemd2 = (const float*)d_in[14];
    const float* bemd2 = (const float*)d_in[15];
    const float* mlng  = (const float*)d_in[16];
    const float* mlnb  = (const float*)d_in[17];
    const float* mw1   = (const float*)d_in[18];
    const float* mb1   = (const float*)d_in[19];
    const float* mw2   = (const float*)d_in[20];
    const float* mb2   = (const float*)d_in[21];

    float* buf = nullptr;
    cudaGetSymbolAddress((void**)&buf, g_buf);
    __half* hb = (__half*)(buf + O_HB);

    const int hg_smem = 6 * STG;                 // 49152
    cudaFuncSetAttribute(qkv_k,        cudaFuncAttributeMaxDynamicSharedMemorySize, hg_smem);
    cudaFuncSetAttribute(hgemm_k<1,0>, cudaFuncAttributeMaxDynamicSharedMemorySize, hg_smem);
    cudaFuncSetAttribute(hgemm_k<2,1>, cudaFuncAttributeMaxDynamicSharedMemorySize, hg_smem);
    const int at_smem = 65536;                   // Q(16K) + 2xKhi + 2xKlo + 2xVs
    cudaFuncSetAttribute(attnh_k, cudaFuncAttributeMaxDynamicSharedMemorySize, at_smem);

    // 0) weights -> [N][K] fp16
    tr512x6_k<<<dim3(16, 16, 6), 256>>>(wq, wk, wv, wout, mw1, mw2, hb + H_WT);

    // 1) both input LayerNorms in one launch
    ln2_k<<<dim3(NB * NT, 2), 128>>>(diff, con, lndg, lndb, lncg, lncb, hb);

    // 2) fused Q/K/V projections
    qkv_k<<<dim3(4, 32, 3), 256, hg_smem>>>(hb);

    // 3) attention (128-row Q tiles, 8 warps)
    attnh_k<<<dim3(NT / 128, NB * NHD), 256, at_smem>>>(
        hb + H_QHI, hb + H_KHI, hb + H_KLO, hb + H_VH, buf + O_ATT);

    // 4) stats + time MLP + FiLM
    stats1_k<<<dim3(NB, 32), 256>>>(buf + O_ATT, buf + O_PART);
    stats2_k<<<1, 128>>>(buf + O_PART, buf + O_STATS);
    tmlp_k<<<NB, 1024>>>(temb, wemd1, bemd1, wemd2, bemd2, buf + O_T);
    film_k<<<(int)(SZ / 512), 256>>>(buf + O_ATT, buf + O_T, buf + O_STATS,
                                     hb + H_X);

    // 5) output projection
    hgemm_k<1,0><<<dim3(4, 32), 256, hg_smem>>>(hb + H_X, hb + H_WT + 3 * WSTEP,
                                                bout, buf + O_OUT1);

    // 6) FeedForward
    ln_k<<<NB * NT, 128>>>(buf + O_OUT1, mlng, mlnb, hb + H_H);
    hgemm_k<2,1><<<dim3(4, 32), 256, hg_smem>>>(hb + H_H, hb + H_WT + 4 * WSTEP,
                                                mb1, hb + H_H2);
    hgemm_k<1,0><<<dim3(4, 32), 256, hg_smem>>>(hb + H_H2, hb + H_WT + 5 * WSTEP,
                                                mb2, (float*)d_out);
}